// round 1
// baseline (speedup 1.0000x reference)
#include <cuda_runtime.h>
#include <math.h>

// Problem dims
#define NB   128        // batch
#define NT   20         // timesteps
#define VNUM 196        // vis_num
#define VDIM 512        // vis_dim
#define NE   256        // embed
#define NH   512        // hidden
#define NV   10000      // vocab
#define G4   2048       // 4*hidden
#define TBR  2560       // NT*NB rows

// ---------------- scratch (__device__ globals; no allocations allowed) ----------------
__device__ float d_emb_all[TBR * NE];            // [t*NB+b][NE]
__device__ float d_feat_sum[NB * VDIM];
__device__ float d_attv[NB * VNUM];
__device__ float d_ctx[NB * VDIM];
__device__ float d_h[NB * NH];
__device__ float d_c[NB * NH];
__device__ float d_hall[TBR * NH];               // [t*NB+b][NH]
__device__ float d_gctx[NB * G4];
__device__ float d_gpre[(size_t)TBR * G4];
__device__ float d_gates[NB * G4];
__device__ float d_bcomb[G4];
__device__ float d_logits[(size_t)TBR * NV];

// ---------------- embedding gather: emb_all[t*NB+b] = embed_table[captions[b,t]] ----------------
__global__ void k_gather(const int* __restrict__ cap, const float* __restrict__ et) {
    int r = blockIdx.x;             // t*NB + b
    int t = r / NB, b = r % NB;
    int id = cap[b * NT + t];
    d_emb_all[(size_t)r * NE + threadIdx.x] = et[(size_t)id * NE + threadIdx.x];
}

// ---------------- att_v[b,n] = dot(features[b,n,:], Wv) + bv ----------------
__global__ void k_attv(const float* __restrict__ feat, const float* __restrict__ Wv,
                       const float* __restrict__ bv) {
    __shared__ float wv[VDIM];
    int b = blockIdx.x;
    for (int i = threadIdx.x; i < VDIM; i += blockDim.x) wv[i] = Wv[i];
    __syncthreads();
    int warp = threadIdx.x >> 5, lane = threadIdx.x & 31;
    int nwarp = blockDim.x >> 5;
    const float* fb = feat + (size_t)b * VNUM * VDIM;
    for (int n = warp; n < VNUM; n += nwarp) {
        const float* fr = fb + n * VDIM;
        float acc = 0.f;
        for (int k = lane; k < VDIM; k += 32) acc += fr[k] * wv[k];
        #pragma unroll
        for (int o = 16; o; o >>= 1) acc += __shfl_xor_sync(0xffffffffu, acc, o);
        if (lane == 0) d_attv[b * VNUM + n] = acc + bv[0];
    }
}

// ---------------- feat_sum[b,v] = sum_n features[b,n,v] ----------------
__global__ void k_featsum(const float* __restrict__ feat) {
    int b = blockIdx.x, v = threadIdx.x;
    const float* fb = feat + (size_t)b * VNUM * VDIM;
    float acc = 0.f;
    for (int n = 0; n < VNUM; n++) acc += fb[n * VDIM + v];
    d_feat_sum[b * VDIM + v] = acc;
}

// ---------------- alpha = softmax_n(att_v[b]);  ctx[b,v] = sum_n alpha[n]*features[b,n,v] ----------------
__global__ void k_softmax_ctx(const float* __restrict__ feat) {
    __shared__ float alpha[VNUM];
    __shared__ float red[256];
    int b = blockIdx.x, tid = threadIdx.x;
    float x = (tid < VNUM) ? d_attv[b * VNUM + tid] : -1e30f;
    red[tid] = x; __syncthreads();
    for (int s = 128; s; s >>= 1) { if (tid < s) red[tid] = fmaxf(red[tid], red[tid + s]); __syncthreads(); }
    float mx = red[0]; __syncthreads();
    float e = (tid < VNUM) ? __expf(x - mx) : 0.f;
    red[tid] = e; __syncthreads();
    for (int s = 128; s; s >>= 1) { if (tid < s) red[tid] += red[tid + s]; __syncthreads(); }
    float inv = 1.f / red[0];
    if (tid < VNUM) alpha[tid] = e * inv;
    __syncthreads();
    const float* fb = feat + (size_t)b * VNUM * VDIM;
    for (int v = tid; v < VDIM; v += blockDim.x) {
        float acc = 0.f;
        for (int n = 0; n < VNUM; n++) acc += alpha[n] * fb[n * VDIM + v];
        d_ctx[b * VDIM + v] = acc;
    }
}

// ---------------- b_comb = b_ih + b_hh ----------------
__global__ void k_bias(const float* __restrict__ bih, const float* __restrict__ bhh) {
    int i = blockIdx.x * blockDim.x + threadIdx.x;
    if (i < G4) d_bcomb[i] = bih[i] + bhh[i];
}

// ---------------- generic NT GEMM: C[m,n] = alpha*dot(A[m,:],B[n,:]) + bias[n] + addM[(m%mod),n] ----------------
template<int BM, int BN, int BK, int TM, int TN>
__global__ void gemm_nt(const float* __restrict__ A, int lda,
                        const float* __restrict__ Bw, int ldb,
                        float* __restrict__ C,
                        int M, int N, int K, float alpha,
                        const float* __restrict__ bias,
                        const float* __restrict__ addM, int addRowMod) {
    constexpr int TX = BN / TN, TY = BM / TM;
    constexpr int NTH = TX * TY;
    __shared__ float As[BK][BM];
    __shared__ float Bs[BK][BN];
    int tid = threadIdx.x;
    int tx = tid % TX, ty = tid / TX;
    int m0 = blockIdx.y * BM, n0 = blockIdx.x * BN;
    float acc[TM][TN];
    #pragma unroll
    for (int i = 0; i < TM; i++)
        #pragma unroll
        for (int j = 0; j < TN; j++) acc[i][j] = 0.f;

    for (int k0 = 0; k0 < K; k0 += BK) {
        #pragma unroll
        for (int i = tid; i < BM * BK; i += NTH) {
            int r = i / BK, kk = i % BK;
            As[kk][r] = (m0 + r < M) ? A[(size_t)(m0 + r) * lda + k0 + kk] : 0.f;
        }
        #pragma unroll
        for (int i = tid; i < BN * BK; i += NTH) {
            int r = i / BK, kk = i % BK;
            Bs[kk][r] = (n0 + r < N) ? Bw[(size_t)(n0 + r) * ldb + k0 + kk] : 0.f;
        }
        __syncthreads();
        #pragma unroll
        for (int kk = 0; kk < BK; kk++) {
            float af[TM], bf[TN];
            #pragma unroll
            for (int i = 0; i < TM; i++) af[i] = As[kk][ty * TM + i];
            #pragma unroll
            for (int j = 0; j < TN; j++) bf[j] = Bs[kk][tx * TN + j];
            #pragma unroll
            for (int i = 0; i < TM; i++)
                #pragma unroll
                for (int j = 0; j < TN; j++) acc[i][j] += af[i] * bf[j];
        }
        __syncthreads();
    }
    #pragma unroll
    for (int i = 0; i < TM; i++) {
        int m = m0 + ty * TM + i;
        if (m >= M) continue;
        int ar = addM ? (addRowMod ? (m % addRowMod) : m) : 0;
        #pragma unroll
        for (int j = 0; j < TN; j++) {
            int n = n0 + tx * TN + j;
            if (n >= N) continue;
            float v = alpha * acc[i][j];
            if (bias) v += bias[n];
            if (addM) v += addM[(size_t)ar * N + n];
            C[(size_t)m * N + n] = v;
        }
    }
}

// ---------------- LSTM pointwise (torch gate order i,f,g,o) ----------------
__global__ void k_lstm(int t) {
    int b = blockIdx.x, j = threadIdx.x;
    const float* g = d_gates + b * G4;
    float gi = g[j], gf = g[NH + j], gg = g[2 * NH + j], go = g[3 * NH + j];
    float ii = 1.f / (1.f + __expf(-gi));
    float ff = 1.f / (1.f + __expf(-gf));
    float gt = tanhf(gg);
    float oo = 1.f / (1.f + __expf(-go));
    float c = ff * d_c[b * NH + j] + ii * gt;
    float h = oo * tanhf(c);
    d_c[b * NH + j] = c;
    d_h[b * NH + j] = h;
    d_hall[(size_t)(t * NB + b) * NH + j] = h;
}

// ---------------- fused row-wise log_softmax + softmax over vocab ----------------
__global__ void k_out(float* __restrict__ out) {
    __shared__ float row[NV];
    __shared__ float red[256];
    int r = blockIdx.x, tid = threadIdx.x;
    const float* L = d_logits + (size_t)r * NV;
    float mx = -1e30f;
    for (int v = tid; v < NV; v += 256) { float x = L[v]; row[v] = x; mx = fmaxf(mx, x); }
    red[tid] = mx; __syncthreads();
    for (int s = 128; s; s >>= 1) { if (tid < s) red[tid] = fmaxf(red[tid], red[tid + s]); __syncthreads(); }
    mx = red[0]; __syncthreads();
    float sum = 0.f;
    for (int v = tid; v < NV; v += 256) sum += __expf(row[v] - mx);
    red[tid] = sum; __syncthreads();
    for (int s = 128; s; s >>= 1) { if (tid < s) red[tid] += red[tid + s]; __syncthreads(); }
    float ls = logf(red[0]);
    float* o1 = out + (size_t)r * NV;
    float* o2 = out + (size_t)TBR * NV + (size_t)r * NV;
    for (int v = tid; v < NV; v += 256) {
        float lp = row[v] - mx - ls;
        o1[v] = lp;
        o2[v] = __expf(lp);
    }
}

// ---------------- launch ----------------
extern "C" void kernel_launch(void* const* d_in, const int* in_sizes, int n_in,
                              void* d_out, int out_size) {
    const float* features = (const float*)d_in[0];
    const int*   captions = (const int*)d_in[1];
    const float* W_init_h = (const float*)d_in[2];
    const float* W_init_c = (const float*)d_in[3];
    const float* Wv       = (const float*)d_in[4];
    const float* bv       = (const float*)d_in[5];
    // d_in[6]=Wa, d_in[7]=ba : provably unused (softmax shift-invariance)
    const float* embed    = (const float*)d_in[8];
    const float* W_ih     = (const float*)d_in[9];
    const float* W_hh     = (const float*)d_in[10];
    const float* b_ih     = (const float*)d_in[11];
    const float* b_hh     = (const float*)d_in[12];
    const float* Wo       = (const float*)d_in[13];
    const float* bo       = (const float*)d_in[14];
    float* out = (float*)d_out;

    float *p_emb, *p_fs, *p_ctx, *p_h, *p_c, *p_hall, *p_gctx, *p_gpre, *p_gates, *p_bcomb, *p_logits;
    cudaGetSymbolAddress((void**)&p_emb,    d_emb_all);
    cudaGetSymbolAddress((void**)&p_fs,     d_feat_sum);
    cudaGetSymbolAddress((void**)&p_ctx,    d_ctx);
    cudaGetSymbolAddress((void**)&p_h,      d_h);
    cudaGetSymbolAddress((void**)&p_c,      d_c);
    cudaGetSymbolAddress((void**)&p_hall,   d_hall);
    cudaGetSymbolAddress((void**)&p_gctx,   d_gctx);
    cudaGetSymbolAddress((void**)&p_gpre,   d_gpre);
    cudaGetSymbolAddress((void**)&p_gates,  d_gates);
    cudaGetSymbolAddress((void**)&p_bcomb,  d_bcomb);
    cudaGetSymbolAddress((void**)&p_logits, d_logits);

    // one-time setup
    k_gather<<<TBR, NE>>>(captions, embed);
    k_attv<<<NB, 256>>>(features, Wv, bv);
    k_featsum<<<NB, VDIM>>>(features);
    k_softmax_ctx<<<NB, 256>>>(features);
    k_bias<<<(G4 + 255) / 256, 256>>>(b_ih, b_hh);

    // h0 = feat_sum @ W_init_h^T / 196 ; c0 likewise
    gemm_nt<32, 64, 16, 2, 4><<<dim3(NH / 64, NB / 32), 256>>>(
        p_fs, VDIM, W_init_h, VDIM, p_h, NB, NH, VDIM, 1.f / VNUM, nullptr, nullptr, 0);
    gemm_nt<32, 64, 16, 2, 4><<<dim3(NH / 64, NB / 32), 256>>>(
        p_fs, VDIM, W_init_c, VDIM, p_c, NB, NH, VDIM, 1.f / VNUM, nullptr, nullptr, 0);

    // g_ctx = ctx @ W_ih[:, :512]^T + (b_ih + b_hh)   (time-invariant)
    gemm_nt<32, 64, 16, 2, 4><<<dim3(G4 / 64, NB / 32), 256>>>(
        p_ctx, VDIM, W_ih, VDIM + NE, p_gctx, NB, G4, VDIM, 1.f, p_bcomb, nullptr, 0);

    // g_pre[t*NB+b] = emb @ W_ih[:, 512:]^T + g_ctx[b]  (all timesteps in one GEMM)
    gemm_nt<128, 128, 8, 8, 8><<<dim3(G4 / 128, TBR / 128), 256>>>(
        p_emb, NE, W_ih + VDIM, VDIM + NE, p_gpre, TBR, G4, NE, 1.f, nullptr, p_gctx, NB);

    // sequential recurrence: only h @ W_hh^T + pointwise remain serial
    for (int t = 0; t < NT; t++) {
        gemm_nt<32, 64, 16, 2, 4><<<dim3(G4 / 64, NB / 32), 256>>>(
            p_h, NH, W_hh, NH, p_gates, NB, G4, NH, 1.f, nullptr,
            p_gpre + (size_t)t * NB * G4, 0);
        k_lstm<<<NB, NH>>>(t);
    }

    // vocab projection for all T*B rows at once
    gemm_nt<128, 128, 8, 8, 8><<<dim3((NV + 127) / 128, TBR / 128), 256>>>(
        p_hall, NH, Wo, NH, p_logits, TBR, NV, NH, 1.f, bo, nullptr, 0);

    // fused log_softmax + softmax -> output
    k_out<<<TBR, 256>>>(out);
}

// round 3
// speedup vs baseline: 1.9344x; 1.9344x over previous
#include <cuda_runtime.h>
#include <math.h>
#include <stdint.h>

// Problem dims
#define NB   128
#define NT   20
#define VNUM 196
#define VDIM 512
#define NE   256
#define NH   512
#define NV   10000
#define G4   2048
#define TBR  2560   // NT*NB

// ---------------- tf32 helpers (plain sm_80+ PTX; no 'a'-suffix features) ----------------
__device__ __forceinline__ float to_tf32(float x) {
    uint32_t y;
    asm("cvt.rna.tf32.f32 %0, %1;" : "=r"(y) : "f"(x));
    return __uint_as_float(y);
}
__device__ __forceinline__ void mma8(float* c, const uint32_t* a, const uint32_t* b) {
    asm volatile("mma.sync.aligned.m16n8k8.row.col.f32.tf32.tf32.f32 "
                 "{%0,%1,%2,%3}, {%4,%5,%6,%7}, {%8,%9}, {%0,%1,%2,%3};"
                 : "+f"(c[0]), "+f"(c[1]), "+f"(c[2]), "+f"(c[3])
                 : "r"(a[0]), "r"(a[1]), "r"(a[2]), "r"(a[3]), "r"(b[0]), "r"(b[1]));
}

// ---------------- scratch ----------------
__device__ float d_emb32[TBR * NE];              // tf32-rounded
__device__ float d_wo32[(size_t)NV * NH];        // tf32-rounded
__device__ float d_wih32[G4 * NE];               // tf32-rounded
__device__ float d_hall32[TBR * NH];             // tf32-rounded
__device__ float d_feat_sum[NB * VDIM];
__device__ float d_ctx[NB * VDIM];
__device__ float d_h[NB * NH];
__device__ float d_c[NB * NH];
__device__ float d_gctx[NB * G4];
__device__ float d_gpre[(size_t)TBR * G4];
__device__ float d_gates[NB * G4];
__device__ float d_bcomb[G4];
__device__ float d_logits[(size_t)TBR * NV];
__device__ unsigned d_barCount;
__device__ unsigned d_barGen;

// ---------------- embedding gather -> tf32 ----------------
__global__ void k_gather(const int* __restrict__ cap, const float* __restrict__ et) {
    int r = blockIdx.x;                 // t*NB + b
    int t = r / NB, b = r % NB;
    int id = cap[b * NT + t];
    d_emb32[(size_t)r * NE + threadIdx.x] = to_tf32(et[(size_t)id * NE + threadIdx.x]);
}

// ---------------- strided fp32 -> tf32 ----------------
__global__ void k_cvt32(const float* __restrict__ src, int pitch, int cols,
                        float* __restrict__ dst, int n) {
    int i = blockIdx.x * 256 + threadIdx.x;
    if (i >= n) return;
    int r = i / cols, c = i % cols;
    dst[i] = to_tf32(src[(size_t)r * pitch + c]);
}

__global__ void k_bias(const float* __restrict__ bih, const float* __restrict__ bhh) {
    int i = blockIdx.x * blockDim.x + threadIdx.x;
    if (i < G4) d_bcomb[i] = bih[i] + bhh[i];
}

// ---------------- fused visual: att_v dot (warp/n) -> softmax -> feat_sum + ctx ----------------
__global__ void k_vis(const float* __restrict__ feat, const float* __restrict__ Wv,
                      const float* __restrict__ bv) {
    __shared__ float satt[VNUM];
    __shared__ float red[256];
    int b = blockIdx.x, tid = threadIdx.x;
    int warp = tid >> 5, lane = tid & 31;
    const float* fb = feat + (size_t)b * VNUM * VDIM;
    // phase 1: attention logits, one warp per n
    for (int n = warp; n < VNUM; n += 8) {
        const float* fr = fb + n * VDIM;
        float acc = 0.f;
        #pragma unroll
        for (int k = lane; k < VDIM; k += 32) acc += fr[k] * Wv[k];
        #pragma unroll
        for (int o = 16; o; o >>= 1) acc += __shfl_xor_sync(0xffffffffu, acc, o);
        if (lane == 0) satt[n] = acc + bv[0];
    }
    __syncthreads();
    // softmax over satt[0..195]
    float x = (tid < VNUM) ? satt[tid] : -1e30f;
    red[tid] = x; __syncthreads();
    for (int s = 128; s; s >>= 1) { if (tid < s) red[tid] = fmaxf(red[tid], red[tid + s]); __syncthreads(); }
    float mx = red[0]; __syncthreads();
    float e = (tid < VNUM) ? __expf(x - mx) : 0.f;
    red[tid] = e; __syncthreads();
    for (int s = 128; s; s >>= 1) { if (tid < s) red[tid] += red[tid + s]; __syncthreads(); }
    float inv = 1.f / red[0];
    __syncthreads();
    if (tid < VNUM) satt[tid] = e * inv;
    __syncthreads();
    // phase 2: one pass computes feat_sum and ctx
    for (int v = tid; v < VDIM; v += 256) {
        float fs = 0.f, c0 = 0.f, c1 = 0.f, c2 = 0.f, c3 = 0.f;
        int n = 0;
        for (; n + 4 <= VNUM; n += 4) {
            float x0 = fb[n * VDIM + v];
            float x1 = fb[(n + 1) * VDIM + v];
            float x2 = fb[(n + 2) * VDIM + v];
            float x3 = fb[(n + 3) * VDIM + v];
            fs += (x0 + x1) + (x2 + x3);
            c0 += satt[n] * x0; c1 += satt[n + 1] * x1;
            c2 += satt[n + 2] * x2; c3 += satt[n + 3] * x3;
        }
        for (; n < VNUM; n++) { float xx = fb[n * VDIM + v]; fs += xx; c0 += satt[n] * xx; }
        d_feat_sum[b * VDIM + v] = fs;
        d_ctx[b * VDIM + v] = (c0 + c1) + (c2 + c3);
    }
}

// ---------------- small SIMT NT GEMM (dims divide evenly) ----------------
template<int BM, int BN, int BK, int TM, int TN>
__global__ void gemm_nt(const float* __restrict__ A, int lda,
                        const float* __restrict__ Bw, int ldb,
                        float* __restrict__ C,
                        int M, int N, int K, float alpha,
                        const float* __restrict__ bias) {
    constexpr int TX = BN / TN, TY = BM / TM;
    constexpr int NTH = TX * TY;
    __shared__ float As[BK][BM];
    __shared__ float Bs[BK][BN];
    int tid = threadIdx.x;
    int tx = tid % TX, ty = tid / TX;
    int m0 = blockIdx.y * BM, n0 = blockIdx.x * BN;
    float acc[TM][TN];
    #pragma unroll
    for (int i = 0; i < TM; i++)
        #pragma unroll
        for (int j = 0; j < TN; j++) acc[i][j] = 0.f;
    for (int k0 = 0; k0 < K; k0 += BK) {
        for (int i = tid; i < BM * BK; i += NTH) {
            int r = i / BK, kk = i % BK;
            As[kk][r] = A[(size_t)(m0 + r) * lda + k0 + kk];
        }
        for (int i = tid; i < BN * BK; i += NTH) {
            int r = i / BK, kk = i % BK;
            Bs[kk][r] = Bw[(size_t)(n0 + r) * ldb + k0 + kk];
        }
        __syncthreads();
        #pragma unroll
        for (int kk = 0; kk < BK; kk++) {
            float af[TM], bf[TN];
            #pragma unroll
            for (int i = 0; i < TM; i++) af[i] = As[kk][ty * TM + i];
            #pragma unroll
            for (int j = 0; j < TN; j++) bf[j] = Bs[kk][tx * TN + j];
            #pragma unroll
            for (int i = 0; i < TM; i++)
                #pragma unroll
                for (int j = 0; j < TN; j++) acc[i][j] += af[i] * bf[j];
        }
        __syncthreads();
    }
    #pragma unroll
    for (int i = 0; i < TM; i++) {
        int m = m0 + ty * TM + i;
        #pragma unroll
        for (int j = 0; j < TN; j++) {
            int n = n0 + tx * TN + j;
            float v = alpha * acc[i][j];
            if (bias) v += bias[n];
            C[(size_t)m * N + n] = v;
        }
    }
}

// ======================= tf32 mma.sync GEMM =======================
// C[m,n] = dot(A[m,:], B[n,:]) + bias[n] + addM[m % addRowMod][n]
// BM=BN=128, BK=32. 8 warps (2m x 4n), warp tile 64x32, mma m16n8k8.
// smem: [m][k] layout, stride 36 (conflict-free frag loads & stores).
#define ASTR 36
#define TBUF 4608     // 128*36 floats per buffer

__global__ void __launch_bounds__(256) tmma(const float* __restrict__ A,
        const float* __restrict__ B, float* __restrict__ C,
        int M, int N, int K,
        const float* __restrict__ bias, const float* __restrict__ addM, int addRowMod) {
    extern __shared__ float smf[];
    int tid = threadIdx.x, lane = tid & 31, wid = tid >> 5;
    int wm = wid & 1, wn = wid >> 1;            // 2 x 4 warp grid
    int m0 = blockIdx.y * 128, n0 = blockIdx.x * 128;
    int gid = lane >> 2, tig = lane & 3;

    float acc[4][4][4];
    #pragma unroll
    for (int mi = 0; mi < 4; mi++)
        #pragma unroll
        for (int ni = 0; ni < 4; ni++)
            #pragma unroll
            for (int q = 0; q < 4; q++) acc[mi][ni][q] = 0.f;

    float4 ra[4], rb[4];
    int r_[4], c_[4];
    #pragma unroll
    for (int j = 0; j < 4; j++) { int idx = tid + j * 256; r_[j] = idx >> 3; c_[j] = (idx & 7) << 2; }

    int iters = K >> 5;   // K/32
    // prologue: load tile 0
    #pragma unroll
    for (int j = 0; j < 4; j++) {
        ra[j] = *(const float4*)(A + (size_t)(m0 + r_[j]) * K + c_[j]);
        int n = n0 + r_[j];
        rb[j] = (n < N) ? *(const float4*)(B + (size_t)n * K + c_[j]) : make_float4(0.f, 0.f, 0.f, 0.f);
    }
    {
        float* As0 = smf;
        float* Bs0 = smf + TBUF;
        #pragma unroll
        for (int j = 0; j < 4; j++) {
            *(float4*)(As0 + r_[j] * ASTR + c_[j]) = ra[j];
            *(float4*)(Bs0 + r_[j] * ASTR + c_[j]) = rb[j];
        }
    }
    __syncthreads();

    for (int it = 0; it < iters; it++) {
        const float* Asc = smf + (it & 1) * 2 * TBUF;
        const float* Bsc = Asc + TBUF;
        if (it + 1 < iters) {
            int k0 = (it + 1) << 5;
            #pragma unroll
            for (int j = 0; j < 4; j++) {
                ra[j] = *(const float4*)(A + (size_t)(m0 + r_[j]) * K + k0 + c_[j]);
                int n = n0 + r_[j];
                rb[j] = (n < N) ? *(const float4*)(B + (size_t)n * K + k0 + c_[j]) : make_float4(0.f, 0.f, 0.f, 0.f);
            }
        }
        const uint32_t* Au = (const uint32_t*)Asc;
        const uint32_t* Bu = (const uint32_t*)Bsc;
        #pragma unroll
        for (int ks = 0; ks < 4; ks++) {
            int kb = ks * 8;
            uint32_t a[4][4], b[4][2];
            #pragma unroll
            for (int mi = 0; mi < 4; mi++) {
                const uint32_t* ap = Au + (wm * 64 + mi * 16 + gid) * ASTR + kb + tig;
                a[mi][0] = ap[0];
                a[mi][1] = ap[8 * ASTR];
                a[mi][2] = ap[4];
                a[mi][3] = ap[8 * ASTR + 4];
            }
            #pragma unroll
            for (int ni = 0; ni < 4; ni++) {
                const uint32_t* bp = Bu + (wn * 32 + ni * 8 + gid) * ASTR + kb + tig;
                b[ni][0] = bp[0];
                b[ni][1] = bp[4];
            }
            #pragma unroll
            for (int mi = 0; mi < 4; mi++)
                #pragma unroll
                for (int ni = 0; ni < 4; ni++)
                    mma8(acc[mi][ni], a[mi], b[ni]);
        }
        __syncthreads();
        if (it + 1 < iters) {
            float* Asn = smf + ((it + 1) & 1) * 2 * TBUF;
            float* Bsn = Asn + TBUF;
            #pragma unroll
            for (int j = 0; j < 4; j++) {
                *(float4*)(Asn + r_[j] * ASTR + c_[j]) = ra[j];
                *(float4*)(Bsn + r_[j] * ASTR + c_[j]) = rb[j];
            }
            __syncthreads();
        }
    }

    // epilogue
    #pragma unroll
    for (int mi = 0; mi < 4; mi++) {
        int row0 = m0 + wm * 64 + mi * 16 + gid;
        #pragma unroll
        for (int ni = 0; ni < 4; ni++) {
            int col = n0 + wn * 32 + ni * 8 + tig * 2;
            #pragma unroll
            for (int half = 0; half < 2; half++) {
                int r = row0 + half * 8;
                float v0 = acc[mi][ni][half * 2 + 0];
                float v1 = acc[mi][ni][half * 2 + 1];
                if (bias) { v0 += bias[col]; v1 += (col + 1 < N) ? bias[col + 1] : 0.f; }
                if (addM) {
                    int ar = r % addRowMod;
                    v0 += addM[(size_t)ar * N + col];
                    if (col + 1 < N) v1 += addM[(size_t)ar * N + col + 1];
                }
                if (col < N)     C[(size_t)r * N + col]     = v0;
                if (col + 1 < N) C[(size_t)r * N + col + 1] = v1;
            }
        }
    }
}

// ======================= persistent recurrence =======================
__device__ __forceinline__ void grid_barrier(unsigned nb) {
    __syncthreads();
    if (threadIdx.x == 0) {
        unsigned gen = *((volatile unsigned*)&d_barGen);
        __threadfence();
        if (atomicAdd(&d_barCount, 1u) == nb - 1u) {
            d_barCount = 0u;
            __threadfence();
            atomicAdd(&d_barGen, 1u);
        } else {
            while (*((volatile unsigned*)&d_barGen) == gen) {}
        }
        __threadfence();
    }
    __syncthreads();
}

// 128 blocks x 256 threads (single wave). Per step: block computes one 32x64 gate
// tile of h@Whh^T, grid barrier, pointwise for batch b = blockIdx.x.
__global__ void __launch_bounds__(256, 1) k_recur(const float* __restrict__ Whh) {
    __shared__ float As[16][32];
    __shared__ float Bs[16][64];
    int bid = blockIdx.x;
    int nt = bid & 31, mt = bid >> 5;
    int tid = threadIdx.x;
    int tx = tid & 15, ty = tid >> 4;
    int pb = bid;
    float creg0 = d_c[pb * NH + tid];
    float creg1 = d_c[pb * NH + tid + 256];

    for (int t = 0; t < NT; t++) {
        float acc[2][4] = {{0.f, 0.f, 0.f, 0.f}, {0.f, 0.f, 0.f, 0.f}};
        for (int k0 = 0; k0 < NH; k0 += 16) {
            {
                int i = tid; int r = i >> 4, kk = i & 15;
                As[kk][r] = __ldcg(&d_h[(mt * 32 + r) * NH + k0 + kk]);
                i = tid + 256; r = i >> 4; kk = i & 15;
                As[kk][r] = __ldcg(&d_h[(mt * 32 + r) * NH + k0 + kk]);
            }
            #pragma unroll
            for (int j = 0; j < 4; j++) {
                int i = tid + j * 256; int r = i >> 4, kk = i & 15;
                Bs[kk][r] = Whh[(size_t)(nt * 64 + r) * NH + k0 + kk];
            }
            __syncthreads();
            #pragma unroll
            for (int kk = 0; kk < 16; kk++) {
                float a0 = As[kk][ty * 2], a1 = As[kk][ty * 2 + 1];
                float b0 = Bs[kk][tx * 4], b1 = Bs[kk][tx * 4 + 1];
                float b2 = Bs[kk][tx * 4 + 2], b3 = Bs[kk][tx * 4 + 3];
                acc[0][0] += a0 * b0; acc[0][1] += a0 * b1; acc[0][2] += a0 * b2; acc[0][3] += a0 * b3;
                acc[1][0] += a1 * b0; acc[1][1] += a1 * b1; acc[1][2] += a1 * b2; acc[1][3] += a1 * b3;
            }
            __syncthreads();
        }
        #pragma unroll
        for (int i = 0; i < 2; i++) {
            int m = mt * 32 + ty * 2 + i;
            #pragma unroll
            for (int j = 0; j < 4; j++) {
                int n = nt * 64 + tx * 4 + j;
                d_gates[m * G4 + n] = acc[i][j] + d_gpre[(size_t)(t * NB + m) * G4 + n];
            }
        }
        grid_barrier(gridDim.x);
        #pragma unroll
        for (int half = 0; half < 2; half++) {
            int j = tid + half * 256;
            float gi = __ldcg(&d_gates[pb * G4 + j]);
            float gf = __ldcg(&d_gates[pb * G4 + NH + j]);
            float gg = __ldcg(&d_gates[pb * G4 + 2 * NH + j]);
            float go = __ldcg(&d_gates[pb * G4 + 3 * NH + j]);
            float ii = 1.f / (1.f + __expf(-gi));
            float ff = 1.f / (1.f + __expf(-gf));
            float gt = tanhf(gg);
            float oo = 1.f / (1.f + __expf(-go));
            float c = ff * (half ? creg1 : creg0) + ii * gt;
            float h = oo * tanhf(c);
            if (half) creg1 = c; else creg0 = c;
            d_h[pb * NH + j] = h;
            d_hall32[(size_t)(t * NB + pb) * NH + j] = to_tf32(h);
        }
        grid_barrier(gridDim.x);
    }
}

// ======================= output softmax =======================
__global__ void k_out(float* __restrict__ out) {
    __shared__ float row[NV];
    __shared__ float red[256];
    int r = blockIdx.x, tid = threadIdx.x;
    const float* L = d_logits + (size_t)r * NV;
    float mx = -1e30f;
    for (int v = tid; v < NV; v += 256) { float x = L[v]; row[v] = x; mx = fmaxf(mx, x); }
    red[tid] = mx; __syncthreads();
    for (int s = 128; s; s >>= 1) { if (tid < s) red[tid] = fmaxf(red[tid], red[tid + s]); __syncthreads(); }
    mx = red[0]; __syncthreads();
    float sum = 0.f;
    for (int v = tid; v < NV; v += 256) sum += __expf(row[v] - mx);
    red[tid] = sum; __syncthreads();
    for (int s = 128; s; s >>= 1) { if (tid < s) red[tid] += red[tid + s]; __syncthreads(); }
    float ls = logf(red[0]);
    float* o1 = out + (size_t)r * NV;
    float* o2 = out + (size_t)TBR * NV + (size_t)r * NV;
    for (int v = tid; v < NV; v += 256) {
        float lp = row[v] - mx - ls;
        o1[v] = lp;
        o2[v] = __expf(lp);
    }
}

// ======================= launch =======================
extern "C" void kernel_launch(void* const* d_in, const int* in_sizes, int n_in,
                              void* d_out, int out_size) {
    const float* features = (const float*)d_in[0];
    const int*   captions = (const int*)d_in[1];
    const float* W_init_h = (const float*)d_in[2];
    const float* W_init_c = (const float*)d_in[3];
    const float* Wv       = (const float*)d_in[4];
    const float* bv       = (const float*)d_in[5];
    // d_in[6]=Wa, d_in[7]=ba unused (softmax shift-invariance)
    const float* embed    = (const float*)d_in[8];
    const float* W_ih     = (const float*)d_in[9];
    const float* W_hh     = (const float*)d_in[10];
    const float* b_ih     = (const float*)d_in[11];
    const float* b_hh     = (const float*)d_in[12];
    const float* Wo       = (const float*)d_in[13];
    const float* bo       = (const float*)d_in[14];
    float* out = (float*)d_out;

    float *p_fs, *p_ctx, *p_h, *p_c, *p_gctx, *p_gpre, *p_bcomb, *p_logits;
    float *p_e32, *p_wo32, *p_wih32, *p_h32;
    cudaGetSymbolAddress((void**)&p_fs,     d_feat_sum);
    cudaGetSymbolAddress((void**)&p_ctx,    d_ctx);
    cudaGetSymbolAddress((void**)&p_h,      d_h);
    cudaGetSymbolAddress((void**)&p_c,      d_c);
    cudaGetSymbolAddress((void**)&p_gctx,   d_gctx);
    cudaGetSymbolAddress((void**)&p_gpre,   d_gpre);
    cudaGetSymbolAddress((void**)&p_bcomb,  d_bcomb);
    cudaGetSymbolAddress((void**)&p_logits, d_logits);
    cudaGetSymbolAddress((void**)&p_e32,    d_emb32);
    cudaGetSymbolAddress((void**)&p_wo32,   d_wo32);
    cudaGetSymbolAddress((void**)&p_wih32,  d_wih32);
    cudaGetSymbolAddress((void**)&p_h32,    d_hall32);

    static int smset = 0;
    if (!smset) {
        cudaFuncSetAttribute(tmma, cudaFuncAttributeMaxDynamicSharedMemorySize, 4 * TBUF * 4);
        smset = 1;
    }

    // setup
    k_gather<<<TBR, NE>>>(captions, embed);
    k_vis<<<NB, 256>>>(features, Wv, bv);
    k_bias<<<(G4 + 255) / 256, 256>>>(b_ih, b_hh);
    k_cvt32<<<(NV * NH + 255) / 256, 256>>>(Wo, NH, NH, p_wo32, NV * NH);
    k_cvt32<<<(G4 * NE + 255) / 256, 256>>>(W_ih + VDIM, VDIM + NE, NE, p_wih32, G4 * NE);

    // h0 / c0 / g_ctx (exact fp32 SIMT)
    gemm_nt<32, 64, 16, 2, 4><<<dim3(NH / 64, NB / 32), 256>>>(
        p_fs, VDIM, W_init_h, VDIM, p_h, NB, NH, VDIM, 1.f / VNUM, nullptr);
    gemm_nt<32, 64, 16, 2, 4><<<dim3(NH / 64, NB / 32), 256>>>(
        p_fs, VDIM, W_init_c, VDIM, p_c, NB, NH, VDIM, 1.f / VNUM, nullptr);
    gemm_nt<32, 64, 16, 2, 4><<<dim3(G4 / 64, NB / 32), 256>>>(
        p_ctx, VDIM, W_ih, VDIM + NE, p_gctx, NB, G4, VDIM, 1.f, p_bcomb);

    // g_pre = emb @ WihE^T + g_ctx[b]   (tf32 mma)
    tmma<<<dim3(G4 / 128, TBR / 128), 256, 4 * TBUF * 4>>>(
        p_e32, p_wih32, p_gpre, TBR, G4, NE, nullptr, p_gctx, NB);

    // recurrence (exact fp32)
    k_recur<<<NB, 256>>>(W_hh);

    // logits = hall @ Wo^T + bo   (tf32 mma)
    tmma<<<dim3((NV + 127) / 128, TBR / 128), 256, 4 * TBUF * 4>>>(
        p_h32, p_wo32, p_logits, TBR, NV, NH, bo, nullptr, 0);

    k_out<<<TBR, 256>>>(out);
}

// round 4
// speedup vs baseline: 3.1991x; 1.6538x over previous
#include <cuda_runtime.h>
#include <math.h>
#include <stdint.h>

// Problem dims
#define NB   128
#define NT   20
#define VNUM 196
#define VDIM 512
#define NE   256
#define NH   512
#define NV   10000
#define G4   2048
#define TBR  2560   // NT*NB

// ---------------- tf32 helpers ----------------
__device__ __forceinline__ float to_tf32(float x) {
    uint32_t y;
    asm("cvt.rna.tf32.f32 %0, %1;" : "=r"(y) : "f"(x));
    return __uint_as_float(y);
}
__device__ __forceinline__ void mma8(float* c, const uint32_t* a, const uint32_t* b) {
    asm volatile("mma.sync.aligned.m16n8k8.row.col.f32.tf32.tf32.f32 "
                 "{%0,%1,%2,%3}, {%4,%5,%6,%7}, {%8,%9}, {%0,%1,%2,%3};"
                 : "+f"(c[0]), "+f"(c[1]), "+f"(c[2]), "+f"(c[3])
                 : "r"(a[0]), "r"(a[1]), "r"(a[2]), "r"(a[3]), "r"(b[0]), "r"(b[1]));
}
__device__ __forceinline__ float sigmoidf_(float x) { return 1.f / (1.f + __expf(-x)); }

// ---------------- scratch ----------------
__device__ float d_emb[TBR * NE];
__device__ float d_hall[(size_t)TBR * NH];
__device__ float d_feat_sum[NB * VDIM];
__device__ float d_ctx[NB * VDIM];
__device__ float d_h0[NB * NH];
__device__ float d_c0[NB * NH];
__device__ float d_gctx[NB * G4];
__device__ float d_gpre[(size_t)TBR * G4];
__device__ float d_bcomb[G4];
__device__ float d_logits[(size_t)TBR * NV];
__device__ unsigned d_barCount;
__device__ unsigned d_barGen;

// ---------------- embedding gather ----------------
__global__ void k_gather(const int* __restrict__ cap, const float* __restrict__ et) {
    int r = blockIdx.x;                 // t*NB + b
    int t = r / NB, b = r % NB;
    int id = cap[b * NT + t];
    d_emb[(size_t)r * NE + threadIdx.x] = et[(size_t)id * NE + threadIdx.x];
}

__global__ void k_bias(const float* __restrict__ bih, const float* __restrict__ bhh) {
    int i = blockIdx.x * blockDim.x + threadIdx.x;
    if (i < G4) d_bcomb[i] = bih[i] + bhh[i];
}

// ---------------- fused visual: att_v -> softmax -> feat_sum + ctx ----------------
__global__ void k_vis(const float* __restrict__ feat, const float* __restrict__ Wv,
                      const float* __restrict__ bv) {
    __shared__ float satt[VNUM];
    __shared__ float red[256];
    int b = blockIdx.x, tid = threadIdx.x;
    int warp = tid >> 5, lane = tid & 31;
    const float* fb = feat + (size_t)b * VNUM * VDIM;
    for (int n = warp; n < VNUM; n += 8) {
        const float* fr = fb + n * VDIM;
        float acc = 0.f;
        #pragma unroll
        for (int k = lane; k < VDIM; k += 32) acc += fr[k] * Wv[k];
        #pragma unroll
        for (int o = 16; o; o >>= 1) acc += __shfl_xor_sync(0xffffffffu, acc, o);
        if (lane == 0) satt[n] = acc + bv[0];
    }
    __syncthreads();
    float x = (tid < VNUM) ? satt[tid] : -1e30f;
    red[tid] = x; __syncthreads();
    for (int s = 128; s; s >>= 1) { if (tid < s) red[tid] = fmaxf(red[tid], red[tid + s]); __syncthreads(); }
    float mx = red[0]; __syncthreads();
    float e = (tid < VNUM) ? __expf(x - mx) : 0.f;
    red[tid] = e; __syncthreads();
    for (int s = 128; s; s >>= 1) { if (tid < s) red[tid] += red[tid + s]; __syncthreads(); }
    float inv = 1.f / red[0];
    __syncthreads();
    if (tid < VNUM) satt[tid] = e * inv;
    __syncthreads();
    for (int v = tid; v < VDIM; v += 256) {
        float fs = 0.f, c0 = 0.f, c1 = 0.f, c2 = 0.f, c3 = 0.f;
        int n = 0;
        for (; n + 4 <= VNUM; n += 4) {
            float x0 = fb[n * VDIM + v];
            float x1 = fb[(n + 1) * VDIM + v];
            float x2 = fb[(n + 2) * VDIM + v];
            float x3 = fb[(n + 3) * VDIM + v];
            fs += (x0 + x1) + (x2 + x3);
            c0 += satt[n] * x0; c1 += satt[n + 1] * x1;
            c2 += satt[n + 2] * x2; c3 += satt[n + 3] * x3;
        }
        for (; n < VNUM; n++) { float xx = fb[n * VDIM + v]; fs += xx; c0 += satt[n] * xx; }
        d_feat_sum[b * VDIM + v] = fs;
        d_ctx[b * VDIM + v] = (c0 + c1) + (c2 + c3);
    }
}

// ---------------- small SIMT NT GEMM (init GEMMs, exact fp32) ----------------
template<int BM, int BN, int BK, int TM, int TN>
__global__ void gemm_nt(const float* __restrict__ A, int lda,
                        const float* __restrict__ Bw, int ldb,
                        float* __restrict__ C,
                        int M, int N, int K, float alpha,
                        const float* __restrict__ bias) {
    constexpr int TX = BN / TN, TY = BM / TM;
    constexpr int NTH = TX * TY;
    __shared__ float As[BK][BM];
    __shared__ float Bs[BK][BN];
    int tid = threadIdx.x;
    int tx = tid % TX, ty = tid / TX;
    int m0 = blockIdx.y * BM, n0 = blockIdx.x * BN;
    float acc[TM][TN];
    #pragma unroll
    for (int i = 0; i < TM; i++)
        #pragma unroll
        for (int j = 0; j < TN; j++) acc[i][j] = 0.f;
    for (int k0 = 0; k0 < K; k0 += BK) {
        for (int i = tid; i < BM * BK; i += NTH) {
            int r = i / BK, kk = i % BK;
            As[kk][r] = A[(size_t)(m0 + r) * lda + k0 + kk];
        }
        for (int i = tid; i < BN * BK; i += NTH) {
            int r = i / BK, kk = i % BK;
            Bs[kk][r] = Bw[(size_t)(n0 + r) * ldb + k0 + kk];
        }
        __syncthreads();
        #pragma unroll
        for (int kk = 0; kk < BK; kk++) {
            float af[TM], bf[TN];
            #pragma unroll
            for (int i = 0; i < TM; i++) af[i] = As[kk][ty * TM + i];
            #pragma unroll
            for (int j = 0; j < TN; j++) bf[j] = Bs[kk][tx * TN + j];
            #pragma unroll
            for (int i = 0; i < TM; i++)
                #pragma unroll
                for (int j = 0; j < TN; j++) acc[i][j] += af[i] * bf[j];
        }
        __syncthreads();
    }
    #pragma unroll
    for (int i = 0; i < TM; i++) {
        int m = m0 + ty * TM + i;
        #pragma unroll
        for (int j = 0; j < TN; j++) {
            int n = n0 + tx * TN + j;
            float v = alpha * acc[i][j];
            if (bias) v += bias[n];
            C[(size_t)m * N + n] = v;
        }
    }
}

// ======================= tf32 mma.sync GEMM (cvt on load) =======================
// C[m,n] = dot(A[m,:K], B[n,:K]) + bias[n] + addM[m % addRowMod][n]
// A,B raw fp32 (strided lda/ldb); converted to tf32 while staging to smem.
// BM=BN=128, BK=32, 8 warps (2m x 4n), warp tile 64x32, mma m16n8k8.
#define ASTR 36
#define TBUF 4608     // 128*36 floats per buffer

__global__ void __launch_bounds__(256) tmma(const float* __restrict__ A, int lda,
        const float* __restrict__ B, int ldb, float* __restrict__ C,
        int M, int N, int K,
        const float* __restrict__ bias, const float* __restrict__ addM, int addRowMod) {
    extern __shared__ float smf[];
    int tid = threadIdx.x, lane = tid & 31, wid = tid >> 5;
    int wm = wid & 1, wn = wid >> 1;
    int m0 = blockIdx.y * 128, n0 = blockIdx.x * 128;
    int gid = lane >> 2, tig = lane & 3;

    float acc[4][4][4];
    #pragma unroll
    for (int mi = 0; mi < 4; mi++)
        #pragma unroll
        for (int ni = 0; ni < 4; ni++)
            #pragma unroll
            for (int q = 0; q < 4; q++) acc[mi][ni][q] = 0.f;

    float4 ra[4], rb[4];
    int r_[4], c_[4];
    #pragma unroll
    for (int j = 0; j < 4; j++) { int idx = tid + j * 256; r_[j] = idx >> 3; c_[j] = (idx & 7) << 2; }

    int iters = K >> 5;
    #pragma unroll
    for (int j = 0; j < 4; j++) {
        ra[j] = *(const float4*)(A + (size_t)(m0 + r_[j]) * lda + c_[j]);
        int n = n0 + r_[j];
        rb[j] = (n < N) ? *(const float4*)(B + (size_t)n * ldb + c_[j]) : make_float4(0.f, 0.f, 0.f, 0.f);
    }
    {
        float* As0 = smf;
        float* Bs0 = smf + TBUF;
        #pragma unroll
        for (int j = 0; j < 4; j++) {
            float* pa = As0 + r_[j] * ASTR + c_[j];
            pa[0] = to_tf32(ra[j].x); pa[1] = to_tf32(ra[j].y); pa[2] = to_tf32(ra[j].z); pa[3] = to_tf32(ra[j].w);
            float* pb = Bs0 + r_[j] * ASTR + c_[j];
            pb[0] = to_tf32(rb[j].x); pb[1] = to_tf32(rb[j].y); pb[2] = to_tf32(rb[j].z); pb[3] = to_tf32(rb[j].w);
        }
    }
    __syncthreads();

    for (int it = 0; it < iters; it++) {
        const float* Asc = smf + (it & 1) * 2 * TBUF;
        const float* Bsc = Asc + TBUF;
        if (it + 1 < iters) {
            int k0 = (it + 1) << 5;
            #pragma unroll
            for (int j = 0; j < 4; j++) {
                ra[j] = *(const float4*)(A + (size_t)(m0 + r_[j]) * lda + k0 + c_[j]);
                int n = n0 + r_[j];
                rb[j] = (n < N) ? *(const float4*)(B + (size_t)n * ldb + k0 + c_[j]) : make_float4(0.f, 0.f, 0.f, 0.f);
            }
        }
        const uint32_t* Au = (const uint32_t*)Asc;
        const uint32_t* Bu = (const uint32_t*)Bsc;
        #pragma unroll
        for (int ks = 0; ks < 4; ks++) {
            int kb = ks * 8;
            uint32_t a[4][4], b[4][2];
            #pragma unroll
            for (int mi = 0; mi < 4; mi++) {
                const uint32_t* ap = Au + (wm * 64 + mi * 16 + gid) * ASTR + kb + tig;
                a[mi][0] = ap[0];
                a[mi][1] = ap[8 * ASTR];
                a[mi][2] = ap[4];
                a[mi][3] = ap[8 * ASTR + 4];
            }
            #pragma unroll
            for (int ni = 0; ni < 4; ni++) {
                const uint32_t* bp = Bu + (wn * 32 + ni * 8 + gid) * ASTR + kb + tig;
                b[ni][0] = bp[0];
                b[ni][1] = bp[4];
            }
            #pragma unroll
            for (int mi = 0; mi < 4; mi++)
                #pragma unroll
                for (int ni = 0; ni < 4; ni++)
                    mma8(acc[mi][ni], a[mi], b[ni]);
        }
        __syncthreads();
        if (it + 1 < iters) {
            float* Asn = smf + ((it + 1) & 1) * 2 * TBUF;
            float* Bsn = Asn + TBUF;
            #pragma unroll
            for (int j = 0; j < 4; j++) {
                float* pa = Asn + r_[j] * ASTR + c_[j];
                pa[0] = to_tf32(ra[j].x); pa[1] = to_tf32(ra[j].y); pa[2] = to_tf32(ra[j].z); pa[3] = to_tf32(ra[j].w);
                float* pb = Bsn + r_[j] * ASTR + c_[j];
                pb[0] = to_tf32(rb[j].x); pb[1] = to_tf32(rb[j].y); pb[2] = to_tf32(rb[j].z); pb[3] = to_tf32(rb[j].w);
            }
            __syncthreads();
        }
    }

    #pragma unroll
    for (int mi = 0; mi < 4; mi++) {
        int row0 = m0 + wm * 64 + mi * 16 + gid;
        #pragma unroll
        for (int ni = 0; ni < 4; ni++) {
            int col = n0 + wn * 32 + ni * 8 + tig * 2;
            #pragma unroll
            for (int half = 0; half < 2; half++) {
                int r = row0 + half * 8;
                float v0 = acc[mi][ni][half * 2 + 0];
                float v1 = acc[mi][ni][half * 2 + 1];
                if (bias) { v0 += bias[col]; v1 += (col + 1 < N) ? bias[col + 1] : 0.f; }
                if (addM) {
                    int ar = r % addRowMod;
                    v0 += addM[(size_t)ar * N + col];
                    if (col + 1 < N) v1 += addM[(size_t)ar * N + col + 1];
                }
                if (col < N)     C[(size_t)r * N + col]     = v0;
                if (col + 1 < N) C[(size_t)r * N + col + 1] = v1;
            }
        }
    }
}

// ======================= persistent recurrence (tf32 mma, 1 barrier/step) ==========
__device__ __forceinline__ void grid_barrier(unsigned nb) {
    __syncthreads();
    if (threadIdx.x == 0) {
        unsigned gen = *((volatile unsigned*)&d_barGen);
        __threadfence();
        if (atomicAdd(&d_barCount, 1u) == nb - 1u) {
            d_barCount = 0u;
            __threadfence();
            atomicAdd(&d_barGen, 1u);
        } else {
            while (*((volatile unsigned*)&d_barGen) == gen) {}
        }
        __threadfence();
    }
    __syncthreads();
}

// 128 blocks x 256 threads (one per SM, single wave). Block (mt,nt):
//   m rows = mt*32..+31 (batches), gate cols {g*512 + nt*16 + jj : g<4, jj<16}.
// Whh rows staged ONCE (permuted so block-local col lc -> Whh row (lc&3)*512+nt*16+(lc>>2)).
// Pointwise done locally: i,f live on even-tig lanes, g,o on odd; one shfl pairs them.
// h(t) written to hall[t] (distinct region per step) => single grid barrier per step.
#define RSTR 516
#define RS_SMEM ((32 * RSTR + 64 * RSTR) * 4)

__global__ void __launch_bounds__(256, 1) k_recur(const float* __restrict__ Whh) {
    extern __shared__ float rsm[];
    float* As = rsm;                 // 32 x 516
    float* Bs = rsm + 32 * RSTR;     // 64 x 516
    int bid = blockIdx.x, tid = threadIdx.x;
    int mt = bid >> 5, nt = bid & 31;
    int lane = tid & 31, wid = tid >> 5;
    int wm = wid & 1, wn = wid >> 1;
    int gid = lane >> 2, tig = lane & 3;

    // stage Whh block rows (once), with tf32 rounding
    for (int i = tid; i < 64 * 128; i += 256) {
        int r = i >> 7, q = (i & 127) << 2;
        int w = ((r & 3) << 9) + (nt << 4) + (r >> 2);
        float4 v = *(const float4*)(Whh + (size_t)w * NH + q);
        float* d = Bs + r * RSTR + q;
        d[0] = to_tf32(v.x); d[1] = to_tf32(v.y); d[2] = to_tf32(v.z); d[3] = to_tf32(v.w);
    }

    int mrow0 = mt * 32 + wm * 16 + gid;
    int g0 = (2 * tig) & 3, g1 = (2 * tig + 1) & 3;
    float creg[2][2];
    int jcol[2], gp0_[2], gp1_[2];
    #pragma unroll
    for (int ni = 0; ni < 2; ni++) {
        int jj = wn * 4 + ni * 2 + (tig >> 1);
        int j = nt * 16 + jj;
        jcol[ni] = j;
        gp0_[ni] = g0 * 512 + j;
        gp1_[ni] = g1 * 512 + j;
        creg[ni][0] = d_c0[mrow0 * NH + j];
        creg[ni][1] = d_c0[(mrow0 + 8) * NH + j];
    }

    for (int t = 0; t < NT; t++) {
        const float* hsrc = (t == 0) ? d_h0 : (d_hall + (size_t)(t - 1) * NB * NH);
        __syncthreads();
        for (int i = tid; i < 32 * 128; i += 256) {
            int r = i >> 7, q = (i & 127) << 2;
            float4 v = *(const float4*)(hsrc + (size_t)(mt * 32 + r) * NH + q);
            float* d = As + r * RSTR + q;
            d[0] = to_tf32(v.x); d[1] = to_tf32(v.y); d[2] = to_tf32(v.z); d[3] = to_tf32(v.w);
        }
        __syncthreads();

        float acc[2][4] = {{0.f, 0.f, 0.f, 0.f}, {0.f, 0.f, 0.f, 0.f}};
        const uint32_t* Au = (const uint32_t*)As;
        const uint32_t* Bu = (const uint32_t*)Bs;
        const uint32_t* apb = Au + (wm * 16 + gid) * RSTR + tig;
        #pragma unroll 4
        for (int k = 0; k < 512; k += 8) {
            uint32_t a[4];
            a[0] = apb[k]; a[1] = apb[k + 8 * RSTR]; a[2] = apb[k + 4]; a[3] = apb[k + 8 * RSTR + 4];
            #pragma unroll
            for (int ni = 0; ni < 2; ni++) {
                const uint32_t* bp = Bu + (wn * 16 + ni * 8 + gid) * RSTR + k + tig;
                uint32_t b[2];
                b[0] = bp[0]; b[1] = bp[4];
                mma8(acc[ni], a, b);
            }
        }

        // pointwise (local): add gpre, pair-exchange, LSTM, write hall[t]
        const float* gp = d_gpre + (size_t)t * NB * G4;
        float* hd = d_hall + (size_t)t * NB * NH;
        #pragma unroll
        for (int ni = 0; ni < 2; ni++) {
            float v0 = acc[ni][0] + gp[(size_t)mrow0 * G4 + gp0_[ni]];
            float v1 = acc[ni][1] + gp[(size_t)mrow0 * G4 + gp1_[ni]];
            float v2 = acc[ni][2] + gp[(size_t)(mrow0 + 8) * G4 + gp0_[ni]];
            float v3 = acc[ni][3] + gp[(size_t)(mrow0 + 8) * G4 + gp1_[ni]];
            float w0 = __shfl_xor_sync(0xffffffffu, v0, 1);
            float w1 = __shfl_xor_sync(0xffffffffu, v1, 1);
            float w2 = __shfl_xor_sync(0xffffffffu, v2, 1);
            float w3 = __shfl_xor_sync(0xffffffffu, v3, 1);
            float iA, fA, gA, oA, iB, fB, gB, oB;
            if ((tig & 1) == 0) { iA = v0; fA = v1; gA = w0; oA = w1; iB = v2; fB = v3; gB = w2; oB = w3; }
            else                { iA = w0; fA = w1; gA = v0; oA = v1; iB = w2; fB = w3; gB = v2; oB = v3; }
            float c0n = sigmoidf_(fA) * creg[ni][0] + sigmoidf_(iA) * tanhf(gA);
            float h0v = sigmoidf_(oA) * tanhf(c0n);
            creg[ni][0] = c0n;
            float c1n = sigmoidf_(fB) * creg[ni][1] + sigmoidf_(iB) * tanhf(gB);
            float h1v = sigmoidf_(oB) * tanhf(c1n);
            creg[ni][1] = c1n;
            if ((tig & 1) == 0) {
                hd[(size_t)mrow0 * NH + jcol[ni]] = h0v;
                hd[(size_t)(mrow0 + 8) * NH + jcol[ni]] = h1v;
            }
        }
        grid_barrier(gridDim.x);
    }
}

// ======================= output softmax =======================
__global__ void k_out(float* __restrict__ out) {
    __shared__ float row[NV];
    __shared__ float red[256];
    int r = blockIdx.x, tid = threadIdx.x;
    const float* L = d_logits + (size_t)r * NV;
    float mx = -1e30f;
    for (int v = tid; v < NV; v += 256) { float x = L[v]; row[v] = x; mx = fmaxf(mx, x); }
    red[tid] = mx; __syncthreads();
    for (int s = 128; s; s >>= 1) { if (tid < s) red[tid] = fmaxf(red[tid], red[tid + s]); __syncthreads(); }
    mx = red[0]; __syncthreads();
    float sum = 0.f;
    for (int v = tid; v < NV; v += 256) sum += __expf(row[v] - mx);
    red[tid] = sum; __syncthreads();
    for (int s = 128; s; s >>= 1) { if (tid < s) red[tid] += red[tid + s]; __syncthreads(); }
    float ls = logf(red[0]);
    float* o1 = out + (size_t)r * NV;
    float* o2 = out + (size_t)TBR * NV + (size_t)r * NV;
    for (int v = tid; v < NV; v += 256) {
        float lp = row[v] - mx - ls;
        o1[v] = lp;
        o2[v] = __expf(lp);
    }
}

// ======================= launch =======================
extern "C" void kernel_launch(void* const* d_in, const int* in_sizes, int n_in,
                              void* d_out, int out_size) {
    const float* features = (const float*)d_in[0];
    const int*   captions = (const int*)d_in[1];
    const float* W_init_h = (const float*)d_in[2];
    const float* W_init_c = (const float*)d_in[3];
    const float* Wv       = (const float*)d_in[4];
    const float* bv       = (const float*)d_in[5];
    // d_in[6]=Wa, d_in[7]=ba unused (softmax shift-invariance)
    const float* embed    = (const float*)d_in[8];
    const float* W_ih     = (const float*)d_in[9];
    const float* W_hh     = (const float*)d_in[10];
    const float* b_ih     = (const float*)d_in[11];
    const float* b_hh     = (const float*)d_in[12];
    const float* Wo       = (const float*)d_in[13];
    const float* bo       = (const float*)d_in[14];
    float* out = (float*)d_out;

    float *p_fs, *p_ctx, *p_h0, *p_c0, *p_gctx, *p_gpre, *p_bcomb, *p_logits, *p_emb, *p_hall;
    cudaGetSymbolAddress((void**)&p_fs,     d_feat_sum);
    cudaGetSymbolAddress((void**)&p_ctx,    d_ctx);
    cudaGetSymbolAddress((void**)&p_h0,     d_h0);
    cudaGetSymbolAddress((void**)&p_c0,     d_c0);
    cudaGetSymbolAddress((void**)&p_gctx,   d_gctx);
    cudaGetSymbolAddress((void**)&p_gpre,   d_gpre);
    cudaGetSymbolAddress((void**)&p_bcomb,  d_bcomb);
    cudaGetSymbolAddress((void**)&p_logits, d_logits);
    cudaGetSymbolAddress((void**)&p_emb,    d_emb);
    cudaGetSymbolAddress((void**)&p_hall,   d_hall);

    static int smset = 0;
    if (!smset) {
        cudaFuncSetAttribute(tmma, cudaFuncAttributeMaxDynamicSharedMemorySize, 4 * TBUF * 4);
        cudaFuncSetAttribute(k_recur, cudaFuncAttributeMaxDynamicSharedMemorySize, RS_SMEM);
        smset = 1;
    }

    // setup
    k_gather<<<TBR, NE>>>(captions, embed);
    k_vis<<<NB, 256>>>(features, Wv, bv);
    k_bias<<<(G4 + 255) / 256, 256>>>(b_ih, b_hh);

    // h0 / c0 / g_ctx (exact fp32 SIMT)
    gemm_nt<32, 64, 16, 2, 4><<<dim3(NH / 64, NB / 32), 256>>>(
        p_fs, VDIM, W_init_h, VDIM, p_h0, NB, NH, VDIM, 1.f / VNUM, nullptr);
    gemm_nt<32, 64, 16, 2, 4><<<dim3(NH / 64, NB / 32), 256>>>(
        p_fs, VDIM, W_init_c, VDIM, p_c0, NB, NH, VDIM, 1.f / VNUM, nullptr);
    gemm_nt<32, 64, 16, 2, 4><<<dim3(G4 / 64, NB / 32), 256>>>(
        p_ctx, VDIM, W_ih, VDIM + NE, p_gctx, NB, G4, VDIM, 1.f, p_bcomb);

    // g_pre = emb @ WihE^T + g_ctx[b]  (tf32 mma, cvt on load)
    tmma<<<dim3(G4 / 128, TBR / 128), 256, 4 * TBUF * 4>>>(
        p_emb, NE, W_ih + VDIM, VDIM + NE, p_gpre, TBR, G4, NE, nullptr, p_gctx, NB);

    // recurrence: tf32 mma persistent, 1 grid barrier / step
    k_recur<<<NB, 256, RS_SMEM>>>(W_hh);

    // logits = hall @ Wo^T + bo  (tf32 mma, cvt on load)
    tmma<<<dim3((NV + 127) / 128, TBR / 128), 256, 4 * TBUF * 4>>>(
        p_hall, NH, Wo, NH, p_logits, TBR, NV, NH, bo, nullptr, 0);

    k_out<<<TBR, 256>>>(out);
}

// round 5
// speedup vs baseline: 3.9212x; 1.2257x over previous
#include <cuda_runtime.h>
#include <math.h>
#include <stdint.h>

// Problem dims
#define NB   128
#define NT   20
#define VNUM 196
#define VDIM 512
#define NE   256
#define NH   512
#define NV   10000
#define G4   2048
#define TBR  2560   // NT*NB

// ---------------- tf32 helpers ----------------
__device__ __forceinline__ float to_tf32(float x) {
    uint32_t y;
    asm("cvt.rna.tf32.f32 %0, %1;" : "=r"(y) : "f"(x));
    return __uint_as_float(y);
}
__device__ __forceinline__ void mma8(float* c, const uint32_t* a, const uint32_t* b) {
    asm volatile("mma.sync.aligned.m16n8k8.row.col.f32.tf32.tf32.f32 "
                 "{%0,%1,%2,%3}, {%4,%5,%6,%7}, {%8,%9}, {%0,%1,%2,%3};"
                 : "+f"(c[0]), "+f"(c[1]), "+f"(c[2]), "+f"(c[3])
                 : "r"(a[0]), "r"(a[1]), "r"(a[2]), "r"(a[3]), "r"(b[0]), "r"(b[1]));
}
__device__ __forceinline__ float sigmoidf_(float x) { return 1.f / (1.f + __expf(-x)); }

// ---------------- scratch ----------------
__device__ float d_emb[TBR * NE];
__device__ float d_hall[(size_t)TBR * NH];
__device__ float d_feat_sum[NB * VDIM];
__device__ float d_ctx[NB * VDIM];
__device__ float d_h0[NB * NH];
__device__ float d_c0[NB * NH];
__device__ float d_gctx[NB * G4];
__device__ float d_gpre[(size_t)TBR * G4];
__device__ float d_logits[(size_t)TBR * NV];
__device__ unsigned d_barCount;
__device__ unsigned d_barGen;

// ---------------- embedding gather ----------------
__global__ void k_gather(const int* __restrict__ cap, const float* __restrict__ et) {
    int r = blockIdx.x;                 // t*NB + b
    int t = r / NB, b = r % NB;
    int id = cap[b * NT + t];
    d_emb[(size_t)r * NE + threadIdx.x] = et[(size_t)id * NE + threadIdx.x];
}

// ---------------- fused visual: att_v -> softmax -> feat_sum + ctx ----------------
__global__ void k_vis(const float* __restrict__ feat, const float* __restrict__ Wv,
                      const float* __restrict__ bv) {
    __shared__ float satt[VNUM];
    __shared__ float red[256];
    int b = blockIdx.x, tid = threadIdx.x;
    int warp = tid >> 5, lane = tid & 31;
    const float* fb = feat + (size_t)b * VNUM * VDIM;
    for (int n = warp; n < VNUM; n += 8) {
        const float* fr = fb + n * VDIM;
        float acc = 0.f;
        #pragma unroll
        for (int k = lane; k < VDIM; k += 32) acc += fr[k] * Wv[k];
        #pragma unroll
        for (int o = 16; o; o >>= 1) acc += __shfl_xor_sync(0xffffffffu, acc, o);
        if (lane == 0) satt[n] = acc + bv[0];
    }
    __syncthreads();
    float x = (tid < VNUM) ? satt[tid] : -1e30f;
    red[tid] = x; __syncthreads();
    for (int s = 128; s; s >>= 1) { if (tid < s) red[tid] = fmaxf(red[tid], red[tid + s]); __syncthreads(); }
    float mx = red[0]; __syncthreads();
    float e = (tid < VNUM) ? __expf(x - mx) : 0.f;
    red[tid] = e; __syncthreads();
    for (int s = 128; s; s >>= 1) { if (tid < s) red[tid] += red[tid + s]; __syncthreads(); }
    float inv = 1.f / red[0];
    __syncthreads();
    if (tid < VNUM) satt[tid] = e * inv;
    __syncthreads();
    for (int v = tid; v < VDIM; v += 256) {
        float fs = 0.f, c0 = 0.f, c1 = 0.f, c2 = 0.f, c3 = 0.f;
        int n = 0;
        for (; n + 4 <= VNUM; n += 4) {
            float x0 = fb[n * VDIM + v];
            float x1 = fb[(n + 1) * VDIM + v];
            float x2 = fb[(n + 2) * VDIM + v];
            float x3 = fb[(n + 3) * VDIM + v];
            fs += (x0 + x1) + (x2 + x3);
            c0 += satt[n] * x0; c1 += satt[n + 1] * x1;
            c2 += satt[n + 2] * x2; c3 += satt[n + 3] * x3;
        }
        for (; n < VNUM; n++) { float xx = fb[n * VDIM + v]; fs += xx; c0 += satt[n] * xx; }
        d_feat_sum[b * VDIM + v] = fs;
        d_ctx[b * VDIM + v] = (c0 + c1) + (c2 + c3);
    }
}

// ---------------- fused init GEMMs: h0 | c0 | g_ctx over concatenated N=3072 ----------------
// tiles 32x64, BK=16, 256 threads; grid = (48, 4) -> 192 blocks, full-chip wave.
// seg0 (ntile 0..7):   h0   = feat_sum @ W_init_h^T / 196
// seg1 (ntile 8..15):  c0   = feat_sum @ W_init_c^T / 196
// seg2 (ntile 16..47): gctx = ctx @ W_ih[:, :512]^T + b_ih + b_hh
__global__ void __launch_bounds__(256) k_init(
        const float* __restrict__ Wini_h, const float* __restrict__ Wini_c,
        const float* __restrict__ Wih,
        const float* __restrict__ bih, const float* __restrict__ bhh) {
    __shared__ float As[16][32];
    __shared__ float Bs[16][64];
    int ntile = blockIdx.x, mt = blockIdx.y;
    int seg, nloc0;
    const float* A;
    const float* B;
    int ldb;
    if (ntile < 8)       { seg = 0; nloc0 = ntile * 64;        A = d_feat_sum; B = Wini_h; ldb = VDIM; }
    else if (ntile < 16) { seg = 1; nloc0 = (ntile - 8) * 64;  A = d_feat_sum; B = Wini_c; ldb = VDIM; }
    else                 { seg = 2; nloc0 = (ntile - 16) * 64; A = d_ctx;      B = Wih;    ldb = VDIM + NE; }
    int tid = threadIdx.x;
    int tx = tid & 15, ty = tid >> 4;   // TN=4, TM=2
    int m0 = mt * 32;
    float acc[2][4] = {{0.f, 0.f, 0.f, 0.f}, {0.f, 0.f, 0.f, 0.f}};
    for (int k0 = 0; k0 < VDIM; k0 += 16) {
        {
            int i = tid; int r = i >> 4, kk = i & 15;
            As[kk][r] = A[(size_t)(m0 + r) * VDIM + k0 + kk];
            i = tid + 256; r = i >> 4; kk = i & 15;
            As[kk][r] = A[(size_t)(m0 + r) * VDIM + k0 + kk];
        }
        #pragma unroll
        for (int j = 0; j < 4; j++) {
            int i = tid + j * 256; int r = i >> 4, kk = i & 15;
            Bs[kk][r] = B[(size_t)(nloc0 + r) * ldb + k0 + kk];
        }
        __syncthreads();
        #pragma unroll
        for (int kk = 0; kk < 16; kk++) {
            float a0 = As[kk][ty * 2], a1 = As[kk][ty * 2 + 1];
            float b0 = Bs[kk][tx * 4], b1 = Bs[kk][tx * 4 + 1];
            float b2 = Bs[kk][tx * 4 + 2], b3 = Bs[kk][tx * 4 + 3];
            acc[0][0] += a0 * b0; acc[0][1] += a0 * b1; acc[0][2] += a0 * b2; acc[0][3] += a0 * b3;
            acc[1][0] += a1 * b0; acc[1][1] += a1 * b1; acc[1][2] += a1 * b2; acc[1][3] += a1 * b3;
        }
        __syncthreads();
    }
    float alpha = (seg == 2) ? 1.f : (1.f / VNUM);
    float* Cout = (seg == 0) ? d_h0 : (seg == 1) ? d_c0 : d_gctx;
    int Nout = (seg == 2) ? G4 : NH;
    #pragma unroll
    for (int i = 0; i < 2; i++) {
        int m = m0 + ty * 2 + i;
        #pragma unroll
        for (int j = 0; j < 4; j++) {
            int n = nloc0 + tx * 4 + j;
            float v = alpha * acc[i][j];
            if (seg == 2) v += bih[n] + bhh[n];
            Cout[(size_t)m * Nout + n] = v;
        }
    }
}

// ======================= tf32 mma.sync GEMM (cvt on load) =======================
#define ASTR 36
#define TBUF 4608     // 128*36 floats per buffer

__global__ void __launch_bounds__(256) tmma(const float* __restrict__ A, int lda,
        const float* __restrict__ B, int ldb, float* __restrict__ C,
        int M, int N, int K,
        const float* __restrict__ bias, const float* __restrict__ addM, int addRowMod) {
    extern __shared__ float smf[];
    int tid = threadIdx.x, lane = tid & 31, wid = tid >> 5;
    int wm = wid & 1, wn = wid >> 1;
    int m0 = blockIdx.y * 128, n0 = blockIdx.x * 128;
    int gid = lane >> 2, tig = lane & 3;

    float acc[4][4][4];
    #pragma unroll
    for (int mi = 0; mi < 4; mi++)
        #pragma unroll
        for (int ni = 0; ni < 4; ni++)
            #pragma unroll
            for (int q = 0; q < 4; q++) acc[mi][ni][q] = 0.f;

    float4 ra[4], rb[4];
    int r_[4], c_[4];
    #pragma unroll
    for (int j = 0; j < 4; j++) { int idx = tid + j * 256; r_[j] = idx >> 3; c_[j] = (idx & 7) << 2; }

    int iters = K >> 5;
    #pragma unroll
    for (int j = 0; j < 4; j++) {
        ra[j] = *(const float4*)(A + (size_t)(m0 + r_[j]) * lda + c_[j]);
        int n = n0 + r_[j];
        rb[j] = (n < N) ? *(const float4*)(B + (size_t)n * ldb + c_[j]) : make_float4(0.f, 0.f, 0.f, 0.f);
    }
    {
        float* As0 = smf;
        float* Bs0 = smf + TBUF;
        #pragma unroll
        for (int j = 0; j < 4; j++) {
            float* pa = As0 + r_[j] * ASTR + c_[j];
            pa[0] = to_tf32(ra[j].x); pa[1] = to_tf32(ra[j].y); pa[2] = to_tf32(ra[j].z); pa[3] = to_tf32(ra[j].w);
            float* pb = Bs0 + r_[j] * ASTR + c_[j];
            pb[0] = to_tf32(rb[j].x); pb[1] = to_tf32(rb[j].y); pb[2] = to_tf32(rb[j].z); pb[3] = to_tf32(rb[j].w);
        }
    }
    __syncthreads();

    for (int it = 0; it < iters; it++) {
        const float* Asc = smf + (it & 1) * 2 * TBUF;
        const float* Bsc = Asc + TBUF;
        if (it + 1 < iters) {
            int k0 = (it + 1) << 5;
            #pragma unroll
            for (int j = 0; j < 4; j++) {
                ra[j] = *(const float4*)(A + (size_t)(m0 + r_[j]) * lda + k0 + c_[j]);
                int n = n0 + r_[j];
                rb[j] = (n < N) ? *(const float4*)(B + (size_t)n * ldb + k0 + c_[j]) : make_float4(0.f, 0.f, 0.f, 0.f);
            }
        }
        const uint32_t* Au = (const uint32_t*)Asc;
        const uint32_t* Bu = (const uint32_t*)Bsc;
        #pragma unroll
        for (int ks = 0; ks < 4; ks++) {
            int kb = ks * 8;
            uint32_t a[4][4], b[4][2];
            #pragma unroll
            for (int mi = 0; mi < 4; mi++) {
                const uint32_t* ap = Au + (wm * 64 + mi * 16 + gid) * ASTR + kb + tig;
                a[mi][0] = ap[0];
                a[mi][1] = ap[8 * ASTR];
                a[mi][2] = ap[4];
                a[mi][3] = ap[8 * ASTR + 4];
            }
            #pragma unroll
            for (int ni = 0; ni < 4; ni++) {
                const uint32_t* bp = Bu + (wn * 32 + ni * 8 + gid) * ASTR + kb + tig;
                b[ni][0] = bp[0];
                b[ni][1] = bp[4];
            }
            #pragma unroll
            for (int mi = 0; mi < 4; mi++)
                #pragma unroll
                for (int ni = 0; ni < 4; ni++)
                    mma8(acc[mi][ni], a[mi], b[ni]);
        }
        __syncthreads();
        if (it + 1 < iters) {
            float* Asn = smf + ((it + 1) & 1) * 2 * TBUF;
            float* Bsn = Asn + TBUF;
            #pragma unroll
            for (int j = 0; j < 4; j++) {
                float* pa = Asn + r_[j] * ASTR + c_[j];
                pa[0] = to_tf32(ra[j].x); pa[1] = to_tf32(ra[j].y); pa[2] = to_tf32(ra[j].z); pa[3] = to_tf32(ra[j].w);
                float* pb = Bsn + r_[j] * ASTR + c_[j];
                pb[0] = to_tf32(rb[j].x); pb[1] = to_tf32(rb[j].y); pb[2] = to_tf32(rb[j].z); pb[3] = to_tf32(rb[j].w);
            }
            __syncthreads();
        }
    }

    #pragma unroll
    for (int mi = 0; mi < 4; mi++) {
        int row0 = m0 + wm * 64 + mi * 16 + gid;
        #pragma unroll
        for (int ni = 0; ni < 4; ni++) {
            int col = n0 + wn * 32 + ni * 8 + tig * 2;
            #pragma unroll
            for (int half = 0; half < 2; half++) {
                int r = row0 + half * 8;
                float v0 = acc[mi][ni][half * 2 + 0];
                float v1 = acc[mi][ni][half * 2 + 1];
                if (bias) { v0 += bias[col]; v1 += (col + 1 < N) ? bias[col + 1] : 0.f; }
                if (addM) {
                    int ar = r % addRowMod;
                    v0 += addM[(size_t)ar * N + col];
                    if (col + 1 < N) v1 += addM[(size_t)ar * N + col + 1];
                }
                if (col < N)     C[(size_t)r * N + col]     = v0;
                if (col + 1 < N) C[(size_t)r * N + col + 1] = v1;
            }
        }
    }
}

// ======================= persistent recurrence (tf32 mma, 1 barrier/step) ==========
__device__ __forceinline__ void grid_barrier(unsigned nb) {
    __syncthreads();
    if (threadIdx.x == 0) {
        unsigned gen = *((volatile unsigned*)&d_barGen);
        __threadfence();
        if (atomicAdd(&d_barCount, 1u) == nb - 1u) {
            d_barCount = 0u;
            __threadfence();
            atomicAdd(&d_barGen, 1u);
        } else {
            while (*((volatile unsigned*)&d_barGen) == gen) {}
        }
        __threadfence();
    }
    __syncthreads();
}

#define RSTR 516
#define RS_SMEM ((32 * RSTR + 64 * RSTR) * 4)

__global__ void __launch_bounds__(256, 1) k_recur(const float* __restrict__ Whh) {
    extern __shared__ float rsm[];
    float* As = rsm;                 // 32 x 516
    float* Bs = rsm + 32 * RSTR;     // 64 x 516
    int bid = blockIdx.x, tid = threadIdx.x;
    int mt = bid >> 5, nt = bid & 31;
    int lane = tid & 31, wid = tid >> 5;
    int wm = wid & 1, wn = wid >> 1;
    int gid = lane >> 2, tig = lane & 3;

    for (int i = tid; i < 64 * 128; i += 256) {
        int r = i >> 7, q = (i & 127) << 2;
        int w = ((r & 3) << 9) + (nt << 4) + (r >> 2);
        float4 v = *(const float4*)(Whh + (size_t)w * NH + q);
        float* d = Bs + r * RSTR + q;
        d[0] = to_tf32(v.x); d[1] = to_tf32(v.y); d[2] = to_tf32(v.z); d[3] = to_tf32(v.w);
    }

    int mrow0 = mt * 32 + wm * 16 + gid;
    int g0 = (2 * tig) & 3, g1 = (2 * tig + 1) & 3;
    float creg[2][2];
    int jcol[2], gp0_[2], gp1_[2];
    #pragma unroll
    for (int ni = 0; ni < 2; ni++) {
        int jj = wn * 4 + ni * 2 + (tig >> 1);
        int j = nt * 16 + jj;
        jcol[ni] = j;
        gp0_[ni] = g0 * 512 + j;
        gp1_[ni] = g1 * 512 + j;
        creg[ni][0] = d_c0[mrow0 * NH + j];
        creg[ni][1] = d_c0[(mrow0 + 8) * NH + j];
    }

    for (int t = 0; t < NT; t++) {
        const float* hsrc = (t == 0) ? d_h0 : (d_hall + (size_t)(t - 1) * NB * NH);
        __syncthreads();
        for (int i = tid; i < 32 * 128; i += 256) {
            int r = i >> 7, q = (i & 127) << 2;
            float4 v = *(const float4*)(hsrc + (size_t)(mt * 32 + r) * NH + q);
            float* d = As + r * RSTR + q;
            d[0] = to_tf32(v.x); d[1] = to_tf32(v.y); d[2] = to_tf32(v.z); d[3] = to_tf32(v.w);
        }
        __syncthreads();

        float acc[2][4] = {{0.f, 0.f, 0.f, 0.f}, {0.f, 0.f, 0.f, 0.f}};
        const uint32_t* Au = (const uint32_t*)As;
        const uint32_t* Bu = (const uint32_t*)Bs;
        const uint32_t* apb = Au + (wm * 16 + gid) * RSTR + tig;
        #pragma unroll 4
        for (int k = 0; k < 512; k += 8) {
            uint32_t a[4];
            a[0] = apb[k]; a[1] = apb[k + 8 * RSTR]; a[2] = apb[k + 4]; a[3] = apb[k + 8 * RSTR + 4];
            #pragma unroll
            for (int ni = 0; ni < 2; ni++) {
                const uint32_t* bp = Bu + (wn * 16 + ni * 8 + gid) * RSTR + k + tig;
                uint32_t b[2];
                b[0] = bp[0]; b[1] = bp[4];
                mma8(acc[ni], a, b);
            }
        }

        const float* gp = d_gpre + (size_t)t * NB * G4;
        float* hd = d_hall + (size_t)t * NB * NH;
        #pragma unroll
        for (int ni = 0; ni < 2; ni++) {
            float v0 = acc[ni][0] + gp[(size_t)mrow0 * G4 + gp0_[ni]];
            float v1 = acc[ni][1] + gp[(size_t)mrow0 * G4 + gp1_[ni]];
            float v2 = acc[ni][2] + gp[(size_t)(mrow0 + 8) * G4 + gp0_[ni]];
            float v3 = acc[ni][3] + gp[(size_t)(mrow0 + 8) * G4 + gp1_[ni]];
            float w0 = __shfl_xor_sync(0xffffffffu, v0, 1);
            float w1 = __shfl_xor_sync(0xffffffffu, v1, 1);
            float w2 = __shfl_xor_sync(0xffffffffu, v2, 1);
            float w3 = __shfl_xor_sync(0xffffffffu, v3, 1);
            float iA, fA, gA, oA, iB, fB, gB, oB;
            if ((tig & 1) == 0) { iA = v0; fA = v1; gA = w0; oA = w1; iB = v2; fB = v3; gB = w2; oB = w3; }
            else                { iA = w0; fA = w1; gA = v0; oA = v1; iB = w2; fB = w3; gB = v2; oB = v3; }
            float c0n = sigmoidf_(fA) * creg[ni][0] + sigmoidf_(iA) * tanhf(gA);
            float h0v = sigmoidf_(oA) * tanhf(c0n);
            creg[ni][0] = c0n;
            float c1n = sigmoidf_(fB) * creg[ni][1] + sigmoidf_(iB) * tanhf(gB);
            float h1v = sigmoidf_(oB) * tanhf(c1n);
            creg[ni][1] = c1n;
            if ((tig & 1) == 0) {
                hd[(size_t)mrow0 * NH + jcol[ni]] = h0v;
                hd[(size_t)(mrow0 + 8) * NH + jcol[ni]] = h1v;
            }
        }
        grid_barrier(gridDim.x);
    }
}

// ======================= output softmax =======================
__global__ void k_out(float* __restrict__ out) {
    __shared__ float row[NV];
    __shared__ float red[256];
    int r = blockIdx.x, tid = threadIdx.x;
    const float* L = d_logits + (size_t)r * NV;
    float mx = -1e30f;
    for (int v = tid; v < NV; v += 256) { float x = L[v]; row[v] = x; mx = fmaxf(mx, x); }
    red[tid] = mx; __syncthreads();
    for (int s = 128; s; s >>= 1) { if (tid < s) red[tid] = fmaxf(red[tid], red[tid + s]); __syncthreads(); }
    mx = red[0]; __syncthreads();
    float sum = 0.f;
    for (int v = tid; v < NV; v += 256) sum += __expf(row[v] - mx);
    red[tid] = sum; __syncthreads();
    for (int s = 128; s; s >>= 1) { if (tid < s) red[tid] += red[tid + s]; __syncthreads(); }
    float ls = logf(red[0]);
    float* o1 = out + (size_t)r * NV;
    float* o2 = out + (size_t)TBR * NV + (size_t)r * NV;
    for (int v = tid; v < NV; v += 256) {
        float lp = row[v] - mx - ls;
        o1[v] = lp;
        o2[v] = __expf(lp);
    }
}

// ======================= launch =======================
extern "C" void kernel_launch(void* const* d_in, const int* in_sizes, int n_in,
                              void* d_out, int out_size) {
    const float* features = (const float*)d_in[0];
    const int*   captions = (const int*)d_in[1];
    const float* W_init_h = (const float*)d_in[2];
    const float* W_init_c = (const float*)d_in[3];
    const float* Wv       = (const float*)d_in[4];
    const float* bv       = (const float*)d_in[5];
    // d_in[6]=Wa, d_in[7]=ba unused (softmax shift-invariance)
    const float* embed    = (const float*)d_in[8];
    const float* W_ih     = (const float*)d_in[9];
    const float* W_hh     = (const float*)d_in[10];
    const float* b_ih     = (const float*)d_in[11];
    const float* b_hh     = (const float*)d_in[12];
    const float* Wo       = (const float*)d_in[13];
    const float* bo       = (const float*)d_in[14];
    float* out = (float*)d_out;

    float *p_gctx, *p_gpre, *p_logits, *p_emb, *p_hall;
    cudaGetSymbolAddress((void**)&p_gctx,   d_gctx);
    cudaGetSymbolAddress((void**)&p_gpre,   d_gpre);
    cudaGetSymbolAddress((void**)&p_logits, d_logits);
    cudaGetSymbolAddress((void**)&p_emb,    d_emb);
    cudaGetSymbolAddress((void**)&p_hall,   d_hall);

    static int smset = 0;
    if (!smset) {
        cudaFuncSetAttribute(tmma, cudaFuncAttributeMaxDynamicSharedMemorySize, 4 * TBUF * 4);
        cudaFuncSetAttribute(k_recur, cudaFuncAttributeMaxDynamicSharedMemorySize, RS_SMEM);
        smset = 1;
    }

    // setup
    k_gather<<<TBR, NE>>>(captions, embed);
    k_vis<<<NB, 256>>>(features, Wv, bv);

    // fused h0 | c0 | g_ctx : one full-chip wave (192 blocks)
    k_init<<<dim3(48, 4), 256>>>(W_init_h, W_init_c, W_ih, b_ih, b_hh);

    // g_pre = emb @ WihE^T + g_ctx[b]  (tf32 mma, cvt on load)
    tmma<<<dim3(G4 / 128, TBR / 128), 256, 4 * TBUF * 4>>>(
        p_emb, NE, W_ih + VDIM, VDIM + NE, p_gpre, TBR, G4, NE, nullptr, p_gctx, NB);

    // recurrence: tf32 mma persistent, 1 grid barrier / step
    k_recur<<<NB, 256, RS_SMEM>>>(W_hh);

    // logits = hall @ Wo^T + bo  (tf32 mma, cvt on load)
    tmma<<<dim3((NV + 127) / 128, TBR / 128), 256, 4 * TBUF * 4>>>(
        p_hall, NH, Wo, NH, p_logits, TBR, NV, NH, bo, nullptr, 0);

    k_out<<<TBR, 256>>>(out);
}

// round 6
// speedup vs baseline: 4.1475x; 1.0577x over previous
#include <cuda_runtime.h>
#include <cuda_bf16.h>
#include <math.h>
#include <stdint.h>

// Problem dims
#define NB   128
#define NT   20
#define VNUM 196
#define VDIM 512
#define NE   256
#define NH   512
#define NV   10000
#define G4   2048
#define TBR  2560   // NT*NB

// ---------------- helpers ----------------
__device__ __forceinline__ float to_tf32(float x) {
    uint32_t y;
    asm("cvt.rna.tf32.f32 %0, %1;" : "=r"(y) : "f"(x));
    return __uint_as_float(y);
}
__device__ __forceinline__ void mma8(float* c, const uint32_t* a, const uint32_t* b) {
    asm volatile("mma.sync.aligned.m16n8k8.row.col.f32.tf32.tf32.f32 "
                 "{%0,%1,%2,%3}, {%4,%5,%6,%7}, {%8,%9}, {%0,%1,%2,%3};"
                 : "+f"(c[0]), "+f"(c[1]), "+f"(c[2]), "+f"(c[3])
                 : "r"(a[0]), "r"(a[1]), "r"(a[2]), "r"(a[3]), "r"(b[0]), "r"(b[1]));
}
__device__ __forceinline__ void mma16(float* c, const uint32_t* a, const uint32_t* b) {
    asm volatile("mma.sync.aligned.m16n8k16.row.col.f32.bf16.bf16.f32 "
                 "{%0,%1,%2,%3}, {%4,%5,%6,%7}, {%8,%9}, {%0,%1,%2,%3};"
                 : "+f"(c[0]), "+f"(c[1]), "+f"(c[2]), "+f"(c[3])
                 : "r"(a[0]), "r"(a[1]), "r"(a[2]), "r"(a[3]), "r"(b[0]), "r"(b[1]));
}
__device__ __forceinline__ uint32_t smem_u32(const void* p) {
    uint32_t a;
    asm("{ .reg .u64 t; cvta.to.shared.u64 t, %1; cvt.u32.u64 %0, t; }" : "=r"(a) : "l"(p));
    return a;
}
__device__ __forceinline__ void ldsm4(uint32_t* r, uint32_t addr) {
    asm volatile("ldmatrix.sync.aligned.m8n8.x4.shared.b16 {%0,%1,%2,%3}, [%4];"
                 : "=r"(r[0]), "=r"(r[1]), "=r"(r[2]), "=r"(r[3]) : "r"(addr));
}
__device__ __forceinline__ void cpa16(uint32_t saddr, const void* gaddr, uint32_t srcsz) {
    asm volatile("cp.async.cg.shared.global [%0], [%1], 16, %2;"
                 :: "r"(saddr), "l"(gaddr), "r"(srcsz));
}
#define CP_COMMIT() asm volatile("cp.async.commit_group;")
#define CP_WAIT0()  asm volatile("cp.async.wait_group 0;")
__device__ __forceinline__ float sigmoidf_(float x) { return 1.f / (1.f + __expf(-x)); }

// ---------------- scratch ----------------
__device__ __nv_bfloat16 d_emb_bf[TBR * NE];
__device__ __nv_bfloat16 d_wo_bf[(size_t)NV * NH];
__device__ __nv_bfloat16 d_wih_bf[G4 * NE];
__device__ __nv_bfloat16 d_hall_bf[(size_t)TBR * NH];
__device__ float d_hall[(size_t)TBR * NH];
__device__ float d_feat_sum[NB * VDIM];
__device__ float d_ctx[NB * VDIM];
__device__ float d_h0[NB * NH];
__device__ float d_c0[NB * NH];
__device__ float d_gctx[NB * G4];
__device__ float d_gpre[(size_t)TBR * G4];
__device__ float d_logits[(size_t)TBR * NV];
__device__ unsigned d_barCount;
__device__ unsigned d_barGen;

// ---------------- embedding gather -> bf16 ----------------
__global__ void k_gather(const int* __restrict__ cap, const float* __restrict__ et) {
    int r = blockIdx.x;                 // t*NB + b
    int t = r / NB, b = r % NB;
    int id = cap[b * NT + t];
    d_emb_bf[(size_t)r * NE + threadIdx.x] = __float2bfloat16(et[(size_t)id * NE + threadIdx.x]);
}

// ---------------- strided fp32 -> bf16 (4 elems/thread) ----------------
__global__ void k_cvtb(const float* __restrict__ src, int pitch, int cols,
                       __nv_bfloat16* __restrict__ dst, int n4) {
    int i = blockIdx.x * 256 + threadIdx.x;
    if (i >= n4) return;
    int e = i * 4;
    int r = e / cols, c = e % cols;
    float4 v = *(const float4*)(src + (size_t)r * pitch + c);
    __nv_bfloat16* d = dst + e;
    d[0] = __float2bfloat16(v.x);
    d[1] = __float2bfloat16(v.y);
    d[2] = __float2bfloat16(v.z);
    d[3] = __float2bfloat16(v.w);
}

// ---------------- fused visual: att_v -> softmax -> feat_sum + ctx ----------------
__global__ void k_vis(const float* __restrict__ feat, const float* __restrict__ Wv,
                      const float* __restrict__ bv) {
    __shared__ float satt[VNUM];
    __shared__ float red[256];
    int b = blockIdx.x, tid = threadIdx.x;
    int warp = tid >> 5, lane = tid & 31;
    const float* fb = feat + (size_t)b * VNUM * VDIM;
    for (int n = warp; n < VNUM; n += 8) {
        const float* fr = fb + n * VDIM;
        float acc = 0.f;
        #pragma unroll
        for (int k = lane; k < VDIM; k += 32) acc += fr[k] * Wv[k];
        #pragma unroll
        for (int o = 16; o; o >>= 1) acc += __shfl_xor_sync(0xffffffffu, acc, o);
        if (lane == 0) satt[n] = acc + bv[0];
    }
    __syncthreads();
    float x = (tid < VNUM) ? satt[tid] : -1e30f;
    red[tid] = x; __syncthreads();
    for (int s = 128; s; s >>= 1) { if (tid < s) red[tid] = fmaxf(red[tid], red[tid + s]); __syncthreads(); }
    float mx = red[0]; __syncthreads();
    float e = (tid < VNUM) ? __expf(x - mx) : 0.f;
    red[tid] = e; __syncthreads();
    for (int s = 128; s; s >>= 1) { if (tid < s) red[tid] += red[tid + s]; __syncthreads(); }
    float inv = 1.f / red[0];
    __syncthreads();
    if (tid < VNUM) satt[tid] = e * inv;
    __syncthreads();
    for (int v = tid; v < VDIM; v += 256) {
        float fs = 0.f, c0 = 0.f, c1 = 0.f, c2 = 0.f, c3 = 0.f;
        int n = 0;
        for (; n + 4 <= VNUM; n += 4) {
            float x0 = fb[n * VDIM + v];
            float x1 = fb[(n + 1) * VDIM + v];
            float x2 = fb[(n + 2) * VDIM + v];
            float x3 = fb[(n + 3) * VDIM + v];
            fs += (x0 + x1) + (x2 + x3);
            c0 += satt[n] * x0; c1 += satt[n + 1] * x1;
            c2 += satt[n + 2] * x2; c3 += satt[n + 3] * x3;
        }
        for (; n < VNUM; n++) { float xx = fb[n * VDIM + v]; fs += xx; c0 += satt[n] * xx; }
        d_feat_sum[b * VDIM + v] = fs;
        d_ctx[b * VDIM + v] = (c0 + c1) + (c2 + c3);
    }
}

// ---------------- fused init GEMMs: h0 | c0 | g_ctx (N=3072 concat) ----------------
__global__ void __launch_bounds__(256) k_init(
        const float* __restrict__ Wini_h, const float* __restrict__ Wini_c,
        const float* __restrict__ Wih,
        const float* __restrict__ bih, const float* __restrict__ bhh) {
    __shared__ float As[16][32];
    __shared__ float Bs[16][64];
    int ntile = blockIdx.x, mt = blockIdx.y;
    int seg, nloc0;
    const float* A;
    const float* B;
    int ldb;
    if (ntile < 8)       { seg = 0; nloc0 = ntile * 64;        A = d_feat_sum; B = Wini_h; ldb = VDIM; }
    else if (ntile < 16) { seg = 1; nloc0 = (ntile - 8) * 64;  A = d_feat_sum; B = Wini_c; ldb = VDIM; }
    else                 { seg = 2; nloc0 = (ntile - 16) * 64; A = d_ctx;      B = Wih;    ldb = VDIM + NE; }
    int tid = threadIdx.x;
    int tx = tid & 15, ty = tid >> 4;
    int m0 = mt * 32;
    float acc[2][4] = {{0.f, 0.f, 0.f, 0.f}, {0.f, 0.f, 0.f, 0.f}};
    for (int k0 = 0; k0 < VDIM; k0 += 16) {
        {
            int i = tid; int r = i >> 4, kk = i & 15;
            As[kk][r] = A[(size_t)(m0 + r) * VDIM + k0 + kk];
            i = tid + 256; r = i >> 4; kk = i & 15;
            As[kk][r] = A[(size_t)(m0 + r) * VDIM + k0 + kk];
        }
        #pragma unroll
        for (int j = 0; j < 4; j++) {
            int i = tid + j * 256; int r = i >> 4, kk = i & 15;
            Bs[kk][r] = B[(size_t)(nloc0 + r) * ldb + k0 + kk];
        }
        __syncthreads();
        #pragma unroll
        for (int kk = 0; kk < 16; kk++) {
            float a0 = As[kk][ty * 2], a1 = As[kk][ty * 2 + 1];
            float b0 = Bs[kk][tx * 4], b1 = Bs[kk][tx * 4 + 1];
            float b2 = Bs[kk][tx * 4 + 2], b3 = Bs[kk][tx * 4 + 3];
            acc[0][0] += a0 * b0; acc[0][1] += a0 * b1; acc[0][2] += a0 * b2; acc[0][3] += a0 * b3;
            acc[1][0] += a1 * b0; acc[1][1] += a1 * b1; acc[1][2] += a1 * b2; acc[1][3] += a1 * b3;
        }
        __syncthreads();
    }
    float alpha = (seg == 2) ? 1.f : (1.f / VNUM);
    float* Cout = (seg == 0) ? d_h0 : (seg == 1) ? d_c0 : d_gctx;
    int Nout = (seg == 2) ? G4 : NH;
    #pragma unroll
    for (int i = 0; i < 2; i++) {
        int m = m0 + ty * 2 + i;
        #pragma unroll
        for (int j = 0; j < 4; j++) {
            int n = nloc0 + tx * 4 + j;
            float v = alpha * acc[i][j];
            if (seg == 2) v += bih[n] + bhh[n];
            Cout[(size_t)m * Nout + n] = v;
        }
    }
}

// ======================= bf16 mma GEMM: ldmatrix + cp.async =======================
// C[m,n] = dot(A[m,:K], B[n,:K]) + bias[n] + addM[m % addRowMod][n]
// A,B bf16 row-major (lda/ldb elems). BM=BN=128, BK=32, 8 warps (2m x 4n), warp 64x32.
// smem rows stride 40 bf16 (80B): conflict-free ldmatrix (rows hit all 32 banks).
#define BSTR 40

__global__ void __launch_bounds__(256) tbmma(const __nv_bfloat16* __restrict__ A, int lda,
        const __nv_bfloat16* __restrict__ B, int ldb, float* __restrict__ C,
        int M, int N, int K,
        const float* __restrict__ bias, const float* __restrict__ addM, int addRowMod) {
    __shared__ __align__(16) __nv_bfloat16 sA[2][128 * BSTR];
    __shared__ __align__(16) __nv_bfloat16 sB[2][128 * BSTR];
    int tid = threadIdx.x, lane = tid & 31, wid = tid >> 5;
    int wm = wid & 1, wn = wid >> 1;
    int m0 = blockIdx.y * 128, n0 = blockIdx.x * 128;
    int gid = lane >> 2, tig = lane & 3;

    float acc[4][4][4];
    #pragma unroll
    for (int mi = 0; mi < 4; mi++)
        #pragma unroll
        for (int ni = 0; ni < 4; ni++)
            #pragma unroll
            for (int q = 0; q < 4; q++) acc[mi][ni][q] = 0.f;

    // staging tasks: A: idx=tid, tid+256 ; B: same. row = idx>>2, seg = idx&3 (16B each)
    int ar0 = tid >> 2, as0 = tid & 3;
    int ar1 = (tid + 256) >> 2, as1 = tid & 3;   // (tid+256)&3 == tid&3
    uint32_t sA0 = smem_u32(&sA[0][0]), sB0 = smem_u32(&sB[0][0]);
    uint32_t bufStride = 128 * BSTR * 2;

    int iters = K >> 5;
    // ldmatrix lane addressing precompute
    int lrow = lane & 15;
    int lcg = (lane >> 4) << 3;   // 0 or 8 elems

    #define STAGE(ck, bsel) do {                                                          \
        int k0_ = (ck) << 5;                                                              \
        uint32_t da = sA0 + (bsel) * bufStride;                                           \
        uint32_t db = sB0 + (bsel) * bufStride;                                           \
        cpa16(da + (ar0 * BSTR + as0 * 8) * 2, A + (size_t)(m0 + ar0) * lda + k0_ + as0 * 8, 16u); \
        cpa16(da + (ar1 * BSTR + as1 * 8) * 2, A + (size_t)(m0 + ar1) * lda + k0_ + as1 * 8, 16u); \
        { int n = n0 + ar0; uint32_t sz = (n < N) ? 16u : 0u;                             \
          cpa16(db + (ar0 * BSTR + as0 * 8) * 2, B + (size_t)(n < N ? n : 0) * ldb + k0_ + as0 * 8, sz); } \
        { int n = n0 + ar1; uint32_t sz = (n < N) ? 16u : 0u;                             \
          cpa16(db + (ar1 * BSTR + as1 * 8) * 2, B + (size_t)(n < N ? n : 0) * ldb + k0_ + as1 * 8, sz); } \
        CP_COMMIT();                                                                      \
    } while (0)

    STAGE(0, 0);

    for (int it = 0; it < iters; it++) {
        CP_WAIT0();
        __syncthreads();
        if (it + 1 < iters) STAGE(it + 1, (it + 1) & 1);
        uint32_t ab = sA0 + (it & 1) * bufStride;
        uint32_t bb = sB0 + (it & 1) * bufStride;
        #pragma unroll
        for (int ks = 0; ks < 2; ks++) {
            int kofs = ks * 16 + lcg;
            uint32_t a[4][4], b[4][2];
            #pragma unroll
            for (int mi = 0; mi < 4; mi++)
                ldsm4(a[mi], ab + ((wm * 64 + mi * 16 + lrow) * BSTR + kofs) * 2);
            #pragma unroll
            for (int np = 0; np < 2; np++) {
                uint32_t r[4];
                ldsm4(r, bb + ((wn * 32 + np * 16 + lrow) * BSTR + kofs) * 2);
                b[2 * np][0] = r[0]; b[2 * np + 1][0] = r[1];
                b[2 * np][1] = r[2]; b[2 * np + 1][1] = r[3];
            }
            #pragma unroll
            for (int mi = 0; mi < 4; mi++)
                #pragma unroll
                for (int ni = 0; ni < 4; ni++)
                    mma16(acc[mi][ni], a[mi], b[ni]);
        }
        __syncthreads();
    }

    #pragma unroll
    for (int mi = 0; mi < 4; mi++) {
        int row0 = m0 + wm * 64 + mi * 16 + gid;
        #pragma unroll
        for (int ni = 0; ni < 4; ni++) {
            int col = n0 + wn * 32 + ni * 8 + tig * 2;
            #pragma unroll
            for (int half = 0; half < 2; half++) {
                int r = row0 + half * 8;
                float v0 = acc[mi][ni][half * 2 + 0];
                float v1 = acc[mi][ni][half * 2 + 1];
                if (bias) { v0 += bias[col]; v1 += (col + 1 < N) ? bias[col + 1] : 0.f; }
                if (addM) {
                    int ar = r % addRowMod;
                    v0 += addM[(size_t)ar * N + col];
                    if (col + 1 < N) v1 += addM[(size_t)ar * N + col + 1];
                }
                if (col < N)     C[(size_t)r * N + col]     = v0;
                if (col + 1 < N) C[(size_t)r * N + col + 1] = v1;
            }
        }
    }
    #undef STAGE
}

// ======================= persistent recurrence (tf32 mma, 1 barrier/step) ==========
__device__ __forceinline__ void grid_barrier(unsigned nb) {
    __syncthreads();
    if (threadIdx.x == 0) {
        unsigned gen = *((volatile unsigned*)&d_barGen);
        __threadfence();
        if (atomicAdd(&d_barCount, 1u) == nb - 1u) {
            d_barCount = 0u;
            __threadfence();
            atomicAdd(&d_barGen, 1u);
        } else {
            while (*((volatile unsigned*)&d_barGen) == gen) {}
        }
        __threadfence();
    }
    __syncthreads();
}

#define RSTR 516
#define RS_SMEM ((32 * RSTR + 64 * RSTR) * 4)

__global__ void __launch_bounds__(256, 1) k_recur(const float* __restrict__ Whh) {
    extern __shared__ float rsm[];
    float* As = rsm;                 // 32 x 516
    float* Bs = rsm + 32 * RSTR;     // 64 x 516
    int bid = blockIdx.x, tid = threadIdx.x;
    int mt = bid >> 5, nt = bid & 31;
    int lane = tid & 31, wid = tid >> 5;
    int wm = wid & 1, wn = wid >> 1;
    int gid = lane >> 2, tig = lane & 3;

    for (int i = tid; i < 64 * 128; i += 256) {
        int r = i >> 7, q = (i & 127) << 2;
        int w = ((r & 3) << 9) + (nt << 4) + (r >> 2);
        float4 v = *(const float4*)(Whh + (size_t)w * NH + q);
        float* d = Bs + r * RSTR + q;
        d[0] = to_tf32(v.x); d[1] = to_tf32(v.y); d[2] = to_tf32(v.z); d[3] = to_tf32(v.w);
    }

    int mrow0 = mt * 32 + wm * 16 + gid;
    int g0 = (2 * tig) & 3, g1 = (2 * tig + 1) & 3;
    float creg[2][2];
    int jcol[2], gp0_[2], gp1_[2];
    #pragma unroll
    for (int ni = 0; ni < 2; ni++) {
        int jj = wn * 4 + ni * 2 + (tig >> 1);
        int j = nt * 16 + jj;
        jcol[ni] = j;
        gp0_[ni] = g0 * 512 + j;
        gp1_[ni] = g1 * 512 + j;
        creg[ni][0] = d_c0[mrow0 * NH + j];
        creg[ni][1] = d_c0[(mrow0 + 8) * NH + j];
    }

    for (int t = 0; t < NT; t++) {
        const float* hsrc = (t == 0) ? d_h0 : (d_hall + (size_t)(t - 1) * NB * NH);
        __syncthreads();
        for (int i = tid; i < 32 * 128; i += 256) {
            int r = i >> 7, q = (i & 127) << 2;
            float4 v = *(const float4*)(hsrc + (size_t)(mt * 32 + r) * NH + q);
            float* d = As + r * RSTR + q;
            d[0] = to_tf32(v.x); d[1] = to_tf32(v.y); d[2] = to_tf32(v.z); d[3] = to_tf32(v.w);
        }
        __syncthreads();

        float acc[2][4] = {{0.f, 0.f, 0.f, 0.f}, {0.f, 0.f, 0.f, 0.f}};
        const uint32_t* Au = (const uint32_t*)As;
        const uint32_t* Bu = (const uint32_t*)Bs;
        const uint32_t* apb = Au + (wm * 16 + gid) * RSTR + tig;
        #pragma unroll 4
        for (int k = 0; k < 512; k += 8) {
            uint32_t a[4];
            a[0] = apb[k]; a[1] = apb[k + 8 * RSTR]; a[2] = apb[k + 4]; a[3] = apb[k + 8 * RSTR + 4];
            #pragma unroll
            for (int ni = 0; ni < 2; ni++) {
                const uint32_t* bp = Bu + (wn * 16 + ni * 8 + gid) * RSTR + k + tig;
                uint32_t b[2];
                b[0] = bp[0]; b[1] = bp[4];
                mma8(acc[ni], a, b);
            }
        }

        const float* gp = d_gpre + (size_t)t * NB * G4;
        float* hd = d_hall + (size_t)t * NB * NH;
        __nv_bfloat16* hb = d_hall_bf + (size_t)t * NB * NH;
        #pragma unroll
        for (int ni = 0; ni < 2; ni++) {
            float v0 = acc[ni][0] + gp[(size_t)mrow0 * G4 + gp0_[ni]];
            float v1 = acc[ni][1] + gp[(size_t)mrow0 * G4 + gp1_[ni]];
            float v2 = acc[ni][2] + gp[(size_t)(mrow0 + 8) * G4 + gp0_[ni]];
            float v3 = acc[ni][3] + gp[(size_t)(mrow0 + 8) * G4 + gp1_[ni]];
            float w0 = __shfl_xor_sync(0xffffffffu, v0, 1);
            float w1 = __shfl_xor_sync(0xffffffffu, v1, 1);
            float w2 = __shfl_xor_sync(0xffffffffu, v2, 1);
            float w3 = __shfl_xor_sync(0xffffffffu, v3, 1);
            float iA, fA, gA, oA, iB, fB, gB, oB;
            if ((tig & 1) == 0) { iA = v0; fA = v1; gA = w0; oA = w1; iB = v2; fB = v3; gB = w2; oB = w3; }
            else                { iA = w0; fA = w1; gA = v0; oA = v1; iB = w2; fB = w3; gB = v2; oB = v3; }
            float c0n = sigmoidf_(fA) * creg[ni][0] + sigmoidf_(iA) * tanhf(gA);
            float h0v = sigmoidf_(oA) * tanhf(c0n);
            creg[ni][0] = c0n;
            float c1n = sigmoidf_(fB) * creg[ni][1] + sigmoidf_(iB) * tanhf(gB);
            float h1v = sigmoidf_(oB) * tanhf(c1n);
            creg[ni][1] = c1n;
            if ((tig & 1) == 0) {
                hd[(size_t)mrow0 * NH + jcol[ni]] = h0v;
                hd[(size_t)(mrow0 + 8) * NH + jcol[ni]] = h1v;
                hb[(size_t)mrow0 * NH + jcol[ni]] = __float2bfloat16(h0v);
                hb[(size_t)(mrow0 + 8) * NH + jcol[ni]] = __float2bfloat16(h1v);
            }
        }
        grid_barrier(gridDim.x);
    }
}

// ======================= output softmax =======================
__global__ void k_out(float* __restrict__ out) {
    __shared__ float row[NV];
    __shared__ float red[256];
    int r = blockIdx.x, tid = threadIdx.x;
    const float* L = d_logits + (size_t)r * NV;
    float mx = -1e30f;
    for (int v = tid; v < NV; v += 256) { float x = L[v]; row[v] = x; mx = fmaxf(mx, x); }
    red[tid] = mx; __syncthreads();
    for (int s = 128; s; s >>= 1) { if (tid < s) red[tid] = fmaxf(red[tid], red[tid + s]); __syncthreads(); }
    mx = red[0]; __syncthreads();
    float sum = 0.f;
    for (int v = tid; v < NV; v += 256) sum += __expf(row[v] - mx);
    red[tid] = sum; __syncthreads();
    for (int s = 128; s; s >>= 1) { if (tid < s) red[tid] += red[tid + s]; __syncthreads(); }
    float ls = logf(red[0]);
    float* o1 = out + (size_t)r * NV;
    float* o2 = out + (size_t)TBR * NV + (size_t)r * NV;
    for (int v = tid; v < NV; v += 256) {
        float lp = row[v] - mx - ls;
        o1[v] = lp;
        o2[v] = __expf(lp);
    }
}

// ======================= launch =======================
extern "C" void kernel_launch(void* const* d_in, const int* in_sizes, int n_in,
                              void* d_out, int out_size) {
    const float* features = (const float*)d_in[0];
    const int*   captions = (const int*)d_in[1];
    const float* W_init_h = (const float*)d_in[2];
    const float* W_init_c = (const float*)d_in[3];
    const float* Wv       = (const float*)d_in[4];
    const float* bv       = (const float*)d_in[5];
    // d_in[6]=Wa, d_in[7]=ba unused (softmax shift-invariance)
    const float* embed    = (const float*)d_in[8];
    const float* W_ih     = (const float*)d_in[9];
    const float* W_hh     = (const float*)d_in[10];
    const float* b_ih     = (const float*)d_in[11];
    const float* b_hh     = (const float*)d_in[12];
    const float* Wo       = (const float*)d_in[13];
    const float* bo       = (const float*)d_in[14];
    float* out = (float*)d_out;

    float *p_gctx, *p_gpre, *p_logits;
    __nv_bfloat16 *p_ebf, *p_wobf, *p_wibf, *p_hbf;
    cudaGetSymbolAddress((void**)&p_gctx,   d_gctx);
    cudaGetSymbolAddress((void**)&p_gpre,   d_gpre);
    cudaGetSymbolAddress((void**)&p_logits, d_logits);
    cudaGetSymbolAddress((void**)&p_ebf,    d_emb_bf);
    cudaGetSymbolAddress((void**)&p_wobf,   d_wo_bf);
    cudaGetSymbolAddress((void**)&p_wibf,   d_wih_bf);
    cudaGetSymbolAddress((void**)&p_hbf,    d_hall_bf);

    static int smset = 0;
    if (!smset) {
        cudaFuncSetAttribute(k_recur, cudaFuncAttributeMaxDynamicSharedMemorySize, RS_SMEM);
        smset = 1;
    }

    // setup + conversions
    k_gather<<<TBR, NE>>>(captions, embed);
    k_cvtb<<<(NV * NH / 4 + 255) / 256, 256>>>(Wo, NH, NH, p_wobf, NV * NH / 4);
    k_cvtb<<<(G4 * NE / 4 + 255) / 256, 256>>>(W_ih + VDIM, VDIM + NE, NE, p_wibf, G4 * NE / 4);
    k_vis<<<NB, 256>>>(features, Wv, bv);

    // fused h0 | c0 | g_ctx : one full-chip wave (192 blocks)
    k_init<<<dim3(48, 4), 256>>>(W_init_h, W_init_c, W_ih, b_ih, b_hh);

    // g_pre = emb @ WihE^T + g_ctx[b]  (bf16 mma)
    tbmma<<<dim3(G4 / 128, TBR / 128), 256>>>(
        p_ebf, NE, p_wibf, NE, p_gpre, TBR, G4, NE, nullptr, p_gctx, NB);

    // recurrence: tf32 mma persistent (exact-ish), 1 grid barrier / step
    k_recur<<<NB, 256, RS_SMEM>>>(W_hh);

    // logits = hall @ Wo^T + bo  (bf16 mma)
    tbmma<<<dim3((NV + 127) / 128, TBR / 128), 256>>>(
        p_hbf, NH, p_wobf, NH, p_logits, TBR, NV, NH, bo, nullptr, 0);

    k_out<<<TBR, 256>>>(out);
}

// round 7
// speedup vs baseline: 5.2837x; 1.2739x over previous
#include <cuda_runtime.h>
#include <cuda_bf16.h>
#include <math.h>
#include <stdint.h>

// Problem dims
#define NB   128
#define NT   20
#define VNUM 196
#define VDIM 512
#define NE   256
#define NH   512
#define NV   10000
#define G4   2048
#define TBR  2560   // NT*NB

// ---------------- helpers ----------------
__device__ __forceinline__ float to_tf32(float x) {
    uint32_t y;
    asm("cvt.rna.tf32.f32 %0, %1;" : "=r"(y) : "f"(x));
    return __uint_as_float(y);
}
__device__ __forceinline__ void mma8(float* c, const uint32_t* a, const uint32_t* b) {
    asm volatile("mma.sync.aligned.m16n8k8.row.col.f32.tf32.tf32.f32 "
                 "{%0,%1,%2,%3}, {%4,%5,%6,%7}, {%8,%9}, {%0,%1,%2,%3};"
                 : "+f"(c[0]), "+f"(c[1]), "+f"(c[2]), "+f"(c[3])
                 : "r"(a[0]), "r"(a[1]), "r"(a[2]), "r"(a[3]), "r"(b[0]), "r"(b[1]));
}
__device__ __forceinline__ void mma16(float* c, const uint32_t* a, const uint32_t* b) {
    asm volatile("mma.sync.aligned.m16n8k16.row.col.f32.bf16.bf16.f32 "
                 "{%0,%1,%2,%3}, {%4,%5,%6,%7}, {%8,%9}, {%0,%1,%2,%3};"
                 : "+f"(c[0]), "+f"(c[1]), "+f"(c[2]), "+f"(c[3])
                 : "r"(a[0]), "r"(a[1]), "r"(a[2]), "r"(a[3]), "r"(b[0]), "r"(b[1]));
}
__device__ __forceinline__ uint32_t smem_u32(const void* p) {
    uint32_t a;
    asm("{ .reg .u64 t; cvta.to.shared.u64 t, %1; cvt.u32.u64 %0, t; }" : "=r"(a) : "l"(p));
    return a;
}
__device__ __forceinline__ void ldsm4(uint32_t* r, uint32_t addr) {
    asm volatile("ldmatrix.sync.aligned.m8n8.x4.shared.b16 {%0,%1,%2,%3}, [%4];"
                 : "=r"(r[0]), "=r"(r[1]), "=r"(r[2]), "=r"(r[3]) : "r"(addr));
}
__device__ __forceinline__ void cpa16(uint32_t saddr, const void* gaddr, uint32_t srcsz) {
    asm volatile("cp.async.cg.shared.global [%0], [%1], 16, %2;"
                 :: "r"(saddr), "l"(gaddr), "r"(srcsz));
}
#define CP_COMMIT() asm volatile("cp.async.commit_group;")
#define CP_WAIT0()  asm volatile("cp.async.wait_group 0;")
__device__ __forceinline__ float sigmoidf_(float x) { return 1.f / (1.f + __expf(-x)); }

// ---------------- scratch ----------------
__device__ __nv_bfloat16 d_emb_bf[TBR * NE];
__device__ __nv_bfloat16 d_wo_bf[(size_t)NV * NH];
__device__ __nv_bfloat16 d_wih_bf[G4 * NE];
__device__ __nv_bfloat16 d_hall_bf[(size_t)TBR * NH];
__device__ float d_hall[(size_t)TBR * NH];
__device__ float d_attv[NB * VNUM];
__device__ float d_feat_sum[NB * VDIM];
__device__ float d_ctx[NB * VDIM];
__device__ float d_h0[NB * NH];
__device__ float d_c0[NB * NH];
__device__ float d_gctx[NB * G4];
__device__ float d_gpre[(size_t)TBR * G4];
__device__ float d_logits[(size_t)TBR * NV];
__device__ unsigned d_barCount;
__device__ unsigned d_barGen;

// ---------------- embedding gather -> bf16 ----------------
__global__ void k_gather(const int* __restrict__ cap, const float* __restrict__ et) {
    int r = blockIdx.x;                 // t*NB + b
    int t = r / NB, b = r % NB;
    int id = cap[b * NT + t];
    d_emb_bf[(size_t)r * NE + threadIdx.x] = __float2bfloat16(et[(size_t)id * NE + threadIdx.x]);
}

// ---------------- strided fp32 -> bf16 (4 elems/thread) ----------------
__global__ void k_cvtb(const float* __restrict__ src, int pitch, int cols,
                       __nv_bfloat16* __restrict__ dst, int n4) {
    int i = blockIdx.x * 256 + threadIdx.x;
    if (i >= n4) return;
    int e = i * 4;
    int r = e / cols, c = e % cols;
    float4 v = *(const float4*)(src + (size_t)r * pitch + c);
    __nv_bfloat16* d = dst + e;
    d[0] = __float2bfloat16(v.x);
    d[1] = __float2bfloat16(v.y);
    d[2] = __float2bfloat16(v.z);
    d[3] = __float2bfloat16(v.w);
}

// ---------------- attention logits: one warp per (b, n) ----------------
// grid (25, NB), block 256 (8 warps)
__global__ void __launch_bounds__(256) k_att(const float* __restrict__ feat,
        const float* __restrict__ Wv, const float* __restrict__ bv) {
    int warp = threadIdx.x >> 5, lane = threadIdx.x & 31;
    int b = blockIdx.y;
    int n = blockIdx.x * 8 + warp;
    if (n >= VNUM) return;
    const float* fr = feat + ((size_t)b * VNUM + n) * VDIM;
    float acc = 0.f;
    #pragma unroll
    for (int k = lane; k < VDIM; k += 32) acc += fr[k] * Wv[k];
    #pragma unroll
    for (int o = 16; o; o >>= 1) acc += __shfl_xor_sync(0xffffffffu, acc, o);
    if (lane == 0) d_attv[b * VNUM + n] = acc + bv[0];
}

// ---------------- softmax(attv) -> feat_sum + ctx ----------------
// grid (4, NB), block 256. Each block: 128 v-columns; n-loop split in half per thread pair.
__global__ void __launch_bounds__(256) k_ctx(const float* __restrict__ feat) {
    __shared__ float salpha[VNUM];
    __shared__ float red[256];
    __shared__ float sfs[256];
    __shared__ float sctx[256];
    int b = blockIdx.y, tid = threadIdx.x;
    int v0 = blockIdx.x * 128;
    // softmax over 196 logits (redundant per block; trivial cost)
    float x = (tid < VNUM) ? d_attv[b * VNUM + tid] : -1e30f;
    red[tid] = x; __syncthreads();
    for (int s = 128; s; s >>= 1) { if (tid < s) red[tid] = fmaxf(red[tid], red[tid + s]); __syncthreads(); }
    float mx = red[0]; __syncthreads();
    float e = (tid < VNUM) ? __expf(x - mx) : 0.f;
    red[tid] = e; __syncthreads();
    for (int s = 128; s; s >>= 1) { if (tid < s) red[tid] += red[tid + s]; __syncthreads(); }
    float inv = 1.f / red[0];
    __syncthreads();
    if (tid < VNUM) salpha[tid] = e * inv;
    __syncthreads();

    int v = v0 + (tid & 127);
    int half = tid >> 7;                 // 0 or 1
    int n0 = half * 98, n1 = n0 + 98;    // [0,98) / [98,196)
    if (n1 > VNUM) n1 = VNUM;
    const float* fp = feat + (size_t)b * VNUM * VDIM + v;
    float fs = 0.f, c0 = 0.f, c1 = 0.f, c2 = 0.f, c3 = 0.f;
    int n = n0;
    for (; n + 4 <= n1; n += 4) {
        float x0 = fp[(size_t)n * VDIM];
        float x1 = fp[(size_t)(n + 1) * VDIM];
        float x2 = fp[(size_t)(n + 2) * VDIM];
        float x3 = fp[(size_t)(n + 3) * VDIM];
        fs += (x0 + x1) + (x2 + x3);
        c0 += salpha[n] * x0; c1 += salpha[n + 1] * x1;
        c2 += salpha[n + 2] * x2; c3 += salpha[n + 3] * x3;
    }
    for (; n < n1; n++) { float xx = fp[(size_t)n * VDIM]; fs += xx; c0 += salpha[n] * xx; }
    sfs[tid] = fs;
    sctx[tid] = (c0 + c1) + (c2 + c3);
    __syncthreads();
    if (half == 0) {
        d_feat_sum[b * VDIM + v] = sfs[tid] + sfs[tid + 128];
        d_ctx[b * VDIM + v] = sctx[tid] + sctx[tid + 128];
    }
}

// ---------------- fused init GEMMs: h0 | c0 | g_ctx (N=3072 concat) ----------------
__global__ void __launch_bounds__(256) k_init(
        const float* __restrict__ Wini_h, const float* __restrict__ Wini_c,
        const float* __restrict__ Wih,
        const float* __restrict__ bih, const float* __restrict__ bhh) {
    __shared__ float As[16][32];
    __shared__ float Bs[16][64];
    int ntile = blockIdx.x, mt = blockIdx.y;
    int seg, nloc0;
    const float* A;
    const float* B;
    int ldb;
    if (ntile < 8)       { seg = 0; nloc0 = ntile * 64;        A = d_feat_sum; B = Wini_h; ldb = VDIM; }
    else if (ntile < 16) { seg = 1; nloc0 = (ntile - 8) * 64;  A = d_feat_sum; B = Wini_c; ldb = VDIM; }
    else                 { seg = 2; nloc0 = (ntile - 16) * 64; A = d_ctx;      B = Wih;    ldb = VDIM + NE; }
    int tid = threadIdx.x;
    int tx = tid & 15, ty = tid >> 4;
    int m0 = mt * 32;
    float acc[2][4] = {{0.f, 0.f, 0.f, 0.f}, {0.f, 0.f, 0.f, 0.f}};
    for (int k0 = 0; k0 < VDIM; k0 += 16) {
        {
            int i = tid; int r = i >> 4, kk = i & 15;
            As[kk][r] = A[(size_t)(m0 + r) * VDIM + k0 + kk];
            i = tid + 256; r = i >> 4; kk = i & 15;
            As[kk][r] = A[(size_t)(m0 + r) * VDIM + k0 + kk];
        }
        #pragma unroll
        for (int j = 0; j < 4; j++) {
            int i = tid + j * 256; int r = i >> 4, kk = i & 15;
            Bs[kk][r] = B[(size_t)(nloc0 + r) * ldb + k0 + kk];
        }
        __syncthreads();
        #pragma unroll
        for (int kk = 0; kk < 16; kk++) {
            float a0 = As[kk][ty * 2], a1 = As[kk][ty * 2 + 1];
            float b0 = Bs[kk][tx * 4], b1 = Bs[kk][tx * 4 + 1];
            float b2 = Bs[kk][tx * 4 + 2], b3 = Bs[kk][tx * 4 + 3];
            acc[0][0] += a0 * b0; acc[0][1] += a0 * b1; acc[0][2] += a0 * b2; acc[0][3] += a0 * b3;
            acc[1][0] += a1 * b0; acc[1][1] += a1 * b1; acc[1][2] += a1 * b2; acc[1][3] += a1 * b3;
        }
        __syncthreads();
    }
    float alpha = (seg == 2) ? 1.f : (1.f / VNUM);
    float* Cout = (seg == 0) ? d_h0 : (seg == 1) ? d_c0 : d_gctx;
    int Nout = (seg == 2) ? G4 : NH;
    #pragma unroll
    for (int i = 0; i < 2; i++) {
        int m = m0 + ty * 2 + i;
        #pragma unroll
        for (int j = 0; j < 4; j++) {
            int n = nloc0 + tx * 4 + j;
            float v = alpha * acc[i][j];
            if (seg == 2) v += bih[n] + bhh[n];
            Cout[(size_t)m * Nout + n] = v;
        }
    }
}

// ======================= bf16 mma GEMM: ldmatrix + cp.async =======================
#define BSTR 40

__global__ void __launch_bounds__(256) tbmma(const __nv_bfloat16* __restrict__ A, int lda,
        const __nv_bfloat16* __restrict__ B, int ldb, float* __restrict__ C,
        int M, int N, int K,
        const float* __restrict__ bias, const float* __restrict__ addM, int addRowMod) {
    __shared__ __align__(16) __nv_bfloat16 sA[2][128 * BSTR];
    __shared__ __align__(16) __nv_bfloat16 sB[2][128 * BSTR];
    int tid = threadIdx.x, lane = tid & 31, wid = tid >> 5;
    int wm = wid & 1, wn = wid >> 1;
    int m0 = blockIdx.y * 128, n0 = blockIdx.x * 128;
    int gid = lane >> 2, tig = lane & 3;

    float acc[4][4][4];
    #pragma unroll
    for (int mi = 0; mi < 4; mi++)
        #pragma unroll
        for (int ni = 0; ni < 4; ni++)
            #pragma unroll
            for (int q = 0; q < 4; q++) acc[mi][ni][q] = 0.f;

    int ar0 = tid >> 2, as0 = tid & 3;
    int ar1 = (tid + 256) >> 2, as1 = tid & 3;
    uint32_t sA0 = smem_u32(&sA[0][0]), sB0 = smem_u32(&sB[0][0]);
    uint32_t bufStride = 128 * BSTR * 2;

    int iters = K >> 5;
    int lrow = lane & 15;
    int lcg = (lane >> 4) << 3;

    #define STAGE(ck, bsel) do {                                                          \
        int k0_ = (ck) << 5;                                                              \
        uint32_t da = sA0 + (bsel) * bufStride;                                           \
        uint32_t db = sB0 + (bsel) * bufStride;                                           \
        cpa16(da + (ar0 * BSTR + as0 * 8) * 2, A + (size_t)(m0 + ar0) * lda + k0_ + as0 * 8, 16u); \
        cpa16(da + (ar1 * BSTR + as1 * 8) * 2, A + (size_t)(m0 + ar1) * lda + k0_ + as1 * 8, 16u); \
        { int n = n0 + ar0; uint32_t sz = (n < N) ? 16u : 0u;                             \
          cpa16(db + (ar0 * BSTR + as0 * 8) * 2, B + (size_t)(n < N ? n : 0) * ldb + k0_ + as0 * 8, sz); } \
        { int n = n0 + ar1; uint32_t sz = (n < N) ? 16u : 0u;                             \
          cpa16(db + (ar1 * BSTR + as1 * 8) * 2, B + (size_t)(n < N ? n : 0) * ldb + k0_ + as1 * 8, sz); } \
        CP_COMMIT();                                                                      \
    } while (0)

    STAGE(0, 0);

    for (int it = 0; it < iters; it++) {
        CP_WAIT0();
        __syncthreads();
        if (it + 1 < iters) STAGE(it + 1, (it + 1) & 1);
        uint32_t ab = sA0 + (it & 1) * bufStride;
        uint32_t bb = sB0 + (it & 1) * bufStride;
        #pragma unroll
        for (int ks = 0; ks < 2; ks++) {
            int kofs = ks * 16 + lcg;
            uint32_t a[4][4], b[4][2];
            #pragma unroll
            for (int mi = 0; mi < 4; mi++)
                ldsm4(a[mi], ab + ((wm * 64 + mi * 16 + lrow) * BSTR + kofs) * 2);
            #pragma unroll
            for (int np = 0; np < 2; np++) {
                uint32_t r[4];
                ldsm4(r, bb + ((wn * 32 + np * 16 + lrow) * BSTR + kofs) * 2);
                b[2 * np][0] = r[0]; b[2 * np + 1][0] = r[1];
                b[2 * np][1] = r[2]; b[2 * np + 1][1] = r[3];
            }
            #pragma unroll
            for (int mi = 0; mi < 4; mi++)
                #pragma unroll
                for (int ni = 0; ni < 4; ni++)
                    mma16(acc[mi][ni], a[mi], b[ni]);
        }
        __syncthreads();
    }

    #pragma unroll
    for (int mi = 0; mi < 4; mi++) {
        int row0 = m0 + wm * 64 + mi * 16 + gid;
        #pragma unroll
        for (int ni = 0; ni < 4; ni++) {
            int col = n0 + wn * 32 + ni * 8 + tig * 2;
            #pragma unroll
            for (int half = 0; half < 2; half++) {
                int r = row0 + half * 8;
                float v0 = acc[mi][ni][half * 2 + 0];
                float v1 = acc[mi][ni][half * 2 + 1];
                if (bias) { v0 += bias[col]; v1 += (col + 1 < N) ? bias[col + 1] : 0.f; }
                if (addM) {
                    int ar = r % addRowMod;
                    v0 += addM[(size_t)ar * N + col];
                    if (col + 1 < N) v1 += addM[(size_t)ar * N + col + 1];
                }
                if (col < N)     C[(size_t)r * N + col]     = v0;
                if (col + 1 < N) C[(size_t)r * N + col + 1] = v1;
            }
        }
    }
    #undef STAGE
}

// ======================= persistent recurrence (tf32 mma, 1 barrier/step) ==========
__device__ __forceinline__ void grid_barrier(unsigned nb) {
    __syncthreads();
    if (threadIdx.x == 0) {
        unsigned gen = *((volatile unsigned*)&d_barGen);
        __threadfence();
        if (atomicAdd(&d_barCount, 1u) == nb - 1u) {
            d_barCount = 0u;
            __threadfence();
            atomicAdd(&d_barGen, 1u);
        } else {
            while (*((volatile unsigned*)&d_barGen) == gen) {}
        }
        __threadfence();
    }
    __syncthreads();
}

#define RSTR 516
#define RS_SMEM ((32 * RSTR + 64 * RSTR) * 4)

__global__ void __launch_bounds__(256, 1) k_recur(const float* __restrict__ Whh) {
    extern __shared__ float rsm[];
    float* As = rsm;                 // 32 x 516
    float* Bs = rsm + 32 * RSTR;     // 64 x 516
    int bid = blockIdx.x, tid = threadIdx.x;
    int mt = bid >> 5, nt = bid & 31;
    int lane = tid & 31, wid = tid >> 5;
    int wm = wid & 1, wn = wid >> 1;
    int gid = lane >> 2, tig = lane & 3;

    for (int i = tid; i < 64 * 128; i += 256) {
        int r = i >> 7, q = (i & 127) << 2;
        int w = ((r & 3) << 9) + (nt << 4) + (r >> 2);
        float4 v = *(const float4*)(Whh + (size_t)w * NH + q);
        float* d = Bs + r * RSTR + q;
        d[0] = to_tf32(v.x); d[1] = to_tf32(v.y); d[2] = to_tf32(v.z); d[3] = to_tf32(v.w);
    }

    int mrow0 = mt * 32 + wm * 16 + gid;
    int g0 = (2 * tig) & 3, g1 = (2 * tig + 1) & 3;
    float creg[2][2];
    int jcol[2], gp0_[2], gp1_[2];
    #pragma unroll
    for (int ni = 0; ni < 2; ni++) {
        int jj = wn * 4 + ni * 2 + (tig >> 1);
        int j = nt * 16 + jj;
        jcol[ni] = j;
        gp0_[ni] = g0 * 512 + j;
        gp1_[ni] = g1 * 512 + j;
        creg[ni][0] = d_c0[mrow0 * NH + j];
        creg[ni][1] = d_c0[(mrow0 + 8) * NH + j];
    }

    for (int t = 0; t < NT; t++) {
        const float* hsrc = (t == 0) ? d_h0 : (d_hall + (size_t)(t - 1) * NB * NH);
        __syncthreads();
        for (int i = tid; i < 32 * 128; i += 256) {
            int r = i >> 7, q = (i & 127) << 2;
            float4 v = *(const float4*)(hsrc + (size_t)(mt * 32 + r) * NH + q);
            float* d = As + r * RSTR + q;
            d[0] = to_tf32(v.x); d[1] = to_tf32(v.y); d[2] = to_tf32(v.z); d[3] = to_tf32(v.w);
        }
        __syncthreads();

        float acc[2][4] = {{0.f, 0.f, 0.f, 0.f}, {0.f, 0.f, 0.f, 0.f}};
        const uint32_t* Au = (const uint32_t*)As;
        const uint32_t* Bu = (const uint32_t*)Bs;
        const uint32_t* apb = Au + (wm * 16 + gid) * RSTR + tig;
        #pragma unroll 4
        for (int k = 0; k < 512; k += 8) {
            uint32_t a[4];
            a[0] = apb[k]; a[1] = apb[k + 8 * RSTR]; a[2] = apb[k + 4]; a[3] = apb[k + 8 * RSTR + 4];
            #pragma unroll
            for (int ni = 0; ni < 2; ni++) {
                const uint32_t* bp = Bu + (wn * 16 + ni * 8 + gid) * RSTR + k + tig;
                uint32_t b[2];
                b[0] = bp[0]; b[1] = bp[4];
                mma8(acc[ni], a, b);
            }
        }

        const float* gp = d_gpre + (size_t)t * NB * G4;
        float* hd = d_hall + (size_t)t * NB * NH;
        __nv_bfloat16* hb = d_hall_bf + (size_t)t * NB * NH;
        #pragma unroll
        for (int ni = 0; ni < 2; ni++) {
            float v0 = acc[ni][0] + gp[(size_t)mrow0 * G4 + gp0_[ni]];
            float v1 = acc[ni][1] + gp[(size_t)mrow0 * G4 + gp1_[ni]];
            float v2 = acc[ni][2] + gp[(size_t)(mrow0 + 8) * G4 + gp0_[ni]];
            float v3 = acc[ni][3] + gp[(size_t)(mrow0 + 8) * G4 + gp1_[ni]];
            float w0 = __shfl_xor_sync(0xffffffffu, v0, 1);
            float w1 = __shfl_xor_sync(0xffffffffu, v1, 1);
            float w2 = __shfl_xor_sync(0xffffffffu, v2, 1);
            float w3 = __shfl_xor_sync(0xffffffffu, v3, 1);
            float iA, fA, gA, oA, iB, fB, gB, oB;
            if ((tig & 1) == 0) { iA = v0; fA = v1; gA = w0; oA = w1; iB = v2; fB = v3; gB = w2; oB = w3; }
            else                { iA = w0; fA = w1; gA = v0; oA = v1; iB = w2; fB = w3; gB = v2; oB = v3; }
            float c0n = sigmoidf_(fA) * creg[ni][0] + sigmoidf_(iA) * tanhf(gA);
            float h0v = sigmoidf_(oA) * tanhf(c0n);
            creg[ni][0] = c0n;
            float c1n = sigmoidf_(fB) * creg[ni][1] + sigmoidf_(iB) * tanhf(gB);
            float h1v = sigmoidf_(oB) * tanhf(c1n);
            creg[ni][1] = c1n;
            if ((tig & 1) == 0) {
                hd[(size_t)mrow0 * NH + jcol[ni]] = h0v;
                hd[(size_t)(mrow0 + 8) * NH + jcol[ni]] = h1v;
                hb[(size_t)mrow0 * NH + jcol[ni]] = __float2bfloat16(h0v);
                hb[(size_t)(mrow0 + 8) * NH + jcol[ni]] = __float2bfloat16(h1v);
            }
        }
        grid_barrier(gridDim.x);
    }
}

// ======================= output softmax =======================
__global__ void k_out(float* __restrict__ out) {
    __shared__ float row[NV];
    __shared__ float red[256];
    int r = blockIdx.x, tid = threadIdx.x;
    const float* L = d_logits + (size_t)r * NV;
    float mx = -1e30f;
    for (int v = tid; v < NV; v += 256) { float x = L[v]; row[v] = x; mx = fmaxf(mx, x); }
    red[tid] = mx; __syncthreads();
    for (int s = 128; s; s >>= 1) { if (tid < s) red[tid] = fmaxf(red[tid], red[tid + s]); __syncthreads(); }
    mx = red[0]; __syncthreads();
    float sum = 0.f;
    for (int v = tid; v < NV; v += 256) sum += __expf(row[v] - mx);
    red[tid] = sum; __syncthreads();
    for (int s = 128; s; s >>= 1) { if (tid < s) red[tid] += red[tid + s]; __syncthreads(); }
    float ls = logf(red[0]);
    float* o1 = out + (size_t)r * NV;
    float* o2 = out + (size_t)TBR * NV + (size_t)r * NV;
    for (int v = tid; v < NV; v += 256) {
        float lp = row[v] - mx - ls;
        o1[v] = lp;
        o2[v] = __expf(lp);
    }
}

// ======================= launch =======================
extern "C" void kernel_launch(void* const* d_in, const int* in_sizes, int n_in,
                              void* d_out, int out_size) {
    const float* features = (const float*)d_in[0];
    const int*   captions = (const int*)d_in[1];
    const float* W_init_h = (const float*)d_in[2];
    const float* W_init_c = (const float*)d_in[3];
    const float* Wv       = (const float*)d_in[4];
    const float* bv       = (const float*)d_in[5];
    // d_in[6]=Wa, d_in[7]=ba unused (softmax shift-invariance)
    const float* embed    = (const float*)d_in[8];
    const float* W_ih     = (const float*)d_in[9];
    const float* W_hh     = (const float*)d_in[10];
    const float* b_ih     = (const float*)d_in[11];
    const float* b_hh     = (const float*)d_in[12];
    const float* Wo       = (const float*)d_in[13];
    const float* bo       = (const float*)d_in[14];
    float* out = (float*)d_out;

    float *p_gctx, *p_gpre, *p_logits;
    __nv_bfloat16 *p_ebf, *p_wobf, *p_wibf, *p_hbf;
    cudaGetSymbolAddress((void**)&p_gctx,   d_gctx);
    cudaGetSymbolAddress((void**)&p_gpre,   d_gpre);
    cudaGetSymbolAddress((void**)&p_logits, d_logits);
    cudaGetSymbolAddress((void**)&p_ebf,    d_emb_bf);
    cudaGetSymbolAddress((void**)&p_wobf,   d_wo_bf);
    cudaGetSymbolAddress((void**)&p_wibf,   d_wih_bf);
    cudaGetSymbolAddress((void**)&p_hbf,    d_hall_bf);

    static int smset = 0;
    if (!smset) {
        cudaFuncSetAttribute(k_recur, cudaFuncAttributeMaxDynamicSharedMemorySize, RS_SMEM);
        smset = 1;
    }

    // setup + conversions
    k_gather<<<TBR, NE>>>(captions, embed);
    k_cvtb<<<(NV * NH / 4 + 255) / 256, 256>>>(Wo, NH, NH, p_wobf, NV * NH / 4);
    k_cvtb<<<(G4 * NE / 4 + 255) / 256, 256>>>(W_ih + VDIM, VDIM + NE, NE, p_wibf, G4 * NE / 4);

    // visual stage: wide attention dots, then softmax+ctx+feat_sum
    k_att<<<dim3(25, NB), 256>>>(features, Wv, bv);
    k_ctx<<<dim3(4, NB), 256>>>(features);

    // fused h0 | c0 | g_ctx : one full-chip wave (192 blocks)
    k_init<<<dim3(48, 4), 256>>>(W_init_h, W_init_c, W_ih, b_ih, b_hh);

    // g_pre = emb @ WihE^T + g_ctx[b]  (bf16 mma)
    tbmma<<<dim3(G4 / 128, TBR / 128), 256>>>(
        p_ebf, NE, p_wibf, NE, p_gpre, TBR, G4, NE, nullptr, p_gctx, NB);

    // recurrence: tf32 mma persistent, 1 grid barrier / step
    k_recur<<<NB, 256, RS_SMEM>>>(W_hh);

    // logits = hall @ Wo^T + bo  (bf16 mma)
    tbmma<<<dim3((NV + 127) / 128, TBR / 128), 256>>>(
        p_hbf, NH, p_wobf, NH, p_logits, TBR, NV, NH, bo, nullptr, 0);

    k_out<<<TBR, 256>>>(out);
}

// round 8
// speedup vs baseline: 5.9010x; 1.1168x over previous
#include <cuda_runtime.h>
#include <cuda_bf16.h>
#include <math.h>
#include <stdint.h>

// Problem dims
#define NB   128
#define NT   20
#define VNUM 196
#define VDIM 512
#define NE   256
#define NH   512
#define NV   10000
#define G4   2048
#define TBR  2560   // NT*NB

// ---------------- helpers ----------------
__device__ __forceinline__ float to_tf32(float x) {
    uint32_t y;
    asm("cvt.rna.tf32.f32 %0, %1;" : "=r"(y) : "f"(x));
    return __uint_as_float(y);
}
__device__ __forceinline__ void mma8(float* c, const uint32_t* a, const uint32_t* b) {
    asm volatile("mma.sync.aligned.m16n8k8.row.col.f32.tf32.tf32.f32 "
                 "{%0,%1,%2,%3}, {%4,%5,%6,%7}, {%8,%9}, {%0,%1,%2,%3};"
                 : "+f"(c[0]), "+f"(c[1]), "+f"(c[2]), "+f"(c[3])
                 : "r"(a[0]), "r"(a[1]), "r"(a[2]), "r"(a[3]), "r"(b[0]), "r"(b[1]));
}
__device__ __forceinline__ void mma16(float* c, const uint32_t* a, const uint32_t* b) {
    asm volatile("mma.sync.aligned.m16n8k16.row.col.f32.bf16.bf16.f32 "
                 "{%0,%1,%2,%3}, {%4,%5,%6,%7}, {%8,%9}, {%0,%1,%2,%3};"
                 : "+f"(c[0]), "+f"(c[1]), "+f"(c[2]), "+f"(c[3])
                 : "r"(a[0]), "r"(a[1]), "r"(a[2]), "r"(a[3]), "r"(b[0]), "r"(b[1]));
}
__device__ __forceinline__ uint32_t smem_u32(const void* p) {
    uint32_t a;
    asm("{ .reg .u64 t; cvta.to.shared.u64 t, %1; cvt.u32.u64 %0, t; }" : "=r"(a) : "l"(p));
    return a;
}
__device__ __forceinline__ void ldsm4(uint32_t* r, uint32_t addr) {
    asm volatile("ldmatrix.sync.aligned.m8n8.x4.shared.b16 {%0,%1,%2,%3}, [%4];"
                 : "=r"(r[0]), "=r"(r[1]), "=r"(r[2]), "=r"(r[3]) : "r"(addr));
}
__device__ __forceinline__ void cpa16(uint32_t saddr, const void* gaddr, uint32_t srcsz) {
    asm volatile("cp.async.cg.shared.global [%0], [%1], 16, %2;"
                 :: "r"(saddr), "l"(gaddr), "r"(srcsz));
}
#define CP_COMMIT() asm volatile("cp.async.commit_group;")
#define CP_WAIT0()  asm volatile("cp.async.wait_group 0;")
__device__ __forceinline__ float sigmoidf_(float x) { return 1.f / (1.f + __expf(-x)); }

// ---------------- scratch ----------------
__device__ __nv_bfloat16 d_emb_bf[TBR * NE];
__device__ __nv_bfloat16 d_wo_bf[(size_t)NV * NH];
__device__ __nv_bfloat16 d_wih_bf[G4 * NE];
__device__ __nv_bfloat16 d_hall_bf[(size_t)TBR * NH];
__device__ float d_hall[(size_t)TBR * NH];
__device__ float d_attv[NB * VNUM];
__device__ float d_feat_sum[NB * VDIM];
__device__ float d_ctx[NB * VDIM];
__device__ float d_h0[NB * NH];
__device__ float d_c0[NB * NH];
__device__ float d_gctx[NB * G4];
__device__ float d_gpre[(size_t)TBR * G4];
__device__ float d_logits[(size_t)TBR * NV];
__device__ unsigned d_barCount;
__device__ unsigned d_barGen;

// ---------------- embedding gather -> bf16 ----------------
__global__ void k_gather(const int* __restrict__ cap, const float* __restrict__ et) {
    int r = blockIdx.x;                 // t*NB + b
    int t = r / NB, b = r % NB;
    int id = cap[b * NT + t];
    d_emb_bf[(size_t)r * NE + threadIdx.x] = __float2bfloat16(et[(size_t)id * NE + threadIdx.x]);
}

// ---------------- strided fp32 -> bf16 (4 elems/thread) ----------------
__global__ void k_cvtb(const float* __restrict__ src, int pitch, int cols,
                       __nv_bfloat16* __restrict__ dst, int n4) {
    int i = blockIdx.x * 256 + threadIdx.x;
    if (i >= n4) return;
    int e = i * 4;
    int r = e / cols, c = e % cols;
    float4 v = *(const float4*)(src + (size_t)r * pitch + c);
    __nv_bfloat16* d = dst + e;
    d[0] = __float2bfloat16(v.x);
    d[1] = __float2bfloat16(v.y);
    d[2] = __float2bfloat16(v.z);
    d[3] = __float2bfloat16(v.w);
}

// ---------------- attention logits: one warp per (b, n) ----------------
__global__ void __launch_bounds__(256) k_att(const float* __restrict__ feat,
        const float* __restrict__ Wv, const float* __restrict__ bv) {
    int warp = threadIdx.x >> 5, lane = threadIdx.x & 31;
    int b = blockIdx.y;
    int n = blockIdx.x * 8 + warp;
    if (n >= VNUM) return;
    const float* fr = feat + ((size_t)b * VNUM + n) * VDIM;
    float acc = 0.f;
    #pragma unroll
    for (int k = lane; k < VDIM; k += 32) acc += fr[k] * Wv[k];
    #pragma unroll
    for (int o = 16; o; o >>= 1) acc += __shfl_xor_sync(0xffffffffu, acc, o);
    if (lane == 0) d_attv[b * VNUM + n] = acc + bv[0];
}

// ---------------- softmax(attv) -> feat_sum + ctx ----------------
__global__ void __launch_bounds__(256) k_ctx(const float* __restrict__ feat) {
    __shared__ float salpha[VNUM];
    __shared__ float red[256];
    __shared__ float sfs[256];
    __shared__ float sctx[256];
    int b = blockIdx.y, tid = threadIdx.x;
    int v0 = blockIdx.x * 128;
    float x = (tid < VNUM) ? d_attv[b * VNUM + tid] : -1e30f;
    red[tid] = x; __syncthreads();
    for (int s = 128; s; s >>= 1) { if (tid < s) red[tid] = fmaxf(red[tid], red[tid + s]); __syncthreads(); }
    float mx = red[0]; __syncthreads();
    float e = (tid < VNUM) ? __expf(x - mx) : 0.f;
    red[tid] = e; __syncthreads();
    for (int s = 128; s; s >>= 1) { if (tid < s) red[tid] += red[tid + s]; __syncthreads(); }
    float inv = 1.f / red[0];
    __syncthreads();
    if (tid < VNUM) salpha[tid] = e * inv;
    __syncthreads();

    int v = v0 + (tid & 127);
    int half = tid >> 7;
    int n0 = half * 98, n1 = n0 + 98;
    if (n1 > VNUM) n1 = VNUM;
    const float* fp = feat + (size_t)b * VNUM * VDIM + v;
    float fs = 0.f, c0 = 0.f, c1 = 0.f, c2 = 0.f, c3 = 0.f;
    int n = n0;
    for (; n + 4 <= n1; n += 4) {
        float x0 = fp[(size_t)n * VDIM];
        float x1 = fp[(size_t)(n + 1) * VDIM];
        float x2 = fp[(size_t)(n + 2) * VDIM];
        float x3 = fp[(size_t)(n + 3) * VDIM];
        fs += (x0 + x1) + (x2 + x3);
        c0 += salpha[n] * x0; c1 += salpha[n + 1] * x1;
        c2 += salpha[n + 2] * x2; c3 += salpha[n + 3] * x3;
    }
    for (; n < n1; n++) { float xx = fp[(size_t)n * VDIM]; fs += xx; c0 += salpha[n] * xx; }
    sfs[tid] = fs;
    sctx[tid] = (c0 + c1) + (c2 + c3);
    __syncthreads();
    if (half == 0) {
        d_feat_sum[b * VDIM + v] = sfs[tid] + sfs[tid + 128];
        d_ctx[b * VDIM + v] = sctx[tid] + sctx[tid + 128];
    }
}

// ---------------- fused init GEMMs: h0 | c0 | g_ctx (N=3072 concat) ----------------
__global__ void __launch_bounds__(256) k_init(
        const float* __restrict__ Wini_h, const float* __restrict__ Wini_c,
        const float* __restrict__ Wih,
        const float* __restrict__ bih, const float* __restrict__ bhh) {
    __shared__ float As[16][32];
    __shared__ float Bs[16][64];
    int ntile = blockIdx.x, mt = blockIdx.y;
    int seg, nloc0;
    const float* A;
    const float* B;
    int ldb;
    if (ntile < 8)       { seg = 0; nloc0 = ntile * 64;        A = d_feat_sum; B = Wini_h; ldb = VDIM; }
    else if (ntile < 16) { seg = 1; nloc0 = (ntile - 8) * 64;  A = d_feat_sum; B = Wini_c; ldb = VDIM; }
    else                 { seg = 2; nloc0 = (ntile - 16) * 64; A = d_ctx;      B = Wih;    ldb = VDIM + NE; }
    int tid = threadIdx.x;
    int tx = tid & 15, ty = tid >> 4;
    int m0 = mt * 32;
    float acc[2][4] = {{0.f, 0.f, 0.f, 0.f}, {0.f, 0.f, 0.f, 0.f}};
    for (int k0 = 0; k0 < VDIM; k0 += 16) {
        {
            int i = tid; int r = i >> 4, kk = i & 15;
            As[kk][r] = A[(size_t)(m0 + r) * VDIM + k0 + kk];
            i = tid + 256; r = i >> 4; kk = i & 15;
            As[kk][r] = A[(size_t)(m0 + r) * VDIM + k0 + kk];
        }
        #pragma unroll
        for (int j = 0; j < 4; j++) {
            int i = tid + j * 256; int r = i >> 4, kk = i & 15;
            Bs[kk][r] = B[(size_t)(nloc0 + r) * ldb + k0 + kk];
        }
        __syncthreads();
        #pragma unroll
        for (int kk = 0; kk < 16; kk++) {
            float a0 = As[kk][ty * 2], a1 = As[kk][ty * 2 + 1];
            float b0 = Bs[kk][tx * 4], b1 = Bs[kk][tx * 4 + 1];
            float b2 = Bs[kk][tx * 4 + 2], b3 = Bs[kk][tx * 4 + 3];
            acc[0][0] += a0 * b0; acc[0][1] += a0 * b1; acc[0][2] += a0 * b2; acc[0][3] += a0 * b3;
            acc[1][0] += a1 * b0; acc[1][1] += a1 * b1; acc[1][2] += a1 * b2; acc[1][3] += a1 * b3;
        }
        __syncthreads();
    }
    float alpha = (seg == 2) ? 1.f : (1.f / VNUM);
    float* Cout = (seg == 0) ? d_h0 : (seg == 1) ? d_c0 : d_gctx;
    int Nout = (seg == 2) ? G4 : NH;
    #pragma unroll
    for (int i = 0; i < 2; i++) {
        int m = m0 + ty * 2 + i;
        #pragma unroll
        for (int j = 0; j < 4; j++) {
            int n = nloc0 + tx * 4 + j;
            float v = alpha * acc[i][j];
            if (seg == 2) v += bih[n] + bhh[n];
            Cout[(size_t)m * Nout + n] = v;
        }
    }
}

// ======================= bf16 mma GEMM: ldmatrix + cp.async, 2 CTAs/SM ==============
#define BSTR 40

__global__ void __launch_bounds__(256, 2) tbmma(const __nv_bfloat16* __restrict__ A, int lda,
        const __nv_bfloat16* __restrict__ B, int ldb, float* __restrict__ C,
        int M, int N, int K,
        const float* __restrict__ bias, const float* __restrict__ addM, int addRowMod) {
    __shared__ __align__(16) __nv_bfloat16 sA[2][128 * BSTR];
    __shared__ __align__(16) __nv_bfloat16 sB[2][128 * BSTR];
    int tid = threadIdx.x, lane = tid & 31, wid = tid >> 5;
    int wm = wid & 1, wn = wid >> 1;
    int m0 = blockIdx.y * 128, n0 = blockIdx.x * 128;
    int gid = lane >> 2, tig = lane & 3;

    float acc[4][4][4];
    #pragma unroll
    for (int mi = 0; mi < 4; mi++)
        #pragma unroll
        for (int ni = 0; ni < 4; ni++)
            #pragma unroll
            for (int q = 0; q < 4; q++) acc[mi][ni][q] = 0.f;

    int ar0 = tid >> 2, as0 = tid & 3;
    int ar1 = (tid + 256) >> 2, as1 = tid & 3;
    uint32_t sA0 = smem_u32(&sA[0][0]), sB0 = smem_u32(&sB[0][0]);
    uint32_t bufStride = 128 * BSTR * 2;

    int iters = K >> 5;
    int lrow = lane & 15;
    int lcg = (lane >> 4) << 3;

    #define STAGE(ck, bsel) do {                                                          \
        int k0_ = (ck) << 5;                                                              \
        uint32_t da = sA0 + (bsel) * bufStride;                                           \
        uint32_t db = sB0 + (bsel) * bufStride;                                           \
        cpa16(da + (ar0 * BSTR + as0 * 8) * 2, A + (size_t)(m0 + ar0) * lda + k0_ + as0 * 8, 16u); \
        cpa16(da + (ar1 * BSTR + as1 * 8) * 2, A + (size_t)(m0 + ar1) * lda + k0_ + as1 * 8, 16u); \
        { int n = n0 + ar0; uint32_t sz = (n < N) ? 16u : 0u;                             \
          cpa16(db + (ar0 * BSTR + as0 * 8) * 2, B + (size_t)(n < N ? n : 0) * ldb + k0_ + as0 * 8, sz); } \
        { int n = n0 + ar1; uint32_t sz = (n < N) ? 16u : 0u;                             \
          cpa16(db + (ar1 * BSTR + as1 * 8) * 2, B + (size_t)(n < N ? n : 0) * ldb + k0_ + as1 * 8, sz); } \
        CP_COMMIT();                                                                      \
    } while (0)

    STAGE(0, 0);

    for (int it = 0; it < iters; it++) {
        CP_WAIT0();
        __syncthreads();
        if (it + 1 < iters) STAGE(it + 1, (it + 1) & 1);
        uint32_t ab = sA0 + (it & 1) * bufStride;
        uint32_t bb = sB0 + (it & 1) * bufStride;
        #pragma unroll
        for (int ks = 0; ks < 2; ks++) {
            int kofs = ks * 16 + lcg;
            uint32_t a[4][4], b[4][2];
            #pragma unroll
            for (int mi = 0; mi < 4; mi++)
                ldsm4(a[mi], ab + ((wm * 64 + mi * 16 + lrow) * BSTR + kofs) * 2);
            #pragma unroll
            for (int np = 0; np < 2; np++) {
                uint32_t r[4];
                ldsm4(r, bb + ((wn * 32 + np * 16 + lrow) * BSTR + kofs) * 2);
                b[2 * np][0] = r[0]; b[2 * np + 1][0] = r[1];
                b[2 * np][1] = r[2]; b[2 * np + 1][1] = r[3];
            }
            #pragma unroll
            for (int mi = 0; mi < 4; mi++)
                #pragma unroll
                for (int ni = 0; ni < 4; ni++)
                    mma16(acc[mi][ni], a[mi], b[ni]);
        }
        __syncthreads();
    }

    #pragma unroll
    for (int mi = 0; mi < 4; mi++) {
        int row0 = m0 + wm * 64 + mi * 16 + gid;
        #pragma unroll
        for (int ni = 0; ni < 4; ni++) {
            int col = n0 + wn * 32 + ni * 8 + tig * 2;
            #pragma unroll
            for (int half = 0; half < 2; half++) {
                int r = row0 + half * 8;
                float v0 = acc[mi][ni][half * 2 + 0];
                float v1 = acc[mi][ni][half * 2 + 1];
                if (bias) { v0 += bias[col]; v1 += (col + 1 < N) ? bias[col + 1] : 0.f; }
                if (addM) {
                    int ar = r % addRowMod;
                    v0 += addM[(size_t)ar * N + col];
                    if (col + 1 < N) v1 += addM[(size_t)ar * N + col + 1];
                }
                if (col < N)     C[(size_t)r * N + col]     = v0;
                if (col + 1 < N) C[(size_t)r * N + col + 1] = v1;
            }
        }
    }
    #undef STAGE
}

// ======================= persistent recurrence (tf32 mma, 1 barrier/step) ==========
__device__ __forceinline__ void grid_barrier(unsigned nb) {
    __syncthreads();
    if (threadIdx.x == 0) {
        unsigned gen = *((volatile unsigned*)&d_barGen);
        __threadfence();
        if (atomicAdd(&d_barCount, 1u) == nb - 1u) {
            d_barCount = 0u;
            __threadfence();
            atomicAdd(&d_barGen, 1u);
        } else {
            while (*((volatile unsigned*)&d_barGen) == gen) {}
        }
        __threadfence();
    }
    __syncthreads();
}

#define RSTR 516
#define RS_SMEM ((32 * RSTR + 64 * RSTR) * 4)

__global__ void __launch_bounds__(256, 1) k_recur(const float* __restrict__ Whh) {
    extern __shared__ float rsm[];
    float* As = rsm;                 // 32 x 516
    float* Bs = rsm + 32 * RSTR;     // 64 x 516
    int bid = blockIdx.x, tid = threadIdx.x;
    int mt = bid >> 5, nt = bid & 31;
    int lane = tid & 31, wid = tid >> 5;
    int wm = wid & 1, wn = wid >> 1;
    int gid = lane >> 2, tig = lane & 3;

    for (int i = tid; i < 64 * 128; i += 256) {
        int r = i >> 7, q = (i & 127) << 2;
        int w = ((r & 3) << 9) + (nt << 4) + (r >> 2);
        float4 v = *(const float4*)(Whh + (size_t)w * NH + q);
        float* d = Bs + r * RSTR + q;
        d[0] = to_tf32(v.x); d[1] = to_tf32(v.y); d[2] = to_tf32(v.z); d[3] = to_tf32(v.w);
    }

    int mrow0 = mt * 32 + wm * 16 + gid;
    int g0 = (2 * tig) & 3, g1 = (2 * tig + 1) & 3;
    float creg[2][2];
    int jcol[2], gp0_[2], gp1_[2];
    #pragma unroll
    for (int ni = 0; ni < 2; ni++) {
        int jj = wn * 4 + ni * 2 + (tig >> 1);
        int j = nt * 16 + jj;
        jcol[ni] = j;
        gp0_[ni] = g0 * 512 + j;
        gp1_[ni] = g1 * 512 + j;
        creg[ni][0] = d_c0[mrow0 * NH + j];
        creg[ni][1] = d_c0[(mrow0 + 8) * NH + j];
    }

    for (int t = 0; t < NT; t++) {
        const float* hsrc = (t == 0) ? d_h0 : (d_hall + (size_t)(t - 1) * NB * NH);
        __syncthreads();
        for (int i = tid; i < 32 * 128; i += 256) {
            int r = i >> 7, q = (i & 127) << 2;
            float4 v = *(const float4*)(hsrc + (size_t)(mt * 32 + r) * NH + q);
            float* d = As + r * RSTR + q;
            d[0] = to_tf32(v.x); d[1] = to_tf32(v.y); d[2] = to_tf32(v.z); d[3] = to_tf32(v.w);
        }
        __syncthreads();

        float acc[2][4] = {{0.f, 0.f, 0.f, 0.f}, {0.f, 0.f, 0.f, 0.f}};
        const uint32_t* Au = (const uint32_t*)As;
        const uint32_t* Bu = (const uint32_t*)Bs;
        const uint32_t* apb = Au + (wm * 16 + gid) * RSTR + tig;
        #pragma unroll 4
        for (int k = 0; k < 512; k += 8) {
            uint32_t a[4];
            a[0] = apb[k]; a[1] = apb[k + 8 * RSTR]; a[2] = apb[k + 4]; a[3] = apb[k + 8 * RSTR + 4];
            #pragma unroll
            for (int ni = 0; ni < 2; ni++) {
                const uint32_t* bp = Bu + (wn * 16 + ni * 8 + gid) * RSTR + k + tig;
                uint32_t b[2];
                b[0] = bp[0]; b[1] = bp[4];
                mma8(acc[ni], a, b);
            }
        }

        const float* gp = d_gpre + (size_t)t * NB * G4;
        float* hd = d_hall + (size_t)t * NB * NH;
        __nv_bfloat16* hb = d_hall_bf + (size_t)t * NB * NH;
        #pragma unroll
        for (int ni = 0; ni < 2; ni++) {
            float v0 = acc[ni][0] + gp[(size_t)mrow0 * G4 + gp0_[ni]];
            float v1 = acc[ni][1] + gp[(size_t)mrow0 * G4 + gp1_[ni]];
            float v2 = acc[ni][2] + gp[(size_t)(mrow0 + 8) * G4 + gp0_[ni]];
            float v3 = acc[ni][3] + gp[(size_t)(mrow0 + 8) * G4 + gp1_[ni]];
            float w0 = __shfl_xor_sync(0xffffffffu, v0, 1);
            float w1 = __shfl_xor_sync(0xffffffffu, v1, 1);
            float w2 = __shfl_xor_sync(0xffffffffu, v2, 1);
            float w3 = __shfl_xor_sync(0xffffffffu, v3, 1);
            float iA, fA, gA, oA, iB, fB, gB, oB;
            if ((tig & 1) == 0) { iA = v0; fA = v1; gA = w0; oA = w1; iB = v2; fB = v3; gB = w2; oB = w3; }
            else                { iA = w0; fA = w1; gA = v0; oA = v1; iB = w2; fB = w3; gB = v2; oB = v3; }
            float c0n = sigmoidf_(fA) * creg[ni][0] + sigmoidf_(iA) * tanhf(gA);
            float h0v = sigmoidf_(oA) * tanhf(c0n);
            creg[ni][0] = c0n;
            float c1n = sigmoidf_(fB) * creg[ni][1] + sigmoidf_(iB) * tanhf(gB);
            float h1v = sigmoidf_(oB) * tanhf(c1n);
            creg[ni][1] = c1n;
            if ((tig & 1) == 0) {
                hd[(size_t)mrow0 * NH + jcol[ni]] = h0v;
                hd[(size_t)(mrow0 + 8) * NH + jcol[ni]] = h1v;
                hb[(size_t)mrow0 * NH + jcol[ni]] = __float2bfloat16(h0v);
                hb[(size_t)(mrow0 + 8) * NH + jcol[ni]] = __float2bfloat16(h1v);
            }
        }
        grid_barrier(gridDim.x);
    }
}

// ======================= output softmax (vectorized, 512 threads) =======================
#define NV4 2500   // NV / 4

__global__ void __launch_bounds__(512) k_out(float* __restrict__ out) {
    __shared__ __align__(16) float row[NV];
    __shared__ float red[512];
    int r = blockIdx.x, tid = threadIdx.x;
    const float4* L = (const float4*)(d_logits + (size_t)r * NV);
    float mx = -1e30f;
    for (int v = tid; v < NV4; v += 512) {
        float4 x = L[v];
        *(float4*)(row + v * 4) = x;
        mx = fmaxf(fmaxf(mx, fmaxf(x.x, x.y)), fmaxf(x.z, x.w));
    }
    red[tid] = mx; __syncthreads();
    for (int s = 256; s; s >>= 1) { if (tid < s) red[tid] = fmaxf(red[tid], red[tid + s]); __syncthreads(); }
    mx = red[0]; __syncthreads();
    float sum = 0.f;
    for (int v = tid; v < NV4; v += 512) {
        float4 x = *(const float4*)(row + v * 4);
        sum += (__expf(x.x - mx) + __expf(x.y - mx)) + (__expf(x.z - mx) + __expf(x.w - mx));
    }
    red[tid] = sum; __syncthreads();
    for (int s = 256; s; s >>= 1) { if (tid < s) red[tid] += red[tid + s]; __syncthreads(); }
    float sh = mx + logf(red[0]);
    float4* o1 = (float4*)(out + (size_t)r * NV);
    float4* o2 = (float4*)(out + (size_t)TBR * NV + (size_t)r * NV);
    for (int v = tid; v < NV4; v += 512) {
        float4 x = *(const float4*)(row + v * 4);
        float4 lp, p;
        lp.x = x.x - sh; lp.y = x.y - sh; lp.z = x.z - sh; lp.w = x.w - sh;
        p.x = __expf(lp.x); p.y = __expf(lp.y); p.z = __expf(lp.z); p.w = __expf(lp.w);
        o1[v] = lp;
        o2[v] = p;
    }
}

// ======================= launch =======================
extern "C" void kernel_launch(void* const* d_in, const int* in_sizes, int n_in,
                              void* d_out, int out_size) {
    const float* features = (const float*)d_in[0];
    const int*   captions = (const int*)d_in[1];
    const float* W_init_h = (const float*)d_in[2];
    const float* W_init_c = (const float*)d_in[3];
    const float* Wv       = (const float*)d_in[4];
    const float* bv       = (const float*)d_in[5];
    // d_in[6]=Wa, d_in[7]=ba unused (softmax shift-invariance)
    const float* embed    = (const float*)d_in[8];
    const float* W_ih     = (const float*)d_in[9];
    const float* W_hh     = (const float*)d_in[10];
    const float* b_ih     = (const float*)d_in[11];
    const float* b_hh     = (const float*)d_in[12];
    const float* Wo       = (const float*)d_in[13];
    const float* bo       = (const float*)d_in[14];
    float* out = (float*)d_out;

    float *p_gctx, *p_gpre, *p_logits;
    __nv_bfloat16 *p_ebf, *p_wobf, *p_wibf, *p_hbf;
    cudaGetSymbolAddress((void**)&p_gctx,   d_gctx);
    cudaGetSymbolAddress((void**)&p_gpre,   d_gpre);
    cudaGetSymbolAddress((void**)&p_logits, d_logits);
    cudaGetSymbolAddress((void**)&p_ebf,    d_emb_bf);
    cudaGetSymbolAddress((void**)&p_wobf,   d_wo_bf);
    cudaGetSymbolAddress((void**)&p_wibf,   d_wih_bf);
    cudaGetSymbolAddress((void**)&p_hbf,    d_hall_bf);

    static int smset = 0;
    if (!smset) {
        cudaFuncSetAttribute(k_recur, cudaFuncAttributeMaxDynamicSharedMemorySize, RS_SMEM);
        smset = 1;
    }

    // setup + conversions
    k_gather<<<TBR, NE>>>(captions, embed);
    k_cvtb<<<(NV * NH / 4 + 255) / 256, 256>>>(Wo, NH, NH, p_wobf, NV * NH / 4);
    k_cvtb<<<(G4 * NE / 4 + 255) / 256, 256>>>(W_ih + VDIM, VDIM + NE, NE, p_wibf, G4 * NE / 4);

    // visual stage
    k_att<<<dim3(25, NB), 256>>>(features, Wv, bv);
    k_ctx<<<dim3(4, NB), 256>>>(features);

    // fused h0 | c0 | g_ctx
    k_init<<<dim3(48, 4), 256>>>(W_init_h, W_init_c, W_ih, b_ih, b_hh);

    // g_pre = emb @ WihE^T + g_ctx[b]  (bf16 mma)
    tbmma<<<dim3(G4 / 128, TBR / 128), 256>>>(
        p_ebf, NE, p_wibf, NE, p_gpre, TBR, G4, NE, nullptr, p_gctx, NB);

    // recurrence
    k_recur<<<NB, 256, RS_SMEM>>>(W_hh);

    // logits = hall @ Wo^T + bo  (bf16 mma)
    tbmma<<<dim3((NV + 127) / 128, TBR / 128), 256>>>(
        p_hbf, NH, p_wobf, NH, p_logits, TBR, NV, NH, bo, nullptr, 0);

    k_out<<<TBR, 512>>>(out);
}

// round 10
// speedup vs baseline: 6.4157x; 1.0872x over previous
#include <cuda_runtime.h>
#include <cuda_bf16.h>
#include <math.h>
#include <stdint.h>

// Problem dims
#define NB   128
#define NT   20
#define VNUM 196
#define VDIM 512
#define NE   256
#define NH   512
#define NV   10000
#define G4   2048
#define TBR  2560   // NT*NB

// ---------------- helpers ----------------
__device__ __forceinline__ float to_tf32(float x) {
    uint32_t y;
    asm("cvt.rna.tf32.f32 %0, %1;" : "=r"(y) : "f"(x));
    return __uint_as_float(y);
}
__device__ __forceinline__ void mma8(float* c, const uint32_t* a, const uint32_t* b) {
    asm volatile("mma.sync.aligned.m16n8k8.row.col.f32.tf32.tf32.f32 "
                 "{%0,%1,%2,%3}, {%4,%5,%6,%7}, {%8,%9}, {%0,%1,%2,%3};"
                 : "+f"(c[0]), "+f"(c[1]), "+f"(c[2]), "+f"(c[3])
                 : "r"(a[0]), "r"(a[1]), "r"(a[2]), "r"(a[3]), "r"(b[0]), "r"(b[1]));
}
__device__ __forceinline__ void mma16(float* c, const uint32_t* a, const uint32_t* b) {
    asm volatile("mma.sync.aligned.m16n8k16.row.col.f32.bf16.bf16.f32 "
                 "{%0,%1,%2,%3}, {%4,%5,%6,%7}, {%8,%9}, {%0,%1,%2,%3};"
                 : "+f"(c[0]), "+f"(c[1]), "+f"(c[2]), "+f"(c[3])
                 : "r"(a[0]), "r"(a[1]), "r"(a[2]), "r"(a[3]), "r"(b[0]), "r"(b[1]));
}
__device__ __forceinline__ uint32_t smem_u32(const void* p) {
    uint32_t a;
    asm("{ .reg .u64 t; cvta.to.shared.u64 t, %1; cvt.u32.u64 %0, t; }" : "=r"(a) : "l"(p));
    return a;
}
__device__ __forceinline__ void ldsm4(uint32_t* r, uint32_t addr) {
    asm volatile("ldmatrix.sync.aligned.m8n8.x4.shared.b16 {%0,%1,%2,%3}, [%4];"
                 : "=r"(r[0]), "=r"(r[1]), "=r"(r[2]), "=r"(r[3]) : "r"(addr));
}
__device__ __forceinline__ void cpa16(uint32_t saddr, const void* gaddr, uint32_t srcsz) {
    asm volatile("cp.async.cg.shared.global [%0], [%1], 16, %2;"
                 :: "r"(saddr), "l"(gaddr), "r"(srcsz));
}
#define CP_COMMIT() asm volatile("cp.async.commit_group;")
#define CP_WAIT0()  asm volatile("cp.async.wait_group 0;")
__device__ __forceinline__ float sigmoidf_(float x) { return 1.f / (1.f + __expf(-x)); }

// ---------------- scratch ----------------
__device__ __nv_bfloat16 d_emb_bf[TBR * NE];
__device__ __nv_bfloat16 d_wo_bf[(size_t)NV * NH];
__device__ __nv_bfloat16 d_wih_bf[G4 * NE];
__device__ __nv_bfloat16 d_hall_bf[(size_t)TBR * NH];
__device__ __nv_bfloat16 d_logits_bf[(size_t)TBR * (NV + 16)]; // pad; row stride NV (pad tail safety)
__device__ float d_hall[(size_t)TBR * NH];
__device__ float d_attv[NB * VNUM];
__device__ float d_feat_sum[NB * VDIM];
__device__ float d_ctx[NB * VDIM];
__device__ float d_h0[NB * NH];
__device__ float d_c0[NB * NH];
__device__ float d_gctx[NB * G4];
__device__ float d_gpre[(size_t)TBR * G4];
__device__ unsigned d_barCount;
__device__ unsigned d_barGen;

// ---------------- embedding gather -> bf16 ----------------
__global__ void k_gather(const int* __restrict__ cap, const float* __restrict__ et) {
    int r = blockIdx.x;                 // t*NB + b
    int t = r / NB, b = r % NB;
    int id = cap[b * NT + t];
    d_emb_bf[(size_t)r * NE + threadIdx.x] = __float2bfloat16(et[(size_t)id * NE + threadIdx.x]);
}

// ---------------- fp32 -> bf16 (4 elems/thread, packed 8B stores) ----------------
__global__ void k_cvtb(const float* __restrict__ src, int pitch, int cols,
                       __nv_bfloat16* __restrict__ dst, int n4) {
    int i = blockIdx.x * 256 + threadIdx.x;
    if (i >= n4) return;
    int e = i * 4;
    const float* s;
    if (pitch == cols) {
        s = src + e;
    } else {
        int r = e / cols, c = e % cols;
        s = src + (size_t)r * pitch + c;
    }
    float4 v = *(const float4*)s;
    __nv_bfloat162 p0 = __floats2bfloat162_rn(v.x, v.y);
    __nv_bfloat162 p1 = __floats2bfloat162_rn(v.z, v.w);
    uint2 pk;
    pk.x = *(uint32_t*)&p0;
    pk.y = *(uint32_t*)&p1;
    *(uint2*)(dst + e) = pk;
}

// ---------------- attention logits: one warp per (b, n) ----------------
__global__ void __launch_bounds__(256) k_att(const float* __restrict__ feat,
        const float* __restrict__ Wv, const float* __restrict__ bv) {
    int warp = threadIdx.x >> 5, lane = threadIdx.x & 31;
    int b = blockIdx.y;
    int n = blockIdx.x * 8 + warp;
    if (n >= VNUM) return;
    const float* fr = feat + ((size_t)b * VNUM + n) * VDIM;
    float acc = 0.f;
    #pragma unroll
    for (int k = lane; k < VDIM; k += 32) acc += fr[k] * Wv[k];
    #pragma unroll
    for (int o = 16; o; o >>= 1) acc += __shfl_xor_sync(0xffffffffu, acc, o);
    if (lane == 0) d_attv[b * VNUM + n] = acc + bv[0];
}

// ---------------- softmax(attv) -> feat_sum + ctx ----------------
__global__ void __launch_bounds__(256) k_ctx(const float* __restrict__ feat) {
    __shared__ float salpha[VNUM];
    __shared__ float red[256];
    __shared__ float sfs[256];
    __shared__ float sctx[256];
    int b = blockIdx.y, tid = threadIdx.x;
    int v0 = blockIdx.x * 128;
    float x = (tid < VNUM) ? d_attv[b * VNUM + tid] : -1e30f;
    red[tid] = x; __syncthreads();
    for (int s = 128; s; s >>= 1) { if (tid < s) red[tid] = fmaxf(red[tid], red[tid + s]); __syncthreads(); }
    float mx = red[0]; __syncthreads();
    float e = (tid < VNUM) ? __expf(x - mx) : 0.f;
    red[tid] = e; __syncthreads();
    for (int s = 128; s; s >>= 1) { if (tid < s) red[tid] += red[tid + s]; __syncthreads(); }
    float inv = 1.f / red[0];
    __syncthreads();
    if (tid < VNUM) salpha[tid] = e * inv;
    __syncthreads();

    int v = v0 + (tid & 127);
    int half = tid >> 7;
    int n0 = half * 98, n1 = n0 + 98;
    if (n1 > VNUM) n1 = VNUM;
    const float* fp = feat + (size_t)b * VNUM * VDIM + v;
    float fs = 0.f, c0 = 0.f, c1 = 0.f, c2 = 0.f, c3 = 0.f;
    int n = n0;
    for (; n + 4 <= n1; n += 4) {
        float x0 = fp[(size_t)n * VDIM];
        float x1 = fp[(size_t)(n + 1) * VDIM];
        float x2 = fp[(size_t)(n + 2) * VDIM];
        float x3 = fp[(size_t)(n + 3) * VDIM];
        fs += (x0 + x1) + (x2 + x3);
        c0 += salpha[n] * x0; c1 += salpha[n + 1] * x1;
        c2 += salpha[n + 2] * x2; c3 += salpha[n + 3] * x3;
    }
    for (; n < n1; n++) { float xx = fp[(size_t)n * VDIM]; fs += xx; c0 += salpha[n] * xx; }
    sfs[tid] = fs;
    sctx[tid] = (c0 + c1) + (c2 + c3);
    __syncthreads();
    if (half == 0) {
        d_feat_sum[b * VDIM + v] = sfs[tid] + sfs[tid + 128];
        d_ctx[b * VDIM + v] = sctx[tid] + sctx[tid + 128];
    }
}

// ---------------- fused init GEMMs: h0 | c0 | g_ctx (N=3072 concat) ----------------
__global__ void __launch_bounds__(256) k_init(
        const float* __restrict__ Wini_h, const float* __restrict__ Wini_c,
        const float* __restrict__ Wih,
        const float* __restrict__ bih, const float* __restrict__ bhh) {
    __shared__ float As[16][32];
    __shared__ float Bs[16][64];
    int ntile = blockIdx.x, mt = blockIdx.y;
    int seg, nloc0;
    const float* A;
    const float* B;
    int ldb;
    if (ntile < 8)       { seg = 0; nloc0 = ntile * 64;        A = d_feat_sum; B = Wini_h; ldb = VDIM; }
    else if (ntile < 16) { seg = 1; nloc0 = (ntile - 8) * 64;  A = d_feat_sum; B = Wini_c; ldb = VDIM; }
    else                 { seg = 2; nloc0 = (ntile - 16) * 64; A = d_ctx;      B = Wih;    ldb = VDIM + NE; }
    int tid = threadIdx.x;
    int tx = tid & 15, ty = tid >> 4;
    int m0 = mt * 32;
    float acc[2][4] = {{0.f, 0.f, 0.f, 0.f}, {0.f, 0.f, 0.f, 0.f}};
    for (int k0 = 0; k0 < VDIM; k0 += 16) {
        {
            int i = tid; int r = i >> 4, kk = i & 15;
            As[kk][r] = A[(size_t)(m0 + r) * VDIM + k0 + kk];
            i = tid + 256; r = i >> 4; kk = i & 15;
            As[kk][r] = A[(size_t)(m0 + r) * VDIM + k0 + kk];
        }
        #pragma unroll
        for (int j = 0; j < 4; j++) {
            int i = tid + j * 256; int r = i >> 4, kk = i & 15;
            Bs[kk][r] = B[(size_t)(nloc0 + r) * ldb + k0 + kk];
        }
        __syncthreads();
        #pragma unroll
        for (int kk = 0; kk < 16; kk++) {
            float a0 = As[kk][ty * 2], a1 = As[kk][ty * 2 + 1];
            float b0 = Bs[kk][tx * 4], b1 = Bs[kk][tx * 4 + 1];
            float b2 = Bs[kk][tx * 4 + 2], b3 = Bs[kk][tx * 4 + 3];
            acc[0][0] += a0 * b0; acc[0][1] += a0 * b1; acc[0][2] += a0 * b2; acc[0][3] += a0 * b3;
            acc[1][0] += a1 * b0; acc[1][1] += a1 * b1; acc[1][2] += a1 * b2; acc[1][3] += a1 * b3;
        }
        __syncthreads();
    }
    float alpha = (seg == 2) ? 1.f : (1.f / VNUM);
    float* Cout = (seg == 0) ? d_h0 : (seg == 1) ? d_c0 : d_gctx;
    int Nout = (seg == 2) ? G4 : NH;
    #pragma unroll
    for (int i = 0; i < 2; i++) {
        int m = m0 + ty * 2 + i;
        #pragma unroll
        for (int j = 0; j < 4; j++) {
            int n = nloc0 + tx * 4 + j;
            float v = alpha * acc[i][j];
            if (seg == 2) v += bih[n] + bhh[n];
            Cout[(size_t)m * Nout + n] = v;
        }
    }
}

// ======================= bf16 mma GEMM: BK=64, ldmatrix + cp.async, 2 CTAs/SM =========
// C fp32 (if C != null) else Cb bf16. K % 64 == 0, M % 128 == 0.
#define BSTR64 72
#define TB_BUF (128 * BSTR64)          // elems per matrix per buffer
#define TB_SMEM (4 * TB_BUF * 2)       // bytes: 2 bufs x 2 matrices

__global__ void __launch_bounds__(256, 2) tbmma(const __nv_bfloat16* __restrict__ A, int lda,
        const __nv_bfloat16* __restrict__ B, int ldb,
        float* __restrict__ C, __nv_bfloat16* __restrict__ Cb,
        int M, int N, int K,
        const float* __restrict__ bias, const float* __restrict__ addM, int addRowMod) {
    extern __shared__ __align__(16) __nv_bfloat16 smb[];
    __nv_bfloat16* sA = smb;                    // [2][TB_BUF]
    __nv_bfloat16* sB = smb + 2 * TB_BUF;       // [2][TB_BUF]
    int tid = threadIdx.x, lane = tid & 31, wid = tid >> 5;
    int wm = wid & 1, wn = wid >> 1;
    int m0 = blockIdx.y * 128, n0 = blockIdx.x * 128;
    int gid = lane >> 2, tig = lane & 3;

    float acc[4][4][4];
    #pragma unroll
    for (int mi = 0; mi < 4; mi++)
        #pragma unroll
        for (int ni = 0; ni < 4; ni++)
            #pragma unroll
            for (int q = 0; q < 4; q++) acc[mi][ni][q] = 0.f;

    // staging: 4 x 16B tasks per thread per matrix (128 rows x 8 segs)
    int rr[4], ss[4];
    #pragma unroll
    for (int j = 0; j < 4; j++) { int idx = tid + j * 256; rr[j] = idx >> 3; ss[j] = idx & 7; }
    uint32_t sA0 = smem_u32(sA), sB0 = smem_u32(sB);
    uint32_t bufBytes = TB_BUF * 2;

    int iters = K >> 6;
    int lrow = lane & 15;
    int lcg = (lane >> 4) << 3;

    #define STAGE(ck, bsel) do {                                                          \
        int k0_ = (ck) << 6;                                                              \
        uint32_t da = sA0 + (bsel) * bufBytes;                                            \
        uint32_t db = sB0 + (bsel) * bufBytes;                                            \
        _Pragma("unroll")                                                                 \
        for (int j = 0; j < 4; j++)                                                       \
            cpa16(da + (rr[j] * BSTR64 + ss[j] * 8) * 2,                                  \
                  A + (size_t)(m0 + rr[j]) * lda + k0_ + ss[j] * 8, 16u);                 \
        _Pragma("unroll")                                                                 \
        for (int j = 0; j < 4; j++) {                                                     \
            int n = n0 + rr[j];                                                           \
            uint32_t sz = (n < N) ? 16u : 0u;                                             \
            cpa16(db + (rr[j] * BSTR64 + ss[j] * 8) * 2,                                  \
                  B + (size_t)(n < N ? n : 0) * ldb + k0_ + ss[j] * 8, sz);               \
        }                                                                                 \
        CP_COMMIT();                                                                      \
    } while (0)

    STAGE(0, 0);

    for (int it = 0; it < iters; it++) {
        CP_WAIT0();
        __syncthreads();
        if (it + 1 < iters) STAGE(it + 1, (it + 1) & 1);
        uint32_t ab = sA0 + (it & 1) * bufBytes;
        uint32_t bb = sB0 + (it & 1) * bufBytes;
        #pragma unroll
        for (int ks = 0; ks < 4; ks++) {
            int kofs = ks * 16 + lcg;
            uint32_t a[4][4], b[4][2];
            #pragma unroll
            for (int mi = 0; mi < 4; mi++)
                ldsm4(a[mi], ab + ((wm * 64 + mi * 16 + lrow) * BSTR64 + kofs) * 2);
            #pragma unroll
            for (int np = 0; np < 2; np++) {
                uint32_t r[4];
                ldsm4(r, bb + ((wn * 32 + np * 16 + lrow) * BSTR64 + kofs) * 2);
                b[2 * np][0] = r[0]; b[2 * np + 1][0] = r[1];
                b[2 * np][1] = r[2]; b[2 * np + 1][1] = r[3];
            }
            #pragma unroll
            for (int mi = 0; mi < 4; mi++)
                #pragma unroll
                for (int ni = 0; ni < 4; ni++)
                    mma16(acc[mi][ni], a[mi], b[ni]);
        }
        __syncthreads();
    }

    #pragma unroll
    for (int mi = 0; mi < 4; mi++) {
        int row0 = m0 + wm * 64 + mi * 16 + gid;
        #pragma unroll
        for (int ni = 0; ni < 4; ni++) {
            int col = n0 + wn * 32 + ni * 8 + tig * 2;
            #pragma unroll
            for (int half = 0; half < 2; half++) {
                int r = row0 + half * 8;
                float v0 = acc[mi][ni][half * 2 + 0];
                float v1 = acc[mi][ni][half * 2 + 1];
                if (bias) { v0 += bias[col]; v1 += (col + 1 < N) ? bias[col + 1] : 0.f; }
                if (addM) {
                    int ar = r % addRowMod;
                    v0 += addM[(size_t)ar * N + col];
                    if (col + 1 < N) v1 += addM[(size_t)ar * N + col + 1];
                }
                if (C) {
                    if (col < N)     C[(size_t)r * N + col]     = v0;
                    if (col + 1 < N) C[(size_t)r * N + col + 1] = v1;
                } else {
                    if (col + 1 < N) {
                        __nv_bfloat162 p = __floats2bfloat162_rn(v0, v1);
                        *(uint32_t*)(Cb + (size_t)r * NV + col) = *(uint32_t*)&p;
                    } else if (col < N) {
                        Cb[(size_t)r * NV + col] = __float2bfloat16(v0);
                    }
                }
            }
        }
    }
    #undef STAGE
}

// ======================= persistent recurrence (tf32 mma, 1 barrier/step) ==========
__device__ __forceinline__ void grid_barrier(unsigned nb) {
    __syncthreads();
    if (threadIdx.x == 0) {
        unsigned gen = *((volatile unsigned*)&d_barGen);
        __threadfence();
        if (atomicAdd(&d_barCount, 1u) == nb - 1u) {
            d_barCount = 0u;
            __threadfence();
            atomicAdd(&d_barGen, 1u);
        } else {
            while (*((volatile unsigned*)&d_barGen) == gen) {}
        }
        __threadfence();
    }
    __syncthreads();
}

#define RSTR 516
#define RS_SMEM ((32 * RSTR + 64 * RSTR) * 4)

__global__ void __launch_bounds__(256, 1) k_recur(const float* __restrict__ Whh) {
    extern __shared__ float rsm[];
    float* As = rsm;                 // 32 x 516
    float* Bs = rsm + 32 * RSTR;     // 64 x 516
    int bid = blockIdx.x, tid = threadIdx.x;
    int mt = bid >> 5, nt = bid & 31;
    int lane = tid & 31, wid = tid >> 5;
    int wm = wid & 1, wn = wid >> 1;
    int gid = lane >> 2, tig = lane & 3;

    for (int i = tid; i < 64 * 128; i += 256) {
        int r = i >> 7, q = (i & 127) << 2;
        int w = ((r & 3) << 9) + (nt << 4) + (r >> 2);
        float4 v = *(const float4*)(Whh + (size_t)w * NH + q);
        float* d = Bs + r * RSTR + q;
        d[0] = to_tf32(v.x); d[1] = to_tf32(v.y); d[2] = to_tf32(v.z); d[3] = to_tf32(v.w);
    }

    int mrow0 = mt * 32 + wm * 16 + gid;
    int g0 = (2 * tig) & 3, g1 = (2 * tig + 1) & 3;
    float creg[2][2];
    int jcol[2], gp0_[2], gp1_[2];
    #pragma unroll
    for (int ni = 0; ni < 2; ni++) {
        int jj = wn * 4 + ni * 2 + (tig >> 1);
        int j = nt * 16 + jj;
        jcol[ni] = j;
        gp0_[ni] = g0 * 512 + j;
        gp1_[ni] = g1 * 512 + j;
        creg[ni][0] = d_c0[mrow0 * NH + j];
        creg[ni][1] = d_c0[(mrow0 + 8) * NH + j];
    }

    for (int t = 0; t < NT; t++) {
        const float* hsrc = (t == 0) ? d_h0 : (d_hall + (size_t)(t - 1) * NB * NH);
        __syncthreads();
        for (int i = tid; i < 32 * 128; i += 256) {
            int r = i >> 7, q = (i & 127) << 2;
            float4 v = *(const float4*)(hsrc + (size_t)(mt * 32 + r) * NH + q);
            float* d = As + r * RSTR + q;
            d[0] = to_tf32(v.x); d[1] = to_tf32(v.y); d[2] = to_tf32(v.z); d[3] = to_tf32(v.w);
        }
        __syncthreads();

        float acc[2][4] = {{0.f, 0.f, 0.f, 0.f}, {0.f, 0.f, 0.f, 0.f}};
        const uint32_t* Au = (const uint32_t*)As;
        const uint32_t* Bu = (const uint32_t*)Bs;
        const uint32_t* apb = Au + (wm * 16 + gid) * RSTR + tig;
        #pragma unroll 4
        for (int k = 0; k < 512; k += 8) {
            uint32_t a[4];
            a[0] = apb[k]; a[1] = apb[k + 8 * RSTR]; a[2] = apb[k + 4]; a[3] = apb[k + 8 * RSTR + 4];
            #pragma unroll
            for (int ni = 0; ni < 2; ni++) {
                const uint32_t* bp = Bu + (wn * 16 + ni * 8 + gid) * RSTR + k + tig;
                uint32_t b[2];
                b[0] = bp[0]; b[1] = bp[4];
                mma8(acc[ni], a, b);
            }
        }

        const float* gp = d_gpre + (size_t)t * NB * G4;
        float* hd = d_hall + (size_t)t * NB * NH;
        __nv_bfloat16* hb = d_hall_bf + (size_t)t * NB * NH;
        #pragma unroll
        for (int ni = 0; ni < 2; ni++) {
            float v0 = acc[ni][0] + gp[(size_t)mrow0 * G4 + gp0_[ni]];
            float v1 = acc[ni][1] + gp[(size_t)mrow0 * G4 + gp1_[ni]];
            float v2 = acc[ni][2] + gp[(size_t)(mrow0 + 8) * G4 + gp0_[ni]];
            float v3 = acc[ni][3] + gp[(size_t)(mrow0 + 8) * G4 + gp1_[ni]];
            float w0 = __shfl_xor_sync(0xffffffffu, v0, 1);
            float w1 = __shfl_xor_sync(0xffffffffu, v1, 1);
            float w2 = __shfl_xor_sync(0xffffffffu, v2, 1);
            float w3 = __shfl_xor_sync(0xffffffffu, v3, 1);
            float iA, fA, gA, oA, iB, fB, gB, oB;
            if ((tig & 1) == 0) { iA = v0; fA = v1; gA = w0; oA = w1; iB = v2; fB = v3; gB = w2; oB = w3; }
            else                { iA = w0; fA = w1; gA = v0; oA = v1; iB = w2; fB = w3; gB = v2; oB = v3; }
            float c0n = sigmoidf_(fA) * creg[ni][0] + sigmoidf_(iA) * tanhf(gA);
            float h0v = sigmoidf_(oA) * tanhf(c0n);
            creg[ni][0] = c0n;
            float c1n = sigmoidf_(fB) * creg[ni][1] + sigmoidf_(iB) * tanhf(gB);
            float h1v = sigmoidf_(oB) * tanhf(c1n);
            creg[ni][1] = c1n;
            if ((tig & 1) == 0) {
                hd[(size_t)mrow0 * NH + jcol[ni]] = h0v;
                hd[(size_t)(mrow0 + 8) * NH + jcol[ni]] = h1v;
                hb[(size_t)mrow0 * NH + jcol[ni]] = __float2bfloat16(h0v);
                hb[(size_t)(mrow0 + 8) * NH + jcol[ni]] = __float2bfloat16(h1v);
            }
        }
        grid_barrier(gridDim.x);
    }
}

// ======================= output softmax (bf16 logits in, fp32 out) ====================
#define NV8 1250   // NV / 8

__global__ void __launch_bounds__(512) k_out(float* __restrict__ out) {
    __shared__ __align__(16) float row[NV];
    __shared__ float red[512];
    int r = blockIdx.x, tid = threadIdx.x;
    const uint4* L = (const uint4*)(d_logits_bf + (size_t)r * NV);
    float mx = -1e30f;
    for (int v = tid; v < NV8; v += 512) {
        uint4 u = L[v];
        float2 f0 = __bfloat1622float2(*(__nv_bfloat162*)&u.x);
        float2 f1 = __bfloat1622float2(*(__nv_bfloat162*)&u.y);
        float2 f2 = __bfloat1622float2(*(__nv_bfloat162*)&u.z);
        float2 f3 = __bfloat1622float2(*(__nv_bfloat162*)&u.w);
        float4 a = make_float4(f0.x, f0.y, f1.x, f1.y);
        float4 b = make_float4(f2.x, f2.y, f3.x, f3.y);
        *(float4*)(row + v * 8) = a;
        *(float4*)(row + v * 8 + 4) = b;
        mx = fmaxf(mx, fmaxf(fmaxf(a.x, a.y), fmaxf(a.z, a.w)));
        mx = fmaxf(mx, fmaxf(fmaxf(b.x, b.y), fmaxf(b.z, b.w)));
    }
    red[tid] = mx; __syncthreads();
    for (int s = 256; s; s >>= 1) { if (tid < s) red[tid] = fmaxf(red[tid], red[tid + s]); __syncthreads(); }
    mx = red[0]; __syncthreads();
    float sum = 0.f;
    for (int v = tid; v < NV / 4; v += 512) {
        float4 x = *(const float4*)(row + v * 4);
        sum += (__expf(x.x - mx) + __expf(x.y - mx)) + (__expf(x.z - mx) + __expf(x.w - mx));
    }
    red[tid] = sum; __syncthreads();
    for (int s = 256; s; s >>= 1) { if (tid < s) red[tid] += red[tid + s]; __syncthreads(); }
    float sh = mx + logf(red[0]);
    float4* o1 = (float4*)(out + (size_t)r * NV);
    float4* o2 = (float4*)(out + (size_t)TBR * NV + (size_t)r * NV);
    for (int v = tid; v < NV / 4; v += 512) {
        float4 x = *(const float4*)(row + v * 4);
        float4 lp, p;
        lp.x = x.x - sh; lp.y = x.y - sh; lp.z = x.z - sh; lp.w = x.w - sh;
        p.x = __expf(lp.x); p.y = __expf(lp.y); p.z = __expf(lp.z); p.w = __expf(lp.w);
        o1[v] = lp;
        o2[v] = p;
    }
}

// ======================= launch =======================
extern "C" void kernel_launch(void* const* d_in, const int* in_sizes, int n_in,
                              void* d_out, int out_size) {
    const float* features = (const float*)d_in[0];
    const int*   captions = (const int*)d_in[1];
    const float* W_init_h = (const float*)d_in[2];
    const float* W_init_c = (const float*)d_in[3];
    const float* Wv       = (const float*)d_in[4];
    const float* bv       = (const float*)d_in[5];
    // d_in[6]=Wa, d_in[7]=ba unused (softmax shift-invariance)
    const float* embed    = (const float*)d_in[8];
    const float* W_ih     = (const float*)d_in[9];
    const float* W_hh     = (const float*)d_in[10];
    const float* b_ih     = (const float*)d_in[11];
    const float* b_hh     = (const float*)d_in[12];
    const float* Wo       = (const float*)d_in[13];
    const float* bo       = (const float*)d_in[14];
    float* out = (float*)d_out;

    float *p_gctx, *p_gpre;
    __nv_bfloat16 *p_ebf, *p_wobf, *p_wibf, *p_hbf, *p_lbf;
    cudaGetSymbolAddress((void**)&p_gctx,   d_gctx);
    cudaGetSymbolAddress((void**)&p_gpre,   d_gpre);
    cudaGetSymbolAddress((void**)&p_ebf,    d_emb_bf);
    cudaGetSymbolAddress((void**)&p_wobf,   d_wo_bf);
    cudaGetSymbolAddress((void**)&p_wibf,   d_wih_bf);
    cudaGetSymbolAddress((void**)&p_hbf,    d_hall_bf);
    cudaGetSymbolAddress((void**)&p_lbf,    d_logits_bf);

    static int smset = 0;
    if (!smset) {
        cudaFuncSetAttribute(k_recur, cudaFuncAttributeMaxDynamicSharedMemorySize, RS_SMEM);
        cudaFuncSetAttribute(tbmma, cudaFuncAttributeMaxDynamicSharedMemorySize, TB_SMEM);
        smset = 1;
    }

    // setup + conversions
    k_gather<<<TBR, NE>>>(captions, embed);
    k_cvtb<<<(NV * NH / 4 + 255) / 256, 256>>>(Wo, NH, NH, p_wobf, NV * NH / 4);
    k_cvtb<<<(G4 * NE / 4 + 255) / 256, 256>>>(W_ih + VDIM, VDIM + NE, NE, p_wibf, G4 * NE / 4);

    // visual stage
    k_att<<<dim3(25, NB), 256>>>(features, Wv, bv);
    k_ctx<<<dim3(4, NB), 256>>>(features);

    // fused h0 | c0 | g_ctx
    k_init<<<dim3(48, 4), 256>>>(W_init_h, W_init_c, W_ih, b_ih, b_hh);

    // g_pre = emb @ WihE^T + g_ctx[b]  (bf16 mma, fp32 out)
    tbmma<<<dim3(G4 / 128, TBR / 128), 256, TB_SMEM>>>(
        p_ebf, NE, p_wibf, NE, p_gpre, nullptr, TBR, G4, NE, nullptr, p_gctx, NB);

    // recurrence
    k_recur<<<NB, 256, RS_SMEM>>>(W_hh);

    // logits = hall @ Wo^T + bo  (bf16 mma, bf16 out)
    tbmma<<<dim3((NV + 127) / 128, TBR / 128), 256, TB_SMEM>>>(
        p_hbf, NH, p_wobf, NH, nullptr, p_lbf, TBR, NV, NH, bo, nullptr, 0);

    k_out<<<TBR, 512>>>(out);
}

// round 12
// speedup vs baseline: 7.1161x; 1.1092x over previous
#include <cuda_runtime.h>
#include <cuda_bf16.h>
#include <math.h>
#include <stdint.h>

// Problem dims
#define NB   128
#define NT   20
#define VNUM 196
#define VDIM 512
#define NE   256
#define NH   512
#define NV   10000
#define G4   2048
#define TBR  2560   // NT*NB

// ---------------- helpers ----------------
__device__ __forceinline__ void mma16(float* c, const uint32_t* a, const uint32_t* b) {
    asm volatile("mma.sync.aligned.m16n8k16.row.col.f32.bf16.bf16.f32 "
                 "{%0,%1,%2,%3}, {%4,%5,%6,%7}, {%8,%9}, {%0,%1,%2,%3};"
                 : "+f"(c[0]), "+f"(c[1]), "+f"(c[2]), "+f"(c[3])
                 : "r"(a[0]), "r"(a[1]), "r"(a[2]), "r"(a[3]), "r"(b[0]), "r"(b[1]));
}
__device__ __forceinline__ uint32_t smem_u32(const void* p) {
    uint32_t a;
    asm("{ .reg .u64 t; cvta.to.shared.u64 t, %1; cvt.u32.u64 %0, t; }" : "=r"(a) : "l"(p));
    return a;
}
__device__ __forceinline__ void ldsm4(uint32_t* r, uint32_t addr) {
    asm volatile("ldmatrix.sync.aligned.m8n8.x4.shared.b16 {%0,%1,%2,%3}, [%4];"
                 : "=r"(r[0]), "=r"(r[1]), "=r"(r[2]), "=r"(r[3]) : "r"(addr));
}
__device__ __forceinline__ void cpa16(uint32_t saddr, const void* gaddr, uint32_t srcsz) {
    asm volatile("cp.async.cg.shared.global [%0], [%1], 16, %2;"
                 :: "r"(saddr), "l"(gaddr), "r"(srcsz));
}
#define CP_COMMIT() asm volatile("cp.async.commit_group;")
#define CP_WAIT1()  asm volatile("cp.async.wait_group 1;")
__device__ __forceinline__ float sigmoidf_(float x) { return 1.f / (1.f + __expf(-x)); }

// ---------------- scratch ----------------
__device__ __nv_bfloat16 d_emb_bf[TBR * NE];
__device__ __nv_bfloat16 d_wo_bf[(size_t)NV * NH];
__device__ __nv_bfloat16 d_wih_bf[G4 * NE];
__device__ __nv_bfloat16 d_hall_bf[(size_t)TBR * NH];
__device__ __nv_bfloat16 d_h0_bf[NB * NH];
__device__ __nv_bfloat16 d_logits_bf[(size_t)TBR * (NV + 16)];
__device__ float d_attv[NB * VNUM];
__device__ float d_feat_sum[NB * VDIM];
__device__ float d_ctx[NB * VDIM];
__device__ float d_c0[NB * NH];
__device__ float d_gctx[NB * G4];
__device__ float d_gpre[(size_t)TBR * G4];
__device__ unsigned d_barCount;
__device__ unsigned d_barGen;

// ---------------- embedding gather -> bf16 ----------------
__global__ void k_gather(const int* __restrict__ cap, const float* __restrict__ et) {
    int r = blockIdx.x;                 // t*NB + b
    int t = r / NB, b = r % NB;
    int id = cap[b * NT + t];
    d_emb_bf[(size_t)r * NE + threadIdx.x] = __float2bfloat16(et[(size_t)id * NE + threadIdx.x]);
}

// ---------------- fp32 -> bf16 (4 elems/thread, packed 8B stores) ----------------
__global__ void k_cvtb(const float* __restrict__ src, int pitch, int cols,
                       __nv_bfloat16* __restrict__ dst, int n4) {
    int i = blockIdx.x * 256 + threadIdx.x;
    if (i >= n4) return;
    int e = i * 4;
    const float* s;
    if (pitch == cols) {
        s = src + e;
    } else {
        int r = e / cols, c = e % cols;
        s = src + (size_t)r * pitch + c;
    }
    float4 v = *(const float4*)s;
    __nv_bfloat162 p0 = __floats2bfloat162_rn(v.x, v.y);
    __nv_bfloat162 p1 = __floats2bfloat162_rn(v.z, v.w);
    uint2 pk;
    pk.x = *(uint32_t*)&p0;
    pk.y = *(uint32_t*)&p1;
    *(uint2*)(dst + e) = pk;
}

// ---------------- attention logits: one warp per (b, n) ----------------
__global__ void __launch_bounds__(256) k_att(const float* __restrict__ feat,
        const float* __restrict__ Wv, const float* __restrict__ bv) {
    int warp = threadIdx.x >> 5, lane = threadIdx.x & 31;
    int b = blockIdx.y;
    int n = blockIdx.x * 8 + warp;
    if (n >= VNUM) return;
    const float* fr = feat + ((size_t)b * VNUM + n) * VDIM;
    float acc = 0.f;
    #pragma unroll
    for (int k = lane; k < VDIM; k += 32) acc += fr[k] * Wv[k];
    #pragma unroll
    for (int o = 16; o; o >>= 1) acc += __shfl_xor_sync(0xffffffffu, acc, o);
    if (lane == 0) d_attv[b * VNUM + n] = acc + bv[0];
}

// ---------------- softmax(attv) -> feat_sum + ctx ----------------
__global__ void __launch_bounds__(256) k_ctx(const float* __restrict__ feat) {
    __shared__ float salpha[VNUM];
    __shared__ float red[256];
    __shared__ float sfs[256];
    __shared__ float sctx[256];
    int b = blockIdx.y, tid = threadIdx.x;
    int v0 = blockIdx.x * 128;
    float x = (tid < VNUM) ? d_attv[b * VNUM + tid] : -1e30f;
    red[tid] = x; __syncthreads();
    for (int s = 128; s; s >>= 1) { if (tid < s) red[tid] = fmaxf(red[tid], red[tid + s]); __syncthreads(); }
    float mx = red[0]; __syncthreads();
    float e = (tid < VNUM) ? __expf(x - mx) : 0.f;
    red[tid] = e; __syncthreads();
    for (int s = 128; s; s >>= 1) { if (tid < s) red[tid] += red[tid + s]; __syncthreads(); }
    float inv = 1.f / red[0];
    __syncthreads();
    if (tid < VNUM) salpha[tid] = e * inv;
    __syncthreads();

    int v = v0 + (tid & 127);
    int half = tid >> 7;
    int n0 = half * 98, n1 = n0 + 98;
    if (n1 > VNUM) n1 = VNUM;
    const float* fp = feat + (size_t)b * VNUM * VDIM + v;
    float fs = 0.f, c0 = 0.f, c1 = 0.f, c2 = 0.f, c3 = 0.f;
    int n = n0;
    for (; n + 4 <= n1; n += 4) {
        float x0 = fp[(size_t)n * VDIM];
        float x1 = fp[(size_t)(n + 1) * VDIM];
        float x2 = fp[(size_t)(n + 2) * VDIM];
        float x3 = fp[(size_t)(n + 3) * VDIM];
        fs += (x0 + x1) + (x2 + x3);
        c0 += salpha[n] * x0; c1 += salpha[n + 1] * x1;
        c2 += salpha[n + 2] * x2; c3 += salpha[n + 3] * x3;
    }
    for (; n < n1; n++) { float xx = fp[(size_t)n * VDIM]; fs += xx; c0 += salpha[n] * xx; }
    sfs[tid] = fs;
    sctx[tid] = (c0 + c1) + (c2 + c3);
    __syncthreads();
    if (half == 0) {
        d_feat_sum[b * VDIM + v] = sfs[tid] + sfs[tid + 128];
        d_ctx[b * VDIM + v] = sctx[tid] + sctx[tid + 128];
    }
}

// ---------------- fused init GEMMs: h0(bf16) | c0 | g_ctx (N=3072 concat) ----------------
__global__ void __launch_bounds__(256) k_init(
        const float* __restrict__ Wini_h, const float* __restrict__ Wini_c,
        const float* __restrict__ Wih,
        const float* __restrict__ bih, const float* __restrict__ bhh) {
    __shared__ float As[16][32];
    __shared__ float Bs[16][64];
    int ntile = blockIdx.x, mt = blockIdx.y;
    int seg, nloc0;
    const float* A;
    const float* B;
    int ldb;
    if (ntile < 8)       { seg = 0; nloc0 = ntile * 64;        A = d_feat_sum; B = Wini_h; ldb = VDIM; }
    else if (ntile < 16) { seg = 1; nloc0 = (ntile - 8) * 64;  A = d_feat_sum; B = Wini_c; ldb = VDIM; }
    else                 { seg = 2; nloc0 = (ntile - 16) * 64; A = d_ctx;      B = Wih;    ldb = VDIM + NE; }
    int tid = threadIdx.x;
    int tx = tid & 15, ty = tid >> 4;
    int m0 = mt * 32;
    float acc[2][4] = {{0.f, 0.f, 0.f, 0.f}, {0.f, 0.f, 0.f, 0.f}};
    for (int k0 = 0; k0 < VDIM; k0 += 16) {
        {
            int i = tid; int r = i >> 4, kk = i & 15;
            As[kk][r] = A[(size_t)(m0 + r) * VDIM + k0 + kk];
            i = tid + 256; r = i >> 4; kk = i & 15;
            As[kk][r] = A[(size_t)(m0 + r) * VDIM + k0 + kk];
        }
        #pragma unroll
        for (int j = 0; j < 4; j++) {
            int i = tid + j * 256; int r = i >> 4, kk = i & 15;
            Bs[kk][r] = B[(size_t)(nloc0 + r) * ldb + k0 + kk];
        }
        __syncthreads();
        #pragma unroll
        for (int kk = 0; kk < 16; kk++) {
            float a0 = As[kk][ty * 2], a1 = As[kk][ty * 2 + 1];
            float b0 = Bs[kk][tx * 4], b1 = Bs[kk][tx * 4 + 1];
            float b2 = Bs[kk][tx * 4 + 2], b3 = Bs[kk][tx * 4 + 3];
            acc[0][0] += a0 * b0; acc[0][1] += a0 * b1; acc[0][2] += a0 * b2; acc[0][3] += a0 * b3;
            acc[1][0] += a1 * b0; acc[1][1] += a1 * b1; acc[1][2] += a1 * b2; acc[1][3] += a1 * b3;
        }
        __syncthreads();
    }
    #pragma unroll
    for (int i = 0; i < 2; i++) {
        int m = m0 + ty * 2 + i;
        #pragma unroll
        for (int j = 0; j < 4; j++) {
            int n = nloc0 + tx * 4 + j;
            if (seg == 0) {
                d_h0_bf[(size_t)m * NH + n] = __float2bfloat16(acc[i][j] * (1.f / VNUM));
            } else if (seg == 1) {
                d_c0[(size_t)m * NH + n] = acc[i][j] * (1.f / VNUM);
            } else {
                d_gctx[(size_t)m * G4 + n] = acc[i][j] + bih[n] + bhh[n];
            }
        }
    }
}

// ======================= bf16 mma GEMM: BK=64, 3-stage cp.async, 2 CTAs/SM =========
#define BSTR64 72
#define TB_BUF (128 * BSTR64)                // elems per matrix per stage
#define TB_STAGE_BYTES (2 * TB_BUF * 2)      // A+B per stage, bytes (36864)
#define TB_SMEM (3 * TB_STAGE_BYTES)         // 110592 B

__global__ void __launch_bounds__(256, 2) tbmma(const __nv_bfloat16* __restrict__ A, int lda,
        const __nv_bfloat16* __restrict__ B, int ldb,
        float* __restrict__ C, __nv_bfloat16* __restrict__ Cb,
        int M, int N, int K,
        const float* __restrict__ bias, const float* __restrict__ addM, int addRowMod) {
    extern __shared__ __align__(16) __nv_bfloat16 smb[];
    int tid = threadIdx.x, lane = tid & 31, wid = tid >> 5;
    int wm = wid & 1, wn = wid >> 1;
    int m0 = blockIdx.y * 128, n0 = blockIdx.x * 128;
    int gid = lane >> 2, tig = lane & 3;

    float acc[4][4][4];
    #pragma unroll
    for (int mi = 0; mi < 4; mi++)
        #pragma unroll
        for (int ni = 0; ni < 4; ni++)
            #pragma unroll
            for (int q = 0; q < 4; q++) acc[mi][ni][q] = 0.f;

    int rr[4], ss[4];
    #pragma unroll
    for (int j = 0; j < 4; j++) { int idx = tid + j * 256; rr[j] = idx >> 3; ss[j] = idx & 7; }
    uint32_t sm0 = smem_u32(smb);

    int iters = K >> 6;     // assume >= 2
    int lrow = lane & 15;
    int lcg = (lane >> 4) << 3;

    #define STAGE(ck, bsel) do {                                                          \
        int k0_ = (ck) << 6;                                                              \
        uint32_t da = sm0 + (bsel) * TB_STAGE_BYTES;                                      \
        uint32_t db = da + TB_BUF * 2;                                                    \
        _Pragma("unroll")                                                                 \
        for (int j = 0; j < 4; j++)                                                       \
            cpa16(da + (rr[j] * BSTR64 + ss[j] * 8) * 2,                                  \
                  A + (size_t)(m0 + rr[j]) * lda + k0_ + ss[j] * 8, 16u);                 \
        _Pragma("unroll")                                                                 \
        for (int j = 0; j < 4; j++) {                                                     \
            int n = n0 + rr[j];                                                           \
            uint32_t sz = (n < N) ? 16u : 0u;                                             \
            cpa16(db + (rr[j] * BSTR64 + ss[j] * 8) * 2,                                  \
                  B + (size_t)(n < N ? n : 0) * ldb + k0_ + ss[j] * 8, sz);               \
        }                                                                                 \
        CP_COMMIT();                                                                      \
    } while (0)

    STAGE(0, 0);
    STAGE(1, 1);

    int bc = 0;
    for (int it = 0; it < iters; it++) {
        CP_WAIT1();
        __syncthreads();
        int bs = bc + 2; if (bs >= 3) bs -= 3;
        if (it + 2 < iters) STAGE(it + 2, bs);
        uint32_t ab = sm0 + bc * TB_STAGE_BYTES;
        uint32_t bb = ab + TB_BUF * 2;
        #pragma unroll
        for (int ks = 0; ks < 4; ks++) {
            int kofs = ks * 16 + lcg;
            uint32_t a[4][4], b[4][2];
            #pragma unroll
            for (int mi = 0; mi < 4; mi++)
                ldsm4(a[mi], ab + ((wm * 64 + mi * 16 + lrow) * BSTR64 + kofs) * 2);
            #pragma unroll
            for (int np = 0; np < 2; np++) {
                uint32_t r[4];
                ldsm4(r, bb + ((wn * 32 + np * 16 + lrow) * BSTR64 + kofs) * 2);
                b[2 * np][0] = r[0]; b[2 * np + 1][0] = r[1];
                b[2 * np][1] = r[2]; b[2 * np + 1][1] = r[3];
            }
            #pragma unroll
            for (int mi = 0; mi < 4; mi++)
                #pragma unroll
                for (int ni = 0; ni < 4; ni++)
                    mma16(acc[mi][ni], a[mi], b[ni]);
        }
        bc++; if (bc == 3) bc = 0;
    }

    #pragma unroll
    for (int mi = 0; mi < 4; mi++) {
        int row0 = m0 + wm * 64 + mi * 16 + gid;
        #pragma unroll
        for (int ni = 0; ni < 4; ni++) {
            int col = n0 + wn * 32 + ni * 8 + tig * 2;
            #pragma unroll
            for (int half = 0; half < 2; half++) {
                int r = row0 + half * 8;
                float v0 = acc[mi][ni][half * 2 + 0];
                float v1 = acc[mi][ni][half * 2 + 1];
                if (bias) { v0 += bias[col]; v1 += (col + 1 < N) ? bias[col + 1] : 0.f; }
                if (addM) {
                    int ar = r % addRowMod;
                    v0 += addM[(size_t)ar * N + col];
                    if (col + 1 < N) v1 += addM[(size_t)ar * N + col + 1];
                }
                if (C) {
                    if (col < N)     C[(size_t)r * N + col]     = v0;
                    if (col + 1 < N) C[(size_t)r * N + col + 1] = v1;
                } else {
                    if (col + 1 < N) {
                        __nv_bfloat162 p = __floats2bfloat162_rn(v0, v1);
                        *(uint32_t*)(Cb + (size_t)r * NV + col) = *(uint32_t*)&p;
                    } else if (col < N) {
                        Cb[(size_t)r * NV + col] = __float2bfloat16(v0);
                    }
                }
            }
        }
    }
    #undef STAGE
}

// ======================= persistent recurrence (bf16 mma + ldmatrix) ==========
__device__ __forceinline__ void grid_barrier(unsigned nb) {
    __syncthreads();
    if (threadIdx.x == 0) {
        unsigned gen = *((volatile unsigned*)&d_barGen);
        __threadfence();
        if (atomicAdd(&d_barCount, 1u) == nb - 1u) {
            d_barCount = 0u;
            __threadfence();
            atomicAdd(&d_barGen, 1u);
        } else {
            while (*((volatile unsigned*)&d_barGen) == gen) {}
        }
        __threadfence();
    }
    __syncthreads();
}

// 128 blocks x 256 threads (one per SM). Block (mt = bid>>5, nt = bid&31):
//   m rows mt*32..+31 (batches), gate cols {g*512 + nt*16 + jj}.
// Whh staged ONCE as bf16 (permuted: local col lc -> row (lc&3)*512 + nt*16 + (lc>>2)).
// h tile staged per step from d_hall_bf. mma m16n8k16 bf16 via ldmatrix.
#define RSTR2 520                              // bf16 elems per row (512 + 8 pad)
#define RS_SMEM2 ((64 + 32) * RSTR2 * 2)       // 99840 B

__global__ void __launch_bounds__(256, 1) k_recur(const float* __restrict__ Whh) {
    extern __shared__ __nv_bfloat16 rs[];
    __nv_bfloat16* Bs = rs;                    // 64 x 520 (Whh permuted)
    __nv_bfloat16* As = rs + 64 * RSTR2;       // 32 x 520 (h tile)
    int bid = blockIdx.x, tid = threadIdx.x;
    int mt = bid >> 5, nt = bid & 31;
    int lane = tid & 31, wid = tid >> 5;
    int wm = wid & 1, wn = wid >> 1;
    int gid = lane >> 2, tig = lane & 3;
    int lrow = lane & 15;
    int lcg = (lane >> 4) << 3;

    // stage Whh block rows once (fp32 -> bf16, permuted)
    for (int i = tid; i < 64 * 128; i += 256) {
        int r = i >> 7, q = (i & 127) << 2;
        int w = ((r & 3) << 9) + (nt << 4) + (r >> 2);
        float4 v = *(const float4*)(Whh + (size_t)w * NH + q);
        __nv_bfloat162 p0 = __floats2bfloat162_rn(v.x, v.y);
        __nv_bfloat162 p1 = __floats2bfloat162_rn(v.z, v.w);
        uint2 pk; pk.x = *(uint32_t*)&p0; pk.y = *(uint32_t*)&p1;
        *(uint2*)(Bs + r * RSTR2 + q) = pk;
    }

    int mrow0 = mt * 32 + wm * 16 + gid;
    int g0 = (2 * tig) & 3, g1 = (2 * tig + 1) & 3;
    float creg[2][2];
    int jcol[2], gp0_[2], gp1_[2];
    #pragma unroll
    for (int ni = 0; ni < 2; ni++) {
        int jj = wn * 4 + ni * 2 + (tig >> 1);
        int j = nt * 16 + jj;
        jcol[ni] = j;
        gp0_[ni] = g0 * 512 + j;
        gp1_[ni] = g1 * 512 + j;
        creg[ni][0] = d_c0[mrow0 * NH + j];
        creg[ni][1] = d_c0[(mrow0 + 8) * NH + j];
    }

    uint32_t sB0 = smem_u32(Bs), sA0 = smem_u32(As);
    uint32_t aAddr = sA0 + ((wm * 16 + lrow) * RSTR2 + lcg) * 2;
    uint32_t bAddr = sB0 + ((wn * 16 + lrow) * RSTR2 + lcg) * 2;

    for (int t = 0; t < NT; t++) {
        const __nv_bfloat16* hsrc = (t == 0) ? d_h0_bf : (d_hall_bf + (size_t)(t - 1) * NB * NH);
        // stage h tile (32 x 512 bf16) via 16B loads
        for (int i = tid; i < 32 * 64; i += 256) {
            int r = i >> 6, q = (i & 63) << 3;
            *(uint4*)(As + r * RSTR2 + q) = *(const uint4*)(hsrc + (size_t)(mt * 32 + r) * NH + q);
        }
        __syncthreads();

        float acc[2][4] = {{0.f, 0.f, 0.f, 0.f}, {0.f, 0.f, 0.f, 0.f}};
        #pragma unroll 8
        for (int kc = 0; kc < 512; kc += 16) {
            uint32_t a[4], r[4];
            ldsm4(a, aAddr + kc * 2);
            ldsm4(r, bAddr + kc * 2);
            uint32_t b0[2] = { r[0], r[2] };
            uint32_t b1[2] = { r[1], r[3] };
            mma16(acc[0], a, b0);
            mma16(acc[1], a, b1);
        }

        const float* gp = d_gpre + (size_t)t * NB * G4;
        __nv_bfloat16* hb = d_hall_bf + (size_t)t * NB * NH;
        #pragma unroll
        for (int ni = 0; ni < 2; ni++) {
            float v0 = acc[ni][0] + gp[(size_t)mrow0 * G4 + gp0_[ni]];
            float v1 = acc[ni][1] + gp[(size_t)mrow0 * G4 + gp1_[ni]];
            float v2 = acc[ni][2] + gp[(size_t)(mrow0 + 8) * G4 + gp0_[ni]];
            float v3 = acc[ni][3] + gp[(size_t)(mrow0 + 8) * G4 + gp1_[ni]];
            float w0 = __shfl_xor_sync(0xffffffffu, v0, 1);
            float w1 = __shfl_xor_sync(0xffffffffu, v1, 1);
            float w2 = __shfl_xor_sync(0xffffffffu, v2, 1);
            float w3 = __shfl_xor_sync(0xffffffffu, v3, 1);
            float iA, fA, gA, oA, iB, fB, gB, oB;
            if ((tig & 1) == 0) { iA = v0; fA = v1; gA = w0; oA = w1; iB = v2; fB = v3; gB = w2; oB = w3; }
            else                { iA = w0; fA = w1; gA = v0; oA = v1; iB = w2; fB = w3; gB = v2; oB = v3; }
            float c0n = sigmoidf_(fA) * creg[ni][0] + sigmoidf_(iA) * tanhf(gA);
            float h0v = sigmoidf_(oA) * tanhf(c0n);
            creg[ni][0] = c0n;
            float c1n = sigmoidf_(fB) * creg[ni][1] + sigmoidf_(iB) * tanhf(gB);
            float h1v = sigmoidf_(oB) * tanhf(c1n);
            creg[ni][1] = c1n;
            if ((tig & 1) == 0) {
                hb[(size_t)mrow0 * NH + jcol[ni]] = __float2bfloat16(h0v);
                hb[(size_t)(mrow0 + 8) * NH + jcol[ni]] = __float2bfloat16(h1v);
            }
        }
        grid_barrier(gridDim.x);
    }
}

// ======================= output softmax (bf16 logits in, fp32 out) ====================
#define NV8 1250   // NV / 8

__global__ void __launch_bounds__(512) k_out(float* __restrict__ out) {
    __shared__ __align__(16) float row[NV];
    __shared__ float red[512];
    int r = blockIdx.x, tid = threadIdx.x;
    const uint4* L = (const uint4*)(d_logits_bf + (size_t)r * NV);
    float mx = -1e30f;
    for (int v = tid; v < NV8; v += 512) {
        uint4 u = L[v];
        float2 f0 = __bfloat1622float2(*(__nv_bfloat162*)&u.x);
        float2 f1 = __bfloat1622float2(*(__nv_bfloat162*)&u.y);
        float2 f2 = __bfloat1622float2(*(__nv_bfloat162*)&u.z);
        float2 f3 = __bfloat1622float2(*(__nv_bfloat162*)&u.w);
        float4 a = make_float4(f0.x, f0.y, f1.x, f1.y);
        float4 b = make_float4(f2.x, f2.y, f3.x, f3.y);
        *(float4*)(row + v * 8) = a;
        *(float4*)(row + v * 8 + 4) = b;
        mx = fmaxf(mx, fmaxf(fmaxf(a.x, a.y), fmaxf(a.z, a.w)));
        mx = fmaxf(mx, fmaxf(fmaxf(b.x, b.y), fmaxf(b.z, b.w)));
    }
    red[tid] = mx; __syncthreads();
    for (int s = 256; s; s >>= 1) { if (tid < s) red[tid] = fmaxf(red[tid], red[tid + s]); __syncthreads(); }
    mx = red[0]; __syncthreads();
    float sum = 0.f;
    for (int v = tid; v < NV / 4; v += 512) {
        float4 x = *(const float4*)(row + v * 4);
        sum += (__expf(x.x - mx) + __expf(x.y - mx)) + (__expf(x.z - mx) + __expf(x.w - mx));
    }
    red[tid] = sum; __syncthreads();
    for (int s = 256; s; s >>= 1) { if (tid < s) red[tid] += red[tid + s]; __syncthreads(); }
    float sh = mx + logf(red[0]);
    float4* o1 = (float4*)(out + (size_t)r * NV);
    float4* o2 = (float4*)(out + (size_t)TBR * NV + (size_t)r * NV);
    for (int v = tid; v < NV / 4; v += 512) {
        float4 x = *(const float4*)(row + v * 4);
        float4 lp, p;
        lp.x = x.x - sh; lp.y = x.y - sh; lp.z = x.z - sh; lp.w = x.w - sh;
        p.x = __expf(lp.x); p.y = __expf(lp.y); p.z = __expf(lp.z); p.w = __expf(lp.w);
        o1[v] = lp;
        o2[v] = p;
    }
}

// ======================= launch =======================
extern "C" void kernel_launch(void* const* d_in, const int* in_sizes, int n_in,
                              void* d_out, int out_size) {
    const float* features = (const float*)d_in[0];
    const int*   captions = (const int*)d_in[1];
    const float* W_init_h = (const float*)d_in[2];
    const float* W_init_c = (const float*)d_in[3];
    const float* Wv       = (const float*)d_in[4];
    const float* bv       = (const float*)d_in[5];
    // d_in[6]=Wa, d_in[7]=ba unused (softmax shift-invariance)
    const float* embed    = (const float*)d_in[8];
    const float* W_ih     = (const float*)d_in[9];
    const float* W_hh     = (const float*)d_in[10];
    const float* b_ih     = (const float*)d_in[11];
    const float* b_hh     = (const float*)d_in[12];
    const float* Wo       = (const float*)d_in[13];
    const float* bo       = (const float*)d_in[14];
    float* out = (float*)d_out;

    float *p_gctx, *p_gpre;
    __nv_bfloat16 *p_ebf, *p_wobf, *p_wibf, *p_hbf, *p_lbf;
    cudaGetSymbolAddress((void**)&p_gctx,   d_gctx);
    cudaGetSymbolAddress((void**)&p_gpre,   d_gpre);
    cudaGetSymbolAddress((void**)&p_ebf,    d_emb_bf);
    cudaGetSymbolAddress((void**)&p_wobf,   d_wo_bf);
    cudaGetSymbolAddress((void**)&p_wibf,   d_wih_bf);
    cudaGetSymbolAddress((void**)&p_hbf,    d_hall_bf);
    cudaGetSymbolAddress((void**)&p_lbf,    d_logits_bf);

    static int smset = 0;
    if (!smset) {
        cudaFuncSetAttribute(k_recur, cudaFuncAttributeMaxDynamicSharedMemorySize, RS_SMEM2);
        cudaFuncSetAttribute(tbmma, cudaFuncAttributeMaxDynamicSharedMemorySize, TB_SMEM);
        smset = 1;
    }

    // setup + conversions
    k_gather<<<TBR, NE>>>(captions, embed);
    k_cvtb<<<(NV * NH / 4 + 255) / 256, 256>>>(Wo, NH, NH, p_wobf, NV * NH / 4);
    k_cvtb<<<(G4 * NE / 4 + 255) / 256, 256>>>(W_ih + VDIM, VDIM + NE, NE, p_wibf, G4 * NE / 4);

    // visual stage
    k_att<<<dim3(25, NB), 256>>>(features, Wv, bv);
    k_ctx<<<dim3(4, NB), 256>>>(features);

    // fused h0 | c0 | g_ctx
    k_init<<<dim3(48, 4), 256>>>(W_init_h, W_init_c, W_ih, b_ih, b_hh);

    // g_pre = emb @ WihE^T + g_ctx[b]  (bf16 mma, fp32 out)
    tbmma<<<dim3(G4 / 128, TBR / 128), 256, TB_SMEM>>>(
        p_ebf, NE, p_wibf, NE, p_gpre, nullptr, TBR, G4, NE, nullptr, p_gctx, NB);

    // recurrence (bf16 mma + ldmatrix, 1 grid barrier / step)
    k_recur<<<NB, 256, RS_SMEM2>>>(W_hh);

    // logits = hall @ Wo^T + bo  (bf16 mma, bf16 out)
    tbmma<<<dim3((NV + 127) / 128, TBR / 128), 256, TB_SMEM>>>(
        p_hbf, NH, p_wobf, NH, nullptr, p_lbf, TBR, NV, NH, bo, nullptr, 0);

    k_out<<<TBR, 512>>>(out);
}